// round 7
// baseline (speedup 1.0000x reference)
#include <cuda_runtime.h>
#include <cuda_bf16.h>
#include <cstdint>

// ---------------- problem constants ----------------
#define BAG  8
#define SEQ  512
#define DIM  768
#define NPD  6
#define NN_  48          // N nodes
#define TT   2304        // T = N*N
#define NHEAD 8
#define DK   96
#define DFF  1024
#define NLAYER 4
#define NREL 97

typedef uint32_t u32;

// ---------------- device scratch (no allocations allowed) ----------------
__device__ float g_htb [NN_ * DIM];
__device__ float g_u   [NN_ * DIM];
__device__ float g_v   [NN_ * DIM];
__device__ float g_x   [TT * DIM];
__device__ float g_q   [TT * DIM];
__device__ float g_k   [TT * DIM];
__device__ float g_vv  [TT * DIM];
__device__ float g_attn[TT * DIM];
__device__ float g_tmp [TT * DIM];
__device__ float g_ffn [TT * DFF];
__device__ float g_ht  [BAG * NREL];

// ---------------- tf32 / ldmatrix helpers ----------------
__device__ __forceinline__ u32 f2tf32(float f) {
    u32 r; asm("cvt.rna.tf32.f32 %0, %1;" : "=r"(r) : "f"(f)); return r;
}
__device__ __forceinline__ void mma_tf32(float& c0, float& c1, float& c2, float& c3,
                                         u32 a0, u32 a1, u32 a2, u32 a3,
                                         u32 b0, u32 b1) {
    asm("mma.sync.aligned.m16n8k8.row.col.f32.tf32.tf32.f32 "
        "{%0,%1,%2,%3}, {%4,%5,%6,%7}, {%8,%9}, {%0,%1,%2,%3};"
        : "+f"(c0), "+f"(c1), "+f"(c2), "+f"(c3)
        : "r"(a0), "r"(a1), "r"(a2), "r"(a3), "r"(b0), "r"(b1));
}
__device__ __forceinline__ u32 s2u(const void* p) {
    return (u32)__cvta_generic_to_shared(p);
}
__device__ __forceinline__ void ldsm_x4(u32& r0, u32& r1, u32& r2, u32& r3, u32 addr) {
    asm volatile("ldmatrix.sync.aligned.m8n8.x4.shared.b16 {%0,%1,%2,%3}, [%4];"
                 : "=r"(r0), "=r"(r1), "=r"(r2), "=r"(r3) : "r"(addr));
}
__device__ __forceinline__ void ldsm_x2(u32& r0, u32& r1, u32 addr) {
    asm volatile("ldmatrix.sync.aligned.m8n8.x2.shared.b16 {%0,%1}, [%2];"
                 : "=r"(r0), "=r"(r1) : "r"(addr));
}

// ---------------- block reduction helper ----------------
__device__ __forceinline__ float blk_reduce(float val, float* sh, bool do_max) {
    const unsigned mask = 0xffffffffu;
#pragma unroll
    for (int o = 16; o > 0; o >>= 1) {
        float other = __shfl_xor_sync(mask, val, o);
        val = do_max ? fmaxf(val, other) : (val + other);
    }
    int lane = threadIdx.x & 31, w = threadIdx.x >> 5;
    __syncthreads();
    if (lane == 0) sh[w] = val;
    __syncthreads();
    int nw = (blockDim.x + 31) >> 5;
    if (w == 0) {
        val = (lane < nw) ? sh[lane] : (do_max ? -3.4e38f : 0.f);
#pragma unroll
        for (int o = 16; o > 0; o >>= 1) {
            float other = __shfl_xor_sync(mask, val, o);
            val = do_max ? fmaxf(val, other) : (val + other);
        }
        if (lane == 0) sh[0] = val;
    }
    __syncthreads();
    return sh[0];
}

// ---------------- 128xBN tf32 tensor-core GEMM (ldmatrix fragments) ----------------
// C[m,n] = sum_k A[m,k] * B[k,n]  (+bias) (ReLU).  BN = 32*NT.
// Requires: K % 16 == 0, N % BN == 0, lda % 4 == 0.
template<int NT, bool BIAS, bool RELU>
__global__ __launch_bounds__(256, 1)
void gemm_tc(const float* __restrict__ A, const float* __restrict__ B,
             const float* __restrict__ bias, float* __restrict__ C,
             int M, int N, int K, int lda, int ldb, int ldc)
{
    constexpr int BN = 32 * NT;
    constexpr int BK = 16, P = 20;

    __shared__ u32 As[2][128][P];
    __shared__ u32 Bs[2][BN][P];

    const int tid  = threadIdx.x;
    const int lane = tid & 31;
    const int warp = tid >> 5;
    const int wR   = (warp & 1) * 64;
    const int wC   = (warp >> 1) * (8 * NT);
    const int row0 = blockIdx.y * 128;
    const int col0 = blockIdx.x * BN;
    const int lr   = lane >> 2;
    const int lc   = lane & 3;
    const int ph   = lane >> 3;
    const int rr   = lane & 7;

    // ldmatrix per-thread offsets
    const int aoff_row = rr + (ph & 1) * 8;
    const int aoff_col = (ph >> 1) * 4;
    const int boff_row = rr + (ph >> 1) * 8;
    const int boff_col = (ph & 1) * 4;

    // staging maps
    const int ar = tid >> 1;
    const int ac = (tid & 1) * 8;
    int kb0, nb0, kb1 = 0, nb1 = 0;
    bool b1v;
    if (NT == 4) {
        kb0 = tid >> 5;        nb0 = (tid & 31) * 4;
        kb1 = kb0 + 8;         nb1 = nb0;           b1v = true;
    } else {                   // NT == 3: 384 float4 tasks
        kb0 = tid / 24;        nb0 = (tid % 24) * 4;
        b1v = (tid < 128);
        int id1 = tid + 256;
        kb1 = id1 / 24;        nb1 = (id1 % 24) * 4;
    }

    const u32 as_base = s2u(&As[0][0][0]);
    const u32 bs_base = s2u(&Bs[0][0][0]);

    const float4 f4z = make_float4(0.f, 0.f, 0.f, 0.f);
    float4 fa0, fa1, fb0, fb1;

    float acc[4][NT][4];
#pragma unroll
    for (int i = 0; i < 4; i++)
#pragma unroll
        for (int j = 0; j < NT; j++)
#pragma unroll
            for (int c = 0; c < 4; c++) acc[i][j][c] = 0.f;

    const int KT = K / BK;

    auto fetch = [&](int k0g) {
        int gm = row0 + ar;
        const float* ap = A + (long)gm * lda + k0g + ac;
        fa0 = (gm < M) ? *(const float4*)ap : f4z;
        fa1 = (gm < M) ? *(const float4*)(ap + 4) : f4z;
        fb0 = *(const float4*)(B + (long)(k0g + kb0) * ldb + col0 + nb0);
        if (b1v) fb1 = *(const float4*)(B + (long)(k0g + kb1) * ldb + col0 + nb1);
    };
    auto stage = [&](int buf) {
        uint4 q0, q1;
        q0.x = f2tf32(fa0.x); q0.y = f2tf32(fa0.y); q0.z = f2tf32(fa0.z); q0.w = f2tf32(fa0.w);
        q1.x = f2tf32(fa1.x); q1.y = f2tf32(fa1.y); q1.z = f2tf32(fa1.z); q1.w = f2tf32(fa1.w);
        *(uint4*)&As[buf][ar][ac]     = q0;
        *(uint4*)&As[buf][ar][ac + 4] = q1;
        // transpose-stage B into [n][k]
        Bs[buf][nb0 + 0][kb0] = f2tf32(fb0.x);
        Bs[buf][nb0 + 1][kb0] = f2tf32(fb0.y);
        Bs[buf][nb0 + 2][kb0] = f2tf32(fb0.z);
        Bs[buf][nb0 + 3][kb0] = f2tf32(fb0.w);
        if (b1v) {
            Bs[buf][nb1 + 0][kb1] = f2tf32(fb1.x);
            Bs[buf][nb1 + 1][kb1] = f2tf32(fb1.y);
            Bs[buf][nb1 + 2][kb1] = f2tf32(fb1.z);
            Bs[buf][nb1 + 3][kb1] = f2tf32(fb1.w);
        }
    };

    fetch(0);
    stage(0);
    __syncthreads();

    for (int kt = 0; kt < KT; kt++) {
        const int cur = kt & 1;
        const bool hn = (kt + 1 < KT);
        if (hn) fetch((kt + 1) * BK);

#pragma unroll
        for (int ks = 0; ks < 2; ks++) {
            const int k0 = ks * 8;
            u32 af[4][4], bf[NT][2];
#pragma unroll
            for (int mt = 0; mt < 4; mt++) {
                u32 addr = as_base + 4u * (u32)((cur * 128 + wR + mt * 16 + aoff_row) * P
                                               + k0 + aoff_col);
                ldsm_x4(af[mt][0], af[mt][1], af[mt][2], af[mt][3], addr);
            }
#pragma unroll
            for (int p = 0; p < NT / 2; p++) {
                u32 addr = bs_base + 4u * (u32)((cur * BN + wC + p * 16 + boff_row) * P
                                               + k0 + boff_col);
                ldsm_x4(bf[2 * p][0], bf[2 * p][1], bf[2 * p + 1][0], bf[2 * p + 1][1], addr);
            }
            if (NT & 1) {
                u32 addr = bs_base + 4u * (u32)((cur * BN + wC + (NT - 1) * 8 + rr) * P
                                               + k0 + (ph & 1) * 4);
                ldsm_x2(bf[NT - 1][0], bf[NT - 1][1], addr);
            }
#pragma unroll
            for (int mt = 0; mt < 4; mt++)
#pragma unroll
                for (int nt = 0; nt < NT; nt++)
                    mma_tf32(acc[mt][nt][0], acc[mt][nt][1], acc[mt][nt][2], acc[mt][nt][3],
                             af[mt][0], af[mt][1], af[mt][2], af[mt][3],
                             bf[nt][0], bf[nt][1]);
        }

        if (hn) stage(cur ^ 1);
        __syncthreads();
    }

    // ---- epilogue ----
#pragma unroll
    for (int nt = 0; nt < NT; nt++) {
        int gn = col0 + wC + nt * 8 + 2 * lc;
        float b0 = 0.f, b1 = 0.f;
        if (BIAS) { b0 = bias[gn]; b1 = bias[gn + 1]; }
#pragma unroll
        for (int mt = 0; mt < 4; mt++) {
            int gm0 = row0 + wR + mt * 16 + lr;
#pragma unroll
            for (int h = 0; h < 2; h++) {
                int gm = gm0 + h * 8;
                if (gm >= M) continue;
                float v0 = acc[mt][nt][2 * h]     + b0;
                float v1 = acc[mt][nt][2 * h + 1] + b1;
                if (RELU) { v0 = fmaxf(v0, 0.f); v1 = fmaxf(v1, 0.f); }
                *(float2*)(C + (long)gm * ldc + gn) = make_float2(v0, v1);
            }
        }
    }
}

// ---------------- flash attention (tf32 MMA + ldmatrix, online softmax) ----------------
// Grid: (TT/128, NHEAD). 256 threads (8 warps; warp = 16 Q rows).
// Smem word layout (u32):
//   Qs  [128][100]      @ 0
//   Ks  [2][64][100]    @ 12800     ([kv][dim])
//   Vt  [2][96][68]     @ 25600     ([dim][kv]  = V^T)
//   Ps  [128][68]       @ 38656
#define FQ_P 100
#define FK_P 100
#define FVT_P 68
#define FP_P 68
#define FQ_OFF 0
#define FK_OFF 12800
#define FVT_OFF 25600
#define FP_OFF 38656
#define FLASH_SMEM ((38656 + 128 * 68) * 4)

__global__ __launch_bounds__(256, 1)
void flash_kernel(const float* __restrict__ Q, const float* __restrict__ K,
                  const float* __restrict__ V, float* __restrict__ O, float scale)
{
    extern __shared__ u32 sm[];
    u32* Qs = sm + FQ_OFF;
    u32* Ks = sm + FK_OFF;
    u32* Vt = sm + FVT_OFF;
    u32* Ps = sm + FP_OFF;

    const int tid  = threadIdx.x;
    const int lane = tid & 31;
    const int warp = tid >> 5;
    const int lr   = lane >> 2;
    const int lc   = lane & 3;
    const int ph   = lane >> 3;
    const int rr   = lane & 7;
    const int wm   = warp * 16;
    const int mt0  = blockIdx.x * 128;
    const int head = blockIdx.y;

    const int aoff_row = rr + (ph & 1) * 8;
    const int aoff_col = (ph >> 1) * 4;
    const int boff_row = rr + (ph >> 1) * 8;
    const int boff_col = (ph & 1) * 4;

    const u32 qs_base = s2u(Qs);
    const u32 ks_base = s2u(Ks);
    const u32 vt_base = s2u(Vt);
    const u32 ps_base = s2u(Ps);

    const float* Qb = Q + (long)mt0 * DIM + head * DK;
    const float* Kb = K + head * DK;
    const float* Vb = V + head * DK;

    // ---- load Q tile (128 x 96) as tf32 ----
#pragma unroll
    for (int it = 0; it < 12; it++) {
        int id  = tid + it * 256;
        int row = id / 24;
        int c4  = (id % 24) * 4;
        float4 f = *(const float4*)(Qb + (long)row * DIM + c4);
        uint4 q;
        q.x = f2tf32(f.x); q.y = f2tf32(f.y); q.z = f2tf32(f.z); q.w = f2tf32(f.w);
        *(uint4*)&Qs[row * FQ_P + c4] = q;
    }

    // ---- K/V prefetch machinery (64 x 96 tiles) ----
    float4 rk[6], rv[6];
    auto fetch = [&](int t) {
        int kv0 = t * 64;
#pragma unroll
        for (int it = 0; it < 6; it++) {
            int id  = tid + it * 256;
            int row = id / 24;
            int c4  = (id % 24) * 4;
            rk[it] = *(const float4*)(Kb + (long)(kv0 + row) * DIM + c4);
            rv[it] = *(const float4*)(Vb + (long)(kv0 + row) * DIM + c4);
        }
    };
    auto stage = [&](int buf) {
#pragma unroll
        for (int it = 0; it < 6; it++) {
            int id  = tid + it * 256;
            int row = id / 24;
            int c4  = (id % 24) * 4;
            uint4 qk;
            qk.x = f2tf32(rk[it].x); qk.y = f2tf32(rk[it].y);
            qk.z = f2tf32(rk[it].z); qk.w = f2tf32(rk[it].w);
            *(uint4*)&Ks[(buf * 64 + row) * FK_P + c4] = qk;
            // V transposed into Vt[dim][kv]
            Vt[(buf * 96 + c4 + 0) * FVT_P + row] = f2tf32(rv[it].x);
            Vt[(buf * 96 + c4 + 1) * FVT_P + row] = f2tf32(rv[it].y);
            Vt[(buf * 96 + c4 + 2) * FVT_P + row] = f2tf32(rv[it].z);
            Vt[(buf * 96 + c4 + 3) * FVT_P + row] = f2tf32(rv[it].w);
        }
    };

    float oacc[12][4];
#pragma unroll
    for (int i = 0; i < 12; i++)
#pragma unroll
        for (int c = 0; c < 4; c++) oacc[i][c] = 0.f;
    float mrow0 = -1e30f, mrow1 = -1e30f, lrow0 = 0.f, lrow1 = 0.f;

    fetch(0);
    stage(0);
    __syncthreads();

    const int NIT = TT / 64;   // 36
    for (int t = 0; t < NIT; t++) {
        const int cur = t & 1;
        const bool hn = (t + 1 < NIT);
        if (hn) fetch(t + 1);

        // ---- S = Q K^T over this 64-kv tile (warp: 16 x 64) ----
        float sacc[8][4];
#pragma unroll
        for (int nt = 0; nt < 8; nt++)
#pragma unroll
            for (int c = 0; c < 4; c++) sacc[nt][c] = 0.f;

#pragma unroll
        for (int ks = 0; ks < 12; ks++) {
            const int k0 = ks * 8;
            u32 a0, a1, a2, a3;
            ldsm_x4(a0, a1, a2, a3,
                    qs_base + 4u * (u32)((wm + aoff_row) * FQ_P + k0 + aoff_col));
            u32 bf[8][2];
#pragma unroll
            for (int p = 0; p < 4; p++) {
                u32 addr = ks_base + 4u * (u32)((cur * 64 + p * 16 + boff_row) * FK_P
                                                + k0 + boff_col);
                ldsm_x4(bf[2 * p][0], bf[2 * p][1], bf[2 * p + 1][0], bf[2 * p + 1][1], addr);
            }
#pragma unroll
            for (int nt = 0; nt < 8; nt++)
                mma_tf32(sacc[nt][0], sacc[nt][1], sacc[nt][2], sacc[nt][3],
                         a0, a1, a2, a3, bf[nt][0], bf[nt][1]);
        }

        // ---- online softmax (rows lr, lr+8; intra-warp over lc group) ----
        float rm0 = -1e30f, rm1 = -1e30f;
#pragma unroll
        for (int nt = 0; nt < 8; nt++) {
            rm0 = fmaxf(rm0, fmaxf(sacc[nt][0], sacc[nt][1]));
            rm1 = fmaxf(rm1, fmaxf(sacc[nt][2], sacc[nt][3]));
        }
        rm0 *= scale; rm1 *= scale;
#pragma unroll
        for (int o = 1; o <= 2; o <<= 1) {
            rm0 = fmaxf(rm0, __shfl_xor_sync(0xffffffffu, rm0, o));
            rm1 = fmaxf(rm1, __shfl_xor_sync(0xffffffffu, rm1, o));
        }
        float mn0 = fmaxf(mrow0, rm0);
        float mn1 = fmaxf(mrow1, rm1);
        float al0 = __expf(mrow0 - mn0);
        float al1 = __expf(mrow1 - mn1);
        float sum0 = 0.f, sum1 = 0.f;
#pragma unroll
        for (int nt = 0; nt < 8; nt++) {
            float p0 = __expf(sacc[nt][0] * scale - mn0);
            float p1 = __expf(sacc[nt][1] * scale - mn0);
            float p2 = __expf(sacc[nt][2] * scale - mn1);
            float p3 = __expf(sacc[nt][3] * scale - mn1);
            sum0 += p0 + p1; sum1 += p2 + p3;
            uint2 w0; w0.x = f2tf32(p0); w0.y = f2tf32(p1);
            uint2 w1; w1.x = f2tf32(p2); w1.y = f2tf32(p3);
            *(uint2*)&Ps[(wm + lr) * FP_P + nt * 8 + 2 * lc]     = w0;
            *(uint2*)&Ps[(wm + lr + 8) * FP_P + nt * 8 + 2 * lc] = w1;
        }
#pragma unroll
        for (int o = 1; o <= 2; o <<= 1) {
            sum0 += __shfl_xor_sync(0xffffffffu, sum0, o);
            sum1 += __shfl_xor_sync(0xffffffffu, sum1, o);
        }
        lrow0 = lrow0 * al0 + sum0;
        lrow1 = lrow1 * al1 + sum1;
        mrow0 = mn0; mrow1 = mn1;
#pragma unroll
        for (int nt = 0; nt < 12; nt++) {
            oacc[nt][0] *= al0; oacc[nt][1] *= al0;
            oacc[nt][2] *= al1; oacc[nt][3] *= al1;
        }
        __syncthreads();          // Ps visible; Ks[cur] consumed

        if (hn) stage(cur ^ 1);

        // ---- O += P V  (warp: 16 x 96) ----
#pragma unroll
        for (int ksv = 0; ksv < 8; ksv++) {
            const int k0 = ksv * 8;
            u32 a0, a1, a2, a3;
            ldsm_x4(a0, a1, a2, a3,
                    ps_base + 4u * (u32)((wm + aoff_row) * FP_P + k0 + aoff_col));
            u32 bf[12][2];
#pragma unroll
            for (int p = 0; p < 6; p++) {
                u32 addr = vt_base + 4u * (u32)((cur * 96 + p * 16 + boff_row) * FVT_P
                                                + k0 + boff_col);
                ldsm_x4(bf[2 * p][0], bf[2 * p][1], bf[2 * p + 1][0], bf[2 * p + 1][1], addr);
            }
#pragma unroll
            for (int nt = 0; nt < 12; nt++)
                mma_tf32(oacc[nt][0], oacc[nt][1], oacc[nt][2], oacc[nt][3],
                         a0, a1, a2, a3, bf[nt][0], bf[nt][1]);
        }
        __syncthreads();          // Vt[cur]/Ps consumed; stage STS complete
    }

    // ---- normalize + write ----
    float inv0 = 1.f / lrow0;
    float inv1 = 1.f / lrow1;
    int r0 = mt0 + wm + lr;
    int r1 = r0 + 8;
#pragma unroll
    for (int nt = 0; nt < 12; nt++) {
        int col = head * DK + nt * 8 + 2 * lc;
        *(float2*)(O + (long)r0 * DIM + col) = make_float2(oacc[nt][0] * inv0, oacc[nt][1] * inv0);
        *(float2*)(O + (long)r1 * DIM + col) = make_float2(oacc[nt][2] * inv1, oacc[nt][3] * inv1);
    }
}

// ---------------- span max pooling ----------------
__global__ void pool_kernel(const float* __restrict__ emb, const int* __restrict__ spans,
                            float* __restrict__ htb)
{
    int node = blockIdx.x;
    int bag  = node / NPD;
    int s0 = spans[node * 2 + 0];
    int s1 = spans[node * 2 + 1];
    const float* base = emb + (long)bag * SEQ * DIM;
    for (int d = threadIdx.x; d < DIM; d += blockDim.x) {
        float m = -3.4e38f;
        for (int p = s0; p <= s1; p++)
            m = fmaxf(m, base[(long)p * DIM + d]);
        htb[(long)node * DIM + d] = m;
    }
}

// ---------------- pairwise relu(u_i + v_j) ----------------
__global__ void build_pair_kernel(const float* __restrict__ u, const float* __restrict__ v,
                                  float* __restrict__ out)
{
    int t = blockIdx.x;
    int i = t / NN_, j = t % NN_;
    const float* ur = u + (long)i * DIM;
    const float* vr = v + (long)j * DIM;
    float* o = out + (long)t * DIM;
#pragma unroll
    for (int it = 0; it < DIM / 256; it++) {
        int d = threadIdx.x + it * 256;
        o[d] = fmaxf(ur[d] + vr[d], 0.f);
    }
}

// ---------------- x = LN(x + o) * g + b ----------------
__global__ void add_ln_kernel(float* __restrict__ x, const float* __restrict__ o,
                              const float* __restrict__ g, const float* __restrict__ b)
{
    long base = (long)blockIdx.x * DIM;
    float* xr = x + base;
    const float* orr = o + base;
    __shared__ float sh[32];
    float v[3];
    float s = 0.f, s2 = 0.f;
#pragma unroll
    for (int i = 0; i < 3; i++) {
        int d = threadIdx.x + i * 256;
        float t = xr[d] + orr[d];
        v[i] = t; s += t; s2 += t * t;
    }
    s  = blk_reduce(s,  sh, false);
    s2 = blk_reduce(s2, sh, false);
    float mean = s * (1.f / DIM);
    float var  = s2 * (1.f / DIM) - mean * mean;
    float inv  = rsqrtf(var + 1e-5f);
#pragma unroll
    for (int i = 0; i < 3; i++) {
        int d = threadIdx.x + i * 256;
        xr[d] = (v[i] - mean) * inv * g[d] + b[d];
    }
}

// ---------------- final: gather (h,t) cells, LN, predictor ----------------
__global__ void final_kernel(const float* __restrict__ x, const float* __restrict__ ng,
                             const float* __restrict__ nb, const float* __restrict__ Wp,
                             const float* __restrict__ bp, float* __restrict__ ht)
{
    int bag = blockIdx.x;
    long r = (long)(bag * NPD) * NN_ + (bag * NPD + 1);
    const float* row = x + r * DIM;
    __shared__ float sh[DIM];
    __shared__ float red[32];
    float s = 0.f, s2 = 0.f;
    for (int d = threadIdx.x; d < DIM; d += blockDim.x) {
        float t = row[d];
        sh[d] = t; s += t; s2 += t * t;
    }
    s  = blk_reduce(s,  red, false);
    s2 = blk_reduce(s2, red, false);
    float mean = s * (1.f / DIM);
    float inv  = rsqrtf(s2 * (1.f / DIM) - mean * mean + 1e-5f);
    __syncthreads();
    for (int d = threadIdx.x; d < DIM; d += blockDim.x)
        sh[d] = (sh[d] - mean) * inv * ng[d] + nb[d];
    __syncthreads();
    for (int n = threadIdx.x; n < NREL; n += blockDim.x) {
        float acc = bp[n];
        for (int k = 0; k < DIM; k++)
            acc = fmaf(sh[k], Wp[(long)k * NREL + n], acc);
        ht[bag * NREL + n] = acc;
    }
}

// ---------------- output assembly: bag max + layout ----------------
__global__ void writeout_kernel(const float* __restrict__ ht, float* __restrict__ out,
                                int out_size)
{
    int n = threadIdx.x;
    if (n >= NREL) return;
    float m = -3.4e38f;
    for (int b = 0; b < BAG; b++) m = fmaxf(m, ht[b * NREL + n]);
    if (out_size >= NREL * (BAG + 1)) {
        out[n] = m;
        for (int b = 0; b < BAG; b++) out[NREL + b * NREL + n] = ht[b * NREL + n];
    } else if (out_size == NREL) {
        out[n] = m;
    } else {
        for (int b = 0; b < BAG; b++) out[b * NREL + n] = ht[b * NREL + n];
    }
}

// ---------------- host ----------------
template <typename T>
static inline float* sym(T& s) {
    void* p = nullptr;
    cudaGetSymbolAddress(&p, s);
    return (float*)p;
}

extern "C" void kernel_launch(void* const* d_in, const int* in_sizes, int n_in,
                              void* d_out, int out_size)
{
    const float* emb   = (const float*)d_in[0];
    const int*   spans = (const int*)  d_in[1];
    const float* Wu = (const float*)d_in[2];  const float* bu = (const float*)d_in[3];
    const float* Wv = (const float*)d_in[4];  const float* bv = (const float*)d_in[5];
    const float* Wl = (const float*)d_in[6];  const float* bl = (const float*)d_in[7];
    const float* Wq = (const float*)d_in[8];  const float* bq = (const float*)d_in[9];
    const float* Wk = (const float*)d_in[10]; const float* bk = (const float*)d_in[11];
    const float* Wvm= (const float*)d_in[12]; const float* bvm= (const float*)d_in[13];
    const float* Wo = (const float*)d_in[14]; const float* bo = (const float*)d_in[15];
    const float* F1 = (const float*)d_in[16]; const float* f1 = (const float*)d_in[17];
    const float* F2 = (const float*)d_in[18]; const float* f2 = (const float*)d_in[19];
    const float* g1 = (const float*)d_in[20]; const float* be1= (const float*)d_in[21];
    const float* g2 = (const float*)d_in[22]; const float* be2= (const float*)d_in[23];
    const float* ng = (const float*)d_in[24]; const float* nb = (const float*)d_in[25];
    const float* Wp = (const float*)d_in[26]; const float* bp = (const float*)d_in[27];

    float* htb = sym(g_htb);
    float* u   = sym(g_u);
    float* v   = sym(g_v);
    float* x   = sym(g_x);
    float* q   = sym(g_q);
    float* k   = sym(g_k);
    float* vv  = sym(g_vv);
    float* attn= sym(g_attn);
    float* tmp = sym(g_tmp);
    float* ffn = sym(g_ffn);
    float* ht  = sym(g_ht);
    float* out = (float*)d_out;

    const float scale = 0.102062072615966f;   // 1/sqrt(96)

    cudaFuncSetAttribute(flash_kernel, cudaFuncAttributeMaxDynamicSharedMemorySize,
                         FLASH_SMEM);

    const dim3 gridN768_T(8, 18);    // N=768 via BN=96, M=2304
    const dim3 gridN768_s(8, 1);     // N=768, M=48
    const dim3 gridFFN1(8, 18);      // N=1024 via BN=128
    const dim3 gridFFN2(8, 18);      // N=768 via BN=96, K=1024

    // 1) span max pooling -> htb [48,768]
    pool_kernel<<<NN_, 256>>>(emb, spans, htb);

    // 2) u = htb@Wu+bu ; v = htb@Wv+bv
    gemm_tc<3,true,false><<<gridN768_s, 256>>>(htb, Wu, bu, u, NN_, DIM, DIM, DIM, DIM, DIM);
    gemm_tc<3,true,false><<<gridN768_s, 256>>>(htb, Wv, bv, v, NN_, DIM, DIM, DIM, DIM, DIM);

    // 3) pair = relu(u_i + v_j) ; x = relu(pair @ Wl + bl)
    build_pair_kernel<<<TT, 256>>>(u, v, tmp);
    gemm_tc<3,true,true><<<gridN768_T, 256>>>(tmp, Wl, bl, x, TT, DIM, DIM, DIM, DIM, DIM);

    // 4) MatTransformer layers
    for (int l = 0; l < NLAYER; l++) {
        const float* Wq_l = Wq + (size_t)l * DIM * DIM;  const float* bq_l = bq + (size_t)l * DIM;
        const float* Wk_l = Wk + (size_t)l * DIM * DIM;  const float* bk_l = bk + (size_t)l * DIM;
        const float* Wv_l = Wvm+ (size_t)l * DIM * DIM;  const float* bv_l = bvm+ (size_t)l * DIM;
        const float* Wo_l = Wo + (size_t)l * DIM * DIM;  const float* bo_l = bo + (size_t)l * DIM;
        const float* F1_l = F1 + (size_t)l * DIM * DFF;  const float* f1_l = f1 + (size_t)l * DFF;
        const float* F2_l = F2 + (size_t)l * DFF * DIM;  const float* f2_l = f2 + (size_t)l * DIM;
        const float* g1_l = g1 + (size_t)l * DIM;        const float* be1_l= be1+ (size_t)l * DIM;
        const float* g2_l = g2 + (size_t)l * DIM;        const float* be2_l= be2+ (size_t)l * DIM;

        // QKV projections
        gemm_tc<3,true,false><<<gridN768_T, 256>>>(x, Wq_l, bq_l, q, TT, DIM, DIM, DIM, DIM, DIM);
        gemm_tc<3,true,false><<<gridN768_T, 256>>>(x, Wk_l, bk_l, k, TT, DIM, DIM, DIM, DIM, DIM);
        gemm_tc<3,true,false><<<gridN768_T, 256>>>(x, Wv_l, bv_l, vv, TT, DIM, DIM, DIM, DIM, DIM);

        // fused attention: softmax(QK^T * scale) @ V  -> attn
        flash_kernel<<<dim3(TT / 128, NHEAD), 256, FLASH_SMEM>>>(q, k, vv, attn, scale);

        // output projection + residual LN
        gemm_tc<3,true,false><<<gridN768_T, 256>>>(attn, Wo_l, bo_l, tmp, TT, DIM, DIM, DIM, DIM, DIM);
        add_ln_kernel<<<TT, 256>>>(x, tmp, g1_l, be1_l);

        // FFN + residual LN
        gemm_tc<4,true,true><<<gridFFN1, 256>>>(x, F1_l, f1_l, ffn, TT, DFF, DIM, DIM, DFF, DFF);
        gemm_tc<3,true,false><<<gridFFN2, 256>>>(ffn, F2_l, f2_l, tmp, TT, DIM, DFF, DFF, DIM, DIM);
        add_ln_kernel<<<TT, 256>>>(x, tmp, g2_l, be2_l);
    }

    // 5) final gather + LN + predictor + bag max
    final_kernel<<<BAG, 256>>>(x, ng, nb, Wp, bp, ht);
    writeout_kernel<<<1, 128>>>(ht, out, out_size);
}

// round 10
// speedup vs baseline: 1.4298x; 1.4298x over previous
#include <cuda_runtime.h>
#include <cuda_fp16.h>
#include <cstdint>

// ---------------- problem constants ----------------
#define BAG  8
#define SEQ  512
#define DIM  768
#define NPD  6
#define NN_  48          // N nodes
#define TT   2304        // T = N*N
#define NHEAD 8
#define DK   96
#define DFF  1024
#define NLAYER 4
#define NREL 97

typedef uint32_t u32;

// ---------------- device scratch (no allocations allowed) ----------------
__device__ float g_htb [NN_ * DIM];
__device__ float g_u   [NN_ * DIM];
__device__ float g_v   [NN_ * DIM];
__device__ float g_x   [TT * DIM];
__device__ float g_q   [TT * DIM];
__device__ float g_k   [TT * DIM];
__device__ float g_vv  [TT * DIM];
__device__ float g_attn[TT * DIM];
__device__ float g_tmp [TT * DIM];
__device__ float g_ffn [TT * DFF];
__device__ float g_ht  [BAG * NREL];

// ---------------- fp16 / ldmatrix helpers ----------------
__device__ __forceinline__ u32 pack_h2(float a, float b) {
    __half2 h = __floats2half2_rn(a, b);      // .x = a (low), .y = b (high)
    return *(u32*)&h;
}
__device__ __forceinline__ void mma_f16(float& c0, float& c1, float& c2, float& c3,
                                        u32 a0, u32 a1, u32 a2, u32 a3,
                                        u32 b0, u32 b1) {
    asm("mma.sync.aligned.m16n8k16.row.col.f32.f16.f16.f32 "
        "{%0,%1,%2,%3}, {%4,%5,%6,%7}, {%8,%9}, {%0,%1,%2,%3};"
        : "+f"(c0), "+f"(c1), "+f"(c2), "+f"(c3)
        : "r"(a0), "r"(a1), "r"(a2), "r"(a3), "r"(b0), "r"(b1));
}
__device__ __forceinline__ u32 s2u(const void* p) {
    return (u32)__cvta_generic_to_shared(p);
}
__device__ __forceinline__ void ldsm_x4(u32& r0, u32& r1, u32& r2, u32& r3, u32 addr) {
    asm volatile("ldmatrix.sync.aligned.m8n8.x4.shared.b16 {%0,%1,%2,%3}, [%4];"
                 : "=r"(r0), "=r"(r1), "=r"(r2), "=r"(r3) : "r"(addr));
}
__device__ __forceinline__ void ldsm_x4t(u32& r0, u32& r1, u32& r2, u32& r3, u32 addr) {
    asm volatile("ldmatrix.sync.aligned.m8n8.x4.trans.shared.b16 {%0,%1,%2,%3}, [%4];"
                 : "=r"(r0), "=r"(r1), "=r"(r2), "=r"(r3) : "r"(addr));
}
__device__ __forceinline__ void ldsm_x2t(u32& r0, u32& r1, u32 addr) {
    asm volatile("ldmatrix.sync.aligned.m8n8.x2.trans.shared.b16 {%0,%1}, [%2];"
                 : "=r"(r0), "=r"(r1) : "r"(addr));
}

// ---------------- block reduction helper ----------------
__device__ __forceinline__ float blk_reduce(float val, float* sh, bool do_max) {
    const unsigned mask = 0xffffffffu;
#pragma unroll
    for (int o = 16; o > 0; o >>= 1) {
        float other = __shfl_xor_sync(mask, val, o);
        val = do_max ? fmaxf(val, other) : (val + other);
    }
    int lane = threadIdx.x & 31, w = threadIdx.x >> 5;
    __syncthreads();
    if (lane == 0) sh[w] = val;
    __syncthreads();
    int nw = (blockDim.x + 31) >> 5;
    if (w == 0) {
        val = (lane < nw) ? sh[lane] : (do_max ? -3.4e38f : 0.f);
#pragma unroll
        for (int o = 16; o > 0; o >>= 1) {
            float other = __shfl_xor_sync(mask, val, o);
            val = do_max ? fmaxf(val, other) : (val + other);
        }
        if (lane == 0) sh[0] = val;
    }
    __syncthreads();
    return sh[0];
}

// ---------------- 128xBN fp16 tensor-core GEMM ----------------
// C[m,n] = sum_k A[m,k] * B[k,n]  (+bias) (ReLU).  BN = 32*NT.
// Requires: K % 16 == 0, N % BN == 0, lda % 4 == 0.
template<int NT, bool BIAS, bool RELU>
__global__ __launch_bounds__(256)
void gemm_tc(const float* __restrict__ A, const float* __restrict__ B,
             const float* __restrict__ bias, float* __restrict__ C,
             int M, int N, int K, int lda, int ldb, int ldc)
{
    constexpr int BN = 32 * NT;
    constexpr int BK = 16;
    constexpr int AP = 24;          // 48B row stride (3x16B, odd) -> conflict-free ldsm
    constexpr int BP = BN + 8;      // 104/136 halfs -> 13/17 x16B, odd

    __shared__ __half As[2][128][AP];
    __shared__ __half Bs[2][BK][BP];

    const int tid  = threadIdx.x;
    const int lane = tid & 31;
    const int warp = tid >> 5;
    const int wR   = (warp & 1) * 64;
    const int wC   = (warp >> 1) * (8 * NT);
    const int row0 = blockIdx.y * 128;
    const int col0 = blockIdx.x * BN;
    const int lr   = lane >> 2;
    const int lc   = lane & 3;
    const int ph   = lane >> 3;     // 0..3
    const int rr   = lane & 7;

    // ldmatrix per-thread source rows/cols
    const int arow = rr + (ph & 1) * 8;           // A (non-trans, row-major [m][k])
    const int acol = (ph >> 1) * 8;
    const int tkrow = rr + (ph & 1) * 8;          // B (.trans over [k][n])
    const int tncol = (ph >> 1) * 8;

    // staging maps
    const int ar = tid >> 1;
    const int ac = (tid & 1) * 8;
    int kb0, nb0, kb1 = 0, nb1 = 0;
    bool b1v;
    if (NT == 4) {
        kb0 = tid >> 5;        nb0 = (tid & 31) * 4;
        kb1 = kb0 + 8;         nb1 = nb0;           b1v = true;
    } else {                   // NT == 3: 384 float4 tasks
        kb0 = tid / 24;        nb0 = (tid % 24) * 4;
        b1v = (tid < 128);
        int id1 = tid + 256;
        kb1 = id1 / 24;        nb1 = (id1 % 24) * 4;
    }

    const float4 f4z = make_float4(0.f, 0.f, 0.f, 0.f);
    float4 fa0, fa1, fb0, fb1;

    float acc[4][NT][4];
#pragma unroll
    for (int i = 0; i < 4; i++)
#pragma unroll
        for (int j = 0; j < NT; j++)
#pragma unroll
            for (int c = 0; c < 4; c++) acc[i][j][c] = 0.f;

    const int KT = K / BK;

    auto fetch = [&](int k0g) {
        int gm = row0 + ar;
        const float* ap = A + (long)gm * lda + k0g + ac;
        fa0 = (gm < M) ? *(const float4*)ap : f4z;
        fa1 = (gm < M) ? *(const float4*)(ap + 4) : f4z;
        fb0 = *(const float4*)(B + (long)(k0g + kb0) * ldb + col0 + nb0);
        if (b1v) fb1 = *(const float4*)(B + (long)(k0g + kb1) * ldb + col0 + nb1);
    };
    auto stage = [&](int buf) {
        uint4 qa;
        qa.x = pack_h2(fa0.x, fa0.y); qa.y = pack_h2(fa0.z, fa0.w);
        qa.z = pack_h2(fa1.x, fa1.y); qa.w = pack_h2(fa1.z, fa1.w);
        *(uint4*)&As[buf][ar][ac] = qa;
        uint2 qb0;
        qb0.x = pack_h2(fb0.x, fb0.y); qb0.y = pack_h2(fb0.z, fb0.w);
        *(uint2*)&Bs[buf][kb0][nb0] = qb0;
        if (b1v) {
            uint2 qb1;
            qb1.x = pack_h2(fb1.x, fb1.y); qb1.y = pack_h2(fb1.z, fb1.w);
            *(uint2*)&Bs[buf][kb1][nb1] = qb1;
        }
    };

    fetch(0);
    stage(0);
    __syncthreads();

    for (int kt = 0; kt < KT; kt++) {
        const int cur = kt & 1;
        const bool hn = (kt + 1 < KT);
        if (hn) fetch((kt + 1) * BK);

        u32 af[4][4], bf[NT][2];
#pragma unroll
        for (int mt = 0; mt < 4; mt++)
            ldsm_x4(af[mt][0], af[mt][1], af[mt][2], af[mt][3],
                    s2u(&As[cur][wR + mt * 16 + arow][acol]));
#pragma unroll
        for (int p = 0; p < NT / 2; p++)
            ldsm_x4t(bf[2 * p][0], bf[2 * p][1], bf[2 * p + 1][0], bf[2 * p + 1][1],
                     s2u(&Bs[cur][tkrow][wC + p * 16 + tncol]));
        if (NT & 1)
            ldsm_x2t(bf[NT - 1][0], bf[NT - 1][1],
                     s2u(&Bs[cur][tkrow][wC + (NT - 1) * 8]));
#pragma unroll
        for (int mt = 0; mt < 4; mt++)
#pragma unroll
            for (int nt = 0; nt < NT; nt++)
                mma_f16(acc[mt][nt][0], acc[mt][nt][1], acc[mt][nt][2], acc[mt][nt][3],
                        af[mt][0], af[mt][1], af[mt][2], af[mt][3],
                        bf[nt][0], bf[nt][1]);

        if (hn) stage(cur ^ 1);
        __syncthreads();
    }

    // ---- epilogue ----
#pragma unroll
    for (int nt = 0; nt < NT; nt++) {
        int gn = col0 + wC + nt * 8 + 2 * lc;
        float b0 = 0.f, b1 = 0.f;
        if (BIAS) { b0 = bias[gn]; b1 = bias[gn + 1]; }
#pragma unroll
        for (int mt = 0; mt < 4; mt++) {
            int gm0 = row0 + wR + mt * 16 + lr;
#pragma unroll
            for (int h = 0; h < 2; h++) {
                int gm = gm0 + h * 8;
                if (gm >= M) continue;
                float v0 = acc[mt][nt][2 * h]     + b0;
                float v1 = acc[mt][nt][2 * h + 1] + b1;
                if (RELU) { v0 = fmaxf(v0, 0.f); v1 = fmaxf(v1, 0.f); }
                *(float2*)(C + (long)gm * ldc + gn) = make_float2(v0, v1);
            }
        }
    }
}

// ---------------- flash attention (fp16 MMA + ldmatrix, online softmax) ----------------
// Grid: (TT/128, NHEAD). 256 threads (8 warps; warp = 16 Q rows).
// Smem half layout:
//   Qs [128][104]     @ 0        ([q][dim])
//   Ks [2][64][104]   @ 13312    ([kv][dim])
//   Vs [2][64][104]   @ 26624    ([kv][dim])
//   Ps [128][72]      @ 39936    ([q][kv])
#define FQ_P 104
#define FK_P 104
#define FV_P 104
#define FP_P 72
#define FQ_OFF 0
#define FK_OFF 13312
#define FV_OFF 26624
#define FP_OFF 39936
#define FLASH_SMEM ((39936 + 128 * 72) * 2)

__global__ __launch_bounds__(256)
void flash_kernel(const float* __restrict__ Q, const float* __restrict__ K,
                  const float* __restrict__ V, float* __restrict__ O, float scale)
{
    extern __shared__ __half smh[];
    __half* Qs = smh + FQ_OFF;
    __half* Ks = smh + FK_OFF;
    __half* Vs = smh + FV_OFF;
    __half* Ps = smh + FP_OFF;

    const int tid  = threadIdx.x;
    const int lane = tid & 31;
    const int warp = tid >> 5;
    const int lr   = lane >> 2;
    const int lc   = lane & 3;
    const int ph   = lane >> 3;
    const int rr   = lane & 7;
    const int wm   = warp * 16;
    const int mt0  = blockIdx.x * 128;
    const int head = blockIdx.y;

    const int arow = rr + (ph & 1) * 8;      // non-trans ldsm (A-style)
    const int acol = (ph >> 1) * 8;
    const int brow = rr + (ph >> 1) * 8;     // non-trans ldsm (B [n][k]-style)
    const int bcol = (ph & 1) * 8;
    const int tkrow = rr + (ph & 1) * 8;     // trans ldsm (B [k][n]-style)
    const int tncol = (ph >> 1) * 8;

    const float* Qb = Q + (long)mt0 * DIM + head * DK;
    const float* Kb = K + head * DK;
    const float* Vb = V + head * DK;

    // ---- load Q tile (128 x 96) as fp16 ----
#pragma unroll
    for (int it = 0; it < 12; it++) {
        int id  = tid + it * 256;
        int row = id / 24;
        int c4  = (id % 24) * 4;
        float4 f = *(const float4*)(Qb + (long)row * DIM + c4);
        uint2 q;
        q.x = pack_h2(f.x, f.y); q.y = pack_h2(f.z, f.w);
        *(uint2*)&Qs[row * FQ_P + c4] = q;
    }

    // ---- K/V prefetch machinery (64 x 96 tiles) ----
    float4 rk[6], rv[6];
    auto fetch = [&](int t) {
        int kv0 = t * 64;
#pragma unroll
        for (int it = 0; it < 6; it++) {
            int id  = tid + it * 256;
            int row = id / 24;
            int c4  = (id % 24) * 4;
            rk[it] = *(const float4*)(Kb + (long)(kv0 + row) * DIM + c4);
            rv[it] = *(const float4*)(Vb + (long)(kv0 + row) * DIM + c4);
        }
    };
    auto stage = [&](int buf) {
#pragma unroll
        for (int it = 0; it < 6; it++) {
            int id  = tid + it * 256;
            int row = id / 24;
            int c4  = (id % 24) * 4;
            uint2 qk;
            qk.x = pack_h2(rk[it].x, rk[it].y); qk.y = pack_h2(rk[it].z, rk[it].w);
            *(uint2*)&Ks[(buf * 64 + row) * FK_P + c4] = qk;
            uint2 qv;
            qv.x = pack_h2(rv[it].x, rv[it].y); qv.y = pack_h2(rv[it].z, rv[it].w);
            *(uint2*)&Vs[(buf * 64 + row) * FV_P + c4] = qv;
        }
    };

    float oacc[12][4];
#pragma unroll
    for (int i = 0; i < 12; i++)
#pragma unroll
        for (int c = 0; c < 4; c++) oacc[i][c] = 0.f;
    float mrow0 = -1e30f, mrow1 = -1e30f, lrow0 = 0.f, lrow1 = 0.f;

    fetch(0);
    stage(0);
    __syncthreads();

    const int NIT = TT / 64;   // 36
    for (int t = 0; t < NIT; t++) {
        const int cur = t & 1;
        const bool hn = (t + 1 < NIT);
        if (hn) fetch(t + 1);

        // ---- S = Q K^T over this 64-kv tile (warp: 16 x 64) ----
        float sacc[8][4];
#pragma unroll
        for (int nt = 0; nt < 8; nt++)
#pragma unroll
            for (int c = 0; c < 4; c++) sacc[nt][c] = 0.f;

#pragma unroll
        for (int ks = 0; ks < 6; ks++) {
            const int k0 = ks * 16;
            u32 a0, a1, a2, a3;
            ldsm_x4(a0, a1, a2, a3, s2u(&Qs[(wm + arow) * FQ_P + k0 + acol]));
            u32 bf[8][2];
#pragma unroll
            for (int p = 0; p < 4; p++)
                ldsm_x4(bf[2 * p][0], bf[2 * p][1], bf[2 * p + 1][0], bf[2 * p + 1][1],
                        s2u(&Ks[(cur * 64 + p * 16 + brow) * FK_P + k0 + bcol]));
#pragma unroll
            for (int nt = 0; nt < 8; nt++)
                mma_f16(sacc[nt][0], sacc[nt][1], sacc[nt][2], sacc[nt][3],
                        a0, a1, a2, a3, bf[nt][0], bf[nt][1]);
        }

        // ---- online softmax (rows lr, lr+8; intra-warp over lc group) ----
        float rm0 = -1e30f, rm1 = -1e30f;
#pragma unroll
        for (int nt = 0; nt < 8; nt++) {
            rm0 = fmaxf(rm0, fmaxf(sacc[nt][0], sacc[nt][1]));
            rm1 = fmaxf(rm1, fmaxf(sacc[nt][2], sacc[nt][3]));
        }
        rm0 *= scale; rm1 *= scale;
#pragma unroll
        for (int o = 1; o <= 2; o <<= 1) {
            rm0 = fmaxf(rm0, __shfl_xor_sync(0xffffffffu, rm0, o));
            rm1 = fmaxf(rm1, __shfl_xor_sync(0xffffffffu, rm1, o));
        }
        float mn0 = fmaxf(mrow0, rm0);
        float mn1 = fmaxf(mrow1, rm1);
        float al0 = __expf(mrow0 - mn0);
        float al1 = __expf(mrow1 - mn1);
        float sum0 = 0.f, sum1 = 0.f;
#pragma unroll
        for (int nt = 0; nt < 8; nt++) {
            float p0 = __expf(sacc[nt][0] * scale - mn0);
            float p1 = __expf(sacc[nt][1] * scale - mn0);
            float p2 = __expf(sacc[nt][2] * scale - mn1);
            float p3 = __expf(sacc[nt][3] * scale - mn1);
            sum0 += p0 + p1; sum1 += p2 + p3;
            *(u32*)&Ps[(wm + lr) * FP_P + nt * 8 + 2 * lc]     = pack_h2(p0, p1);
            *(u32*)&Ps[(wm + lr + 8) * FP_P + nt * 8 + 2 * lc] = pack_h2(p2, p3);
        }
#pragma unroll
        for (int o = 1; o <= 2; o <<= 1) {
            sum0 += __shfl_xor_sync(0xffffffffu, sum0, o);
            sum1 += __shfl_xor_sync(0xffffffffu, sum1, o);
        }
        lrow0 = lrow0 * al0 + sum0;
        lrow1 = lrow1 * al1 + sum1;
        mrow0 = mn0; mrow1 = mn1;
#pragma unroll
        for (int nt = 0; nt < 12; nt++) {
            oacc[nt][0] *= al0; oacc[nt][1] *= al0;
            oacc[nt][2] *= al1; oacc[nt][3] *= al1;
        }

        if (hn) stage(cur ^ 1);
        __syncwarp();             // Ps (warp-private) stores -> ldmatrix visibility

        // ---- O += P V  (warp: 16 x 96) ----
#pragma unroll
        for (int ksv = 0; ksv < 4; ksv++) {
            const int k0 = ksv * 16;
            u32 a0, a1, a2, a3;
            ldsm_x4(a0, a1, a2, a3, s2u(&Ps[(wm + arow) * FP_P + k0 + acol]));
            u32 bf[12][2];
#pragma unroll
            for (int p = 0; p < 6; p++)
                ldsm_x4t(bf[2 * p][0], bf[2 * p][1], bf[2 * p + 1][0], bf[2 * p + 1][1],
                         s2u(&Vs[(cur * 64 + k0 + tkrow) * FV_P + p * 16 + tncol]));
#pragma unroll
            for (int nt = 0; nt < 12; nt++)
                mma_f16(oacc[nt][0], oacc[nt][1], oacc[nt][2], oacc[nt][3],
                        a0, a1, a2, a3, bf[nt][0], bf[nt][1]);
        }
        __syncthreads();          // staged Ks/Vs[cur^1] complete; Ks/Vs[cur] consumed
    }

    // ---- normalize + write ----
    float inv0 = 1.f / lrow0;
    float inv1 = 1.f / lrow1;
    int r0 = mt0 + wm + lr;
    int r1 = r0 + 8;
#pragma unroll
    for (int nt = 0; nt < 12; nt++) {
        int col = head * DK + nt * 8 + 2 * lc;
        *(float2*)(O + (long)r0 * DIM + col) = make_float2(oacc[nt][0] * inv0, oacc[nt][1] * inv0);
        *(float2*)(O + (long)r1 * DIM + col) = make_float2(oacc[nt][2] * inv1, oacc[nt][3] * inv1);
    }
}

// ---------------- span max pooling ----------------
__global__ void pool_kernel(const float* __restrict__ emb, const int* __restrict__ spans,
                            float* __restrict__ htb)
{
    int node = blockIdx.x;
    int bag  = node / NPD;
    int s0 = spans[node * 2 + 0];
    int s1 = spans[node * 2 + 1];
    const float* base = emb + (long)bag * SEQ * DIM;
    for (int d = threadIdx.x; d < DIM; d += blockDim.x) {
        float m = -3.4e38f;
        for (int p = s0; p <= s1; p++)
            m = fmaxf(m, base[(long)p * DIM + d]);
        htb[(long)node * DIM + d] = m;
    }
}

// ---------------- pairwise relu(u_i + v_j) ----------------
__global__ void build_pair_kernel(const float* __restrict__ u, const float* __restrict__ v,
                                  float* __restrict__ out)
{
    int t = blockIdx.x;
    int i = t / NN_, j = t % NN_;
    const float* ur = u + (long)i * DIM;
    const float* vr = v + (long)j * DIM;
    float* o = out + (long)t * DIM;
#pragma unroll
    for (int it = 0; it < DIM / 256; it++) {
        int d = threadIdx.x + it * 256;
        o[d] = fmaxf(ur[d] + vr[d], 0.f);
    }
}

// ---------------- x = LN(x + o) * g + b ----------------
__global__ void add_ln_kernel(float* __restrict__ x, const float* __restrict__ o,
                              const float* __restrict__ g, const float* __restrict__ b)
{
    long base = (long)blockIdx.x * DIM;
    float* xr = x + base;
    const float* orr = o + base;
    __shared__ float sh[32];
    float v[3];
    float s = 0.f, s2 = 0.f;
#pragma unroll
    for (int i = 0; i < 3; i++) {
        int d = threadIdx.x + i * 256;
        float t = xr[d] + orr[d];
        v[i] = t; s += t; s2 += t * t;
    }
    s  = blk_reduce(s,  sh, false);
    s2 = blk_reduce(s2, sh, false);
    float mean = s * (1.f / DIM);
    float var  = s2 * (1.f / DIM) - mean * mean;
    float inv  = rsqrtf(var + 1e-5f);
#pragma unroll
    for (int i = 0; i < 3; i++) {
        int d = threadIdx.x + i * 256;
        xr[d] = (v[i] - mean) * inv * g[d] + b[d];
    }
}

// ---------------- final: gather (h,t) cells, LN, predictor ----------------
__global__ void final_kernel(const float* __restrict__ x, const float* __restrict__ ng,
                             const float* __restrict__ nb, const float* __restrict__ Wp,
                             const float* __restrict__ bp, float* __restrict__ ht)
{
    int bag = blockIdx.x;
    long r = (long)(bag * NPD) * NN_ + (bag * NPD + 1);
    const float* row = x + r * DIM;
    __shared__ float sh[DIM];
    __shared__ float red[32];
    float s = 0.f, s2 = 0.f;
    for (int d = threadIdx.x; d < DIM; d += blockDim.x) {
        float t = row[d];
        sh[d] = t; s += t; s2 += t * t;
    }
    s  = blk_reduce(s,  red, false);
    s2 = blk_reduce(s2, red, false);
    float mean = s * (1.f / DIM);
    float inv  = rsqrtf(s2 * (1.f / DIM) - mean * mean + 1e-5f);
    __syncthreads();
    for (int d = threadIdx.x; d < DIM; d += blockDim.x)
        sh[d] = (sh[d] - mean) * inv * ng[d] + nb[d];
    __syncthreads();
    for (int n = threadIdx.x; n < NREL; n += blockDim.x) {
        float acc = bp[n];
        for (int k = 0; k < DIM; k++)
            acc = fmaf(sh[k], Wp[(long)k * NREL + n], acc);
        ht[bag * NREL + n] = acc;
    }
}

// ---------------- output assembly: bag max + layout ----------------
__global__ void writeout_kernel(const float* __restrict__ ht, float* __restrict__ out,
                                int out_size)
{
    int n = threadIdx.x;
    if (n >= NREL) return;
    float m = -3.4e38f;
    for (int b = 0; b < BAG; b++) m = fmaxf(m, ht[b * NREL + n]);
    if (out_size >= NREL * (BAG + 1)) {
        out[n] = m;
        for (int b = 0; b < BAG; b++) out[NREL + b * NREL + n] = ht[b * NREL + n];
    } else if (out_size == NREL) {
        out[n] = m;
    } else {
        for (int b = 0; b < BAG; b++) out[b * NREL + n] = ht[b * NREL + n];
    }
}

// ---------------- host ----------------
template <typename T>
static inline float* sym(T& s) {
    void* p = nullptr;
    cudaGetSymbolAddress(&p, s);
    return (float*)p;
}

extern "C" void kernel_launch(void* const* d_in, const int* in_sizes, int n_in,
                              void* d_out, int out_size)
{
    const float* emb   = (const float*)d_in[0];
    const int*   spans = (const int*)  d_in[1];
    const float* Wu = (const float*)d_in[2];  const float* bu = (const float*)d_in[3];
    const float* Wv = (const float*)d_in[4];  const float* bv = (const float*)d_in[5];
    const float* Wl = (const float*)d_in[6];  const float* bl = (const float*)d_in[7];
    const float* Wq = (const float*)d_in[8];  const float* bq = (const float*)d_in[9];
    const float* Wk = (const float*)d_in[10]; const float* bk = (const float*)d_in[11];
    const float* Wvm= (const float*)d_in[12]; const float* bvm= (const float*)d_in[13];
    const float* Wo = (const float*)d_in[14]; const float* bo = (const float*)d_in[15];
    const float* F1 = (const float*)d_in[16]; const float* f1 = (const float*)d_in[17];
    const float* F2 = (const float*)d_in[18]; const float* f2 = (const float*)d_in[19];
    const float* g1 = (const float*)d_in[20]; const float* be1= (const float*)d_in[21];
    const float* g2 = (const float*)d_in[22]; const float* be2= (const float*)d_in[23];
    const float* ng = (const float*)d_in[24]; const float* nb = (const float*)d_in[25];
    const float* Wp = (const float*)d_in[26]; const float* bp = (const float*)d_in[27];

    float* htb = sym(g_htb);
    float* u   = sym(g_u);
    float* v   = sym(g_v);
    float* x   = sym(g_x);
    float* q   = sym(g_q);
    float* k   = sym(g_k);
    float* vv  = sym(g_vv);
    float* attn= sym(g_attn);
    float* tmp = sym(g_tmp);
    float* ffn = sym(g_ffn);
    float* ht  = sym(g_ht);
    float* out = (float*)d_out;

    const float scale = 0.102062072615966f;   // 1/sqrt(96)

    cudaFuncSetAttribute(flash_kernel, cudaFuncAttributeMaxDynamicSharedMemorySize,
                         FLASH_SMEM);

    const dim3 gridN768_T(8, 18);    // N=768 via BN=96, M=2304  -> 144 CTAs
    const dim3 gridN768_s(8, 1);     // N=768, M=48
    const dim3 gridFFN1(8, 18);      // N=1024 via BN=128        -> 144 CTAs
    const dim3 gridFFN2(8, 18);      // N=768 via BN=96, K=1024

    // 1) span max pooling -> htb [48,768]
    pool_kernel<<<NN_, 256>>>(emb, spans, htb);

    // 2) u = htb@Wu+bu ; v = htb@Wv+bv
    gemm_tc<3,true,false><<<gridN768_s, 256>>>(htb, Wu, bu, u, NN_, DIM, DIM, DIM, DIM, DIM);
    gemm_tc<3,true,false><<<gridN768_s, 256>>>(htb, Wv, bv, v, NN_, DIM, DIM, DIM, DIM, DIM);

    // 3) pair = relu(u_i + v_j) ; x = relu(pair @ Wl + bl)
    build_pair_kernel<<<TT, 256>>>(u, v, tmp);
    gemm_tc<3,true,true><<<gridN768_T, 256>>>(tmp, Wl, bl, x, TT, DIM, DIM, DIM, DIM, DIM);

    // 4) MatTransformer layers
    for (int l = 0; l < NLAYER; l++) {
        const float* Wq_l = Wq + (size_t)l * DIM * DIM;  const float* bq_l = bq + (size_t)l * DIM;
        const float* Wk_l = Wk + (size_t)l * DIM * DIM;  const float* bk_l = bk + (size_t)l * DIM;
        const float* Wv_l = Wvm+ (size_t)l * DIM * DIM;  const float* bv_l = bvm+ (size_t)l * DIM;
        const float* Wo_l = Wo + (size_t)l * DIM * DIM;  const float* bo_l = bo + (size_t)l * DIM;
        const float* F1_l = F1 + (size_t)l * DIM * DFF;  const float* f1_l = f1 + (size_t)l * DFF;
        const float* F2_l = F2 + (size_t)l * DFF * DIM;  const float* f2_l = f2 + (size_t)l * DIM;
        const float* g1_l = g1 + (size_t)l * DIM;        const float* be1_l= be1+ (size_t)l * DIM;
        const float* g2_l = g2 + (size_t)l * DIM;        const float* be2_l= be2+ (size_t)l * DIM;

        // QKV projections
        gemm_tc<3,true,false><<<gridN768_T, 256>>>(x, Wq_l, bq_l, q, TT, DIM, DIM, DIM, DIM, DIM);
        gemm_tc<3,true,false><<<gridN768_T, 256>>>(x, Wk_l, bk_l, k, TT, DIM, DIM, DIM, DIM, DIM);
        gemm_tc<3,true,false><<<gridN768_T, 256>>>(x, Wv_l, bv_l, vv, TT, DIM, DIM, DIM, DIM, DIM);

        // fused attention: softmax(QK^T * scale) @ V  -> attn
        flash_kernel<<<dim3(TT / 128, NHEAD), 256, FLASH_SMEM>>>(q, k, vv, attn, scale);

        // output projection + residual LN
        gemm_tc<3,true,false><<<gridN768_T, 256>>>(attn, Wo_l, bo_l, tmp, TT, DIM, DIM, DIM, DIM, DIM);
        add_ln_kernel<<<TT, 256>>>(x, tmp, g1_l, be1_l);

        // FFN + residual LN
        gemm_tc<4,true,true><<<gridFFN1, 256>>>(x, F1_l, f1_l, ffn, TT, DFF, DIM, DIM, DFF, DFF);
        gemm_tc<3,true,false><<<gridFFN2, 256>>>(ffn, F2_l, f2_l, tmp, TT, DIM, DFF, DFF, DIM, DIM);
        add_ln_kernel<<<TT, 256>>>(x, tmp, g2_l, be2_l);
    }

    // 5) final gather + LN + predictor + bag max
    final_kernel<<<BAG, 256>>>(x, ng, nb, Wp, bp, ht);
    writeout_kernel<<<1, 128>>>(ht, out, out_size);
}

// round 13
// speedup vs baseline: 2.0880x; 1.4604x over previous
#include <cuda_runtime.h>
#include <cuda_fp16.h>
#include <cstdint>

// ---------------- problem constants ----------------
#define BAG  8
#define SEQ  512
#define DIM  768
#define NPD  6
#define NN_  48          // N nodes
#define TT   2304        // T = N*N
#define NHEAD 8
#define DK   96
#define DFF  1024
#define NLAYER 4
#define NREL 97

typedef uint32_t u32;

// ---------------- device scratch (no allocations allowed) ----------------
__device__ float  g_htb [NN_ * DIM];
__device__ float  g_u   [NN_ * DIM];
__device__ float  g_v   [NN_ * DIM];
__device__ float  g_x   [TT * DIM];
__device__ float  g_tmp [TT * DIM];
__device__ float  g_ht  [BAG * NREL];
__device__ __half g_xh  [TT * DIM];
__device__ __half g_qh  [TT * DIM];
__device__ __half g_kh  [TT * DIM];
__device__ __half g_vh  [TT * DIM];
__device__ __half g_ah  [TT * DIM];
__device__ __half g_fh  [TT * DFF];

// ---------------- fp16 / ldmatrix helpers ----------------
__device__ __forceinline__ u32 pack_h2(float a, float b) {
    __half2 h = __floats2half2_rn(a, b);
    return *(u32*)&h;
}
__device__ __forceinline__ void mma_f16(float& c0, float& c1, float& c2, float& c3,
                                        u32 a0, u32 a1, u32 a2, u32 a3,
                                        u32 b0, u32 b1) {
    asm("mma.sync.aligned.m16n8k16.row.col.f32.f16.f16.f32 "
        "{%0,%1,%2,%3}, {%4,%5,%6,%7}, {%8,%9}, {%0,%1,%2,%3};"
        : "+f"(c0), "+f"(c1), "+f"(c2), "+f"(c3)
        : "r"(a0), "r"(a1), "r"(a2), "r"(a3), "r"(b0), "r"(b1));
}
__device__ __forceinline__ u32 s2u(const void* p) {
    return (u32)__cvta_generic_to_shared(p);
}
__device__ __forceinline__ void ldsm_x4(u32& r0, u32& r1, u32& r2, u32& r3, u32 addr) {
    asm volatile("ldmatrix.sync.aligned.m8n8.x4.shared.b16 {%0,%1,%2,%3}, [%4];"
                 : "=r"(r0), "=r"(r1), "=r"(r2), "=r"(r3) : "r"(addr));
}
__device__ __forceinline__ void ldsm_x4t(u32& r0, u32& r1, u32& r2, u32& r3, u32 addr) {
    asm volatile("ldmatrix.sync.aligned.m8n8.x4.trans.shared.b16 {%0,%1,%2,%3}, [%4];"
                 : "=r"(r0), "=r"(r1), "=r"(r2), "=r"(r3) : "r"(addr));
}
__device__ __forceinline__ void ldsm_x2t(u32& r0, u32& r1, u32 addr) {
    asm volatile("ldmatrix.sync.aligned.m8n8.x2.trans.shared.b16 {%0,%1}, [%2];"
                 : "=r"(r0), "=r"(r1) : "r"(addr));
}

// ---------------- block reduction helper ----------------
__device__ __forceinline__ float blk_reduce(float val, float* sh, bool do_max) {
    const unsigned mask = 0xffffffffu;
#pragma unroll
    for (int o = 16; o > 0; o >>= 1) {
        float other = __shfl_xor_sync(mask, val, o);
        val = do_max ? fmaxf(val, other) : (val + other);
    }
    int lane = threadIdx.x & 31, w = threadIdx.x >> 5;
    __syncthreads();
    if (lane == 0) sh[w] = val;
    __syncthreads();
    int nw = (blockDim.x + 31) >> 5;
    if (w == 0) {
        val = (lane < nw) ? sh[lane] : (do_max ? -3.4e38f : 0.f);
#pragma unroll
        for (int o = 16; o > 0; o >>= 1) {
            float other = __shfl_xor_sync(mask, val, o);
            val = do_max ? fmaxf(val, other) : (val + other);
        }
        if (lane == 0) sh[0] = val;
    }
    __syncthreads();
    return sh[0];
}

// ============ 128xBN fp16 GEMM, BK=32, half A, fp32 B (weights) ============
// C = A @ B (+bias)(ReLU).  A: half [M][lda] (or PAIR: relu(u_i+v_j) on the fly)
// M multiple of 128 (no row guards), N % BN == 0, K % 32 == 0.
template<int NT, bool PAIR, bool RELU, bool OUTF, bool OUTH>
__global__ __launch_bounds__(256)
void gemm_h(const __half* __restrict__ A, const float* __restrict__ U,
            const float* __restrict__ Vv, const float* __restrict__ B,
            const float* __restrict__ bias, float* __restrict__ Cf,
            __half* __restrict__ Ch, int K, int lda, int ldb, int ldc)
{
    constexpr int BN = 32 * NT;
    constexpr int BK = 32;
    constexpr int AP = 40;          // 80B row (5x16B, odd) -> conflict-free ldsm
    constexpr int BP = BN + 8;      // 104/136 halfs -> 13/17 x16B, odd
    constexpr int NBT = (BK * BN) / 1024;   // float4 B tasks per thread (3 or 4)

    __shared__ __half As[2][128][AP];
    __shared__ __half Bs[2][BK][BP];

    const int tid  = threadIdx.x;
    const int lane = tid & 31;
    const int warp = tid >> 5;
    const int wR   = (warp & 1) * 64;
    const int wC   = (warp >> 1) * (8 * NT);
    const int row0 = blockIdx.y * 128;
    const int col0 = blockIdx.x * BN;
    const int lr   = lane >> 2;
    const int lc   = lane & 3;
    const int ph   = lane >> 3;
    const int rr   = lane & 7;

    const int arow = rr + (ph & 1) * 8;
    const int acol = (ph >> 1) * 8;
    const int tkrow = rr + (ph & 1) * 8;
    const int tncol = (ph >> 1) * 8;

    // A stage map: 512 uint4 tasks (2/thread)
    const int sr0 = tid >> 2;                 // row for task0 (task1: +64)
    const int sc8 = (tid & 3) * 8;

    uint4 ra[2];
    float4 fu[2][2], fv[2][2];
    float4 fb[NBT];

    float acc[4][NT][4];
#pragma unroll
    for (int i = 0; i < 4; i++)
#pragma unroll
        for (int j = 0; j < NT; j++)
#pragma unroll
            for (int c = 0; c < 4; c++) acc[i][j][c] = 0.f;

    const int KT = K / BK;

    auto fetch = [&](int kb) {
#pragma unroll
        for (int i = 0; i < 2; i++) {
            int r = sr0 + i * 64;
            if (PAIR) {
                int m = row0 + r;
                int ii = m / NN_, jj = m % NN_;
                const float* up = U + (long)ii * DIM + kb + sc8;
                const float* vp = Vv + (long)jj * DIM + kb + sc8;
                fu[i][0] = *(const float4*)up;     fu[i][1] = *(const float4*)(up + 4);
                fv[i][0] = *(const float4*)vp;     fv[i][1] = *(const float4*)(vp + 4);
            } else {
                ra[i] = *(const uint4*)(A + (long)(row0 + r) * lda + kb + sc8);
            }
        }
#pragma unroll
        for (int i = 0; i < NBT; i++) {
            int id = tid + i * 256;
            int krow, nc4;
            if (NT == 4) { krow = id >> 5; nc4 = (id & 31) * 4; }
            else         { krow = id / 24; nc4 = (id % 24) * 4; }
            fb[i] = *(const float4*)(B + (long)(krow) * ldb + col0 + nc4 + (long)kb * ldb);
        }
    };
    auto stage = [&](int buf) {
#pragma unroll
        for (int i = 0; i < 2; i++) {
            int r = sr0 + i * 64;
            if (PAIR) {
                uint4 q;
                q.x = pack_h2(fmaxf(fu[i][0].x + fv[i][0].x, 0.f), fmaxf(fu[i][0].y + fv[i][0].y, 0.f));
                q.y = pack_h2(fmaxf(fu[i][0].z + fv[i][0].z, 0.f), fmaxf(fu[i][0].w + fv[i][0].w, 0.f));
                q.z = pack_h2(fmaxf(fu[i][1].x + fv[i][1].x, 0.f), fmaxf(fu[i][1].y + fv[i][1].y, 0.f));
                q.w = pack_h2(fmaxf(fu[i][1].z + fv[i][1].z, 0.f), fmaxf(fu[i][1].w + fv[i][1].w, 0.f));
                *(uint4*)&As[buf][r][sc8] = q;
            } else {
                *(uint4*)&As[buf][r][sc8] = ra[i];
            }
        }
#pragma unroll
        for (int i = 0; i < NBT; i++) {
            int id = tid + i * 256;
            int krow, nc4;
            if (NT == 4) { krow = id >> 5; nc4 = (id & 31) * 4; }
            else         { krow = id / 24; nc4 = (id % 24) * 4; }
            uint2 q;
            q.x = pack_h2(fb[i].x, fb[i].y); q.y = pack_h2(fb[i].z, fb[i].w);
            *(uint2*)&Bs[buf][krow][nc4] = q;
        }
    };

    fetch(0);
    stage(0);
    __syncthreads();

    for (int kt = 0; kt < KT; kt++) {
        const int cur = kt & 1;
        const bool hn = (kt + 1 < KT);
        if (hn) fetch((kt + 1) * BK);

#pragma unroll
        for (int ks = 0; ks < 2; ks++) {
            const int k0 = ks * 16;
            u32 af[4][4], bf[NT][2];
#pragma unroll
            for (int mt = 0; mt < 4; mt++)
                ldsm_x4(af[mt][0], af[mt][1], af[mt][2], af[mt][3],
                        s2u(&As[cur][wR + mt * 16 + arow][k0 + acol]));
#pragma unroll
            for (int p = 0; p < NT / 2; p++)
                ldsm_x4t(bf[2 * p][0], bf[2 * p][1], bf[2 * p + 1][0], bf[2 * p + 1][1],
                         s2u(&Bs[cur][k0 + tkrow][wC + p * 16 + tncol]));
            if (NT & 1)
                ldsm_x2t(bf[NT - 1][0], bf[NT - 1][1],
                         s2u(&Bs[cur][k0 + tkrow][wC + (NT - 1) * 8]));
#pragma unroll
            for (int mt = 0; mt < 4; mt++)
#pragma unroll
                for (int nt = 0; nt < NT; nt++)
                    mma_f16(acc[mt][nt][0], acc[mt][nt][1], acc[mt][nt][2], acc[mt][nt][3],
                            af[mt][0], af[mt][1], af[mt][2], af[mt][3],
                            bf[nt][0], bf[nt][1]);
        }

        if (hn) stage(cur ^ 1);
        __syncthreads();
    }

    // ---- epilogue ----
#pragma unroll
    for (int nt = 0; nt < NT; nt++) {
        int gn = col0 + wC + nt * 8 + 2 * lc;
        float b0 = bias[gn], b1 = bias[gn + 1];
#pragma unroll
        for (int mt = 0; mt < 4; mt++) {
            int gm0 = row0 + wR + mt * 16 + lr;
#pragma unroll
            for (int h = 0; h < 2; h++) {
                int gm = gm0 + h * 8;
                float v0 = acc[mt][nt][2 * h]     + b0;
                float v1 = acc[mt][nt][2 * h + 1] + b1;
                if (RELU) { v0 = fmaxf(v0, 0.f); v1 = fmaxf(v1, 0.f); }
                if (OUTF) *(float2*)(Cf + (long)gm * ldc + gn) = make_float2(v0, v1);
                if (OUTH) *(u32*)(Ch + (long)gm * ldc + gn) = pack_h2(v0, v1);
            }
        }
    }
}

// ---------------- legacy fp32-input GEMM (small M: u/v, merged pair) ----------------
__global__ __launch_bounds__(256)
void gemm_uv(const float* __restrict__ Aht, const float* __restrict__ B1,
             const float* __restrict__ bias1, float* __restrict__ C1,
             const float* __restrict__ B2, const float* __restrict__ bias2,
             float* __restrict__ C2)
{
    constexpr int NT = 3, BN = 96, BK = 16, AP = 24, BP = BN + 8;
    const float* B   = blockIdx.z ? B2 : B1;
    const float* bia = blockIdx.z ? bias2 : bias1;
    float*       C   = blockIdx.z ? C2 : C1;
    const int M = NN_, Kt = DIM;

    __shared__ __half As[2][128][AP];
    __shared__ __half Bs[2][BK][BP];

    const int tid  = threadIdx.x;
    const int lane = tid & 31;
    const int warp = tid >> 5;
    const int wR   = (warp & 1) * 64;
    const int wC   = (warp >> 1) * 24;
    const int col0 = blockIdx.x * BN;
    const int lr   = lane >> 2;
    const int lc   = lane & 3;
    const int ph   = lane >> 3;
    const int rr   = lane & 7;

    const int arow = rr + (ph & 1) * 8;
    const int acol = (ph >> 1) * 8;
    const int tkrow = rr + (ph & 1) * 8;
    const int tncol = (ph >> 1) * 8;

    const int ar = tid >> 1;
    const int ac = (tid & 1) * 8;
    int kb0 = tid / 24, nb0 = (tid % 24) * 4;
    bool b1v = (tid < 128);
    int id1 = tid + 256;
    int kb1 = id1 / 24, nb1 = (id1 % 24) * 4;

    const float4 f4z = make_float4(0.f, 0.f, 0.f, 0.f);
    float4 fa0, fa1, fb0, fb1;

    float acc[4][NT][4];
#pragma unroll
    for (int i = 0; i < 4; i++)
#pragma unroll
        for (int j = 0; j < NT; j++)
#pragma unroll
            for (int c = 0; c < 4; c++) acc[i][j][c] = 0.f;

    auto fetch = [&](int k0g) {
        const float* ap = Aht + (long)ar * DIM + k0g + ac;
        fa0 = (ar < M) ? *(const float4*)ap : f4z;
        fa1 = (ar < M) ? *(const float4*)(ap + 4) : f4z;
        fb0 = *(const float4*)(B + (long)(k0g + kb0) * DIM + col0 + nb0);
        if (b1v) fb1 = *(const float4*)(B + (long)(k0g + kb1) * DIM + col0 + nb1);
    };
    auto stage = [&](int buf) {
        uint4 qa;
        qa.x = pack_h2(fa0.x, fa0.y); qa.y = pack_h2(fa0.z, fa0.w);
        qa.z = pack_h2(fa1.x, fa1.y); qa.w = pack_h2(fa1.z, fa1.w);
        *(uint4*)&As[buf][ar][ac] = qa;
        uint2 qb0;
        qb0.x = pack_h2(fb0.x, fb0.y); qb0.y = pack_h2(fb0.z, fb0.w);
        *(uint2*)&Bs[buf][kb0][nb0] = qb0;
        if (b1v) {
            uint2 qb1;
            qb1.x = pack_h2(fb1.x, fb1.y); qb1.y = pack_h2(fb1.z, fb1.w);
            *(uint2*)&Bs[buf][kb1][nb1] = qb1;
        }
    };

    fetch(0);
    stage(0);
    __syncthreads();

    const int KT = Kt / BK;
    for (int kt = 0; kt < KT; kt++) {
        const int cur = kt & 1;
        const bool hn = (kt + 1 < KT);
        if (hn) fetch((kt + 1) * BK);

        u32 af[4][4], bf[NT][2];
#pragma unroll
        for (int mt = 0; mt < 4; mt++)
            ldsm_x4(af[mt][0], af[mt][1], af[mt][2], af[mt][3],
                    s2u(&As[cur][wR + mt * 16 + arow][acol]));
#pragma unroll
        for (int p = 0; p < 1; p++)
            ldsm_x4t(bf[0][0], bf[0][1], bf[1][0], bf[1][1],
                     s2u(&Bs[cur][tkrow][wC + tncol]));
        ldsm_x2t(bf[2][0], bf[2][1], s2u(&Bs[cur][tkrow][wC + 16]));
#pragma unroll
        for (int mt = 0; mt < 4; mt++)
#pragma unroll
            for (int nt = 0; nt < NT; nt++)
                mma_f16(acc[mt][nt][0], acc[mt][nt][1], acc[mt][nt][2], acc[mt][nt][3],
                        af[mt][0], af[mt][1], af[mt][2], af[mt][3],
                        bf[nt][0], bf[nt][1]);

        if (hn) stage(cur ^ 1);
        __syncthreads();
    }

#pragma unroll
    for (int nt = 0; nt < NT; nt++) {
        int gn = col0 + wC + nt * 8 + 2 * lc;
        float b0 = bia[gn], b1 = bia[gn + 1];
#pragma unroll
        for (int mt = 0; mt < 4; mt++) {
            int gm0 = wR + mt * 16 + lr;
#pragma unroll
            for (int h = 0; h < 2; h++) {
                int gm = gm0 + h * 8;
                if (gm >= M) continue;
                *(float2*)(C + (long)gm * DIM + gn) =
                    make_float2(acc[mt][nt][2 * h] + b0, acc[mt][nt][2 * h + 1] + b1);
            }
        }
    }
}

// ---------------- flash attention (fp16 in/out, online softmax) ----------------
#define FQ_P 104
#define FK_P 104
#define FV_P 104
#define FP_P 72
#define FQ_OFF 0
#define FK_OFF 13312
#define FV_OFF 26624
#define FP_OFF 39936
#define FLASH_SMEM ((39936 + 128 * 72) * 2)

__global__ __launch_bounds__(256)
void flash_kernel(const __half* __restrict__ Q, const __half* __restrict__ K,
                  const __half* __restrict__ V, __half* __restrict__ O, float scale)
{
    extern __shared__ __half smh[];
    __half* Qs = smh + FQ_OFF;
    __half* Ks = smh + FK_OFF;
    __half* Vs = smh + FV_OFF;
    __half* Ps = smh + FP_OFF;

    const int tid  = threadIdx.x;
    const int lane = tid & 31;
    const int warp = tid >> 5;
    const int lr   = lane >> 2;
    const int lc   = lane & 3;
    const int ph   = lane >> 3;
    const int rr   = lane & 7;
    const int wm   = warp * 16;
    const int mt0  = blockIdx.x * 128;
    const int head = blockIdx.y;

    const int arow = rr + (ph & 1) * 8;
    const int acol = (ph >> 1) * 8;
    const int brow = rr + (ph >> 1) * 8;
    const int bcol = (ph & 1) * 8;
    const int tkrow = rr + (ph & 1) * 8;
    const int tncol = (ph >> 1) * 8;

    const __half* Qb = Q + (long)mt0 * DIM + head * DK;
    const __half* Kb = K + head * DK;
    const __half* Vb = V + head * DK;

    // ---- load Q tile (128 x 96) ----
#pragma unroll
    for (int it = 0; it < 6; it++) {
        int id  = tid + it * 256;
        int row = id / 12;
        int c8  = (id % 12) * 8;
        *(uint4*)&Qs[row * FQ_P + c8] = *(const uint4*)(Qb + (long)row * DIM + c8);
    }

    uint4 rk[3], rv[3];
    auto fetch = [&](int t) {
        int kv0 = t * 64;
#pragma unroll
        for (int it = 0; it < 3; it++) {
            int id  = tid + it * 256;
            int row = id / 12;
            int c8  = (id % 12) * 8;
            rk[it] = *(const uint4*)(Kb + (long)(kv0 + row) * DIM + c8);
            rv[it] = *(const uint4*)(Vb + (long)(kv0 + row) * DIM + c8);
        }
    };
    auto stage = [&](int buf) {
#pragma unroll
        for (int it = 0; it < 3; it++) {
            int id  = tid + it * 256;
            int row = id / 12;
            int c8  = (id % 12) * 8;
            *(uint4*)&Ks[(buf * 64 + row) * FK_P + c8] = rk[it];
            *(uint4*)&Vs[(buf * 64 + row) * FV_P + c8] = rv[it];
        }
    };

    float oacc[12][4];
#pragma unroll
    for (int i = 0; i < 12; i++)
#pragma unroll
        for (int c = 0; c < 4; c++) oacc[i][c] = 0.f;
    float mrow0 = -1e30f, mrow1 = -1e30f, lrow0 = 0.f, lrow1 = 0.f;

    fetch(0);
    stage(0);
    __syncthreads();

    const int NIT = TT / 64;
    for (int t = 0; t < NIT; t++) {
        const int cur = t & 1;
        const bool hn = (t + 1 < NIT);
        if (hn) fetch(t + 1);

        float sacc[8][4];
#pragma unroll
        for (int nt = 0; nt < 8; nt++)
#pragma unroll
            for (int c = 0; c < 4; c++) sacc[nt][c] = 0.f;

#pragma unroll
        for (int ks = 0; ks < 6; ks++) {
            const int k0 = ks * 16;
            u32 a0, a1, a2, a3;
            ldsm_x4(a0, a1, a2, a3, s2u(&Qs[(wm + arow) * FQ_P + k0 + acol]));
            u32 bf[8][2];
#pragma unroll
            for (int p = 0; p < 4; p++)
                ldsm_x4(bf[2 * p][0], bf[2 * p][1], bf[2 * p + 1][0], bf[2 * p + 1][1],
                        s2u(&Ks[(cur * 64 + p * 16 + brow) * FK_P + k0 + bcol]));
#pragma unroll
            for (int nt = 0; nt < 8; nt++)
                mma_f16(sacc[nt][0], sacc[nt][1], sacc[nt][2], sacc[nt][3],
                        a0, a1, a2, a3, bf[nt][0], bf[nt][1]);
        }

        float rm0 = -1e30f, rm1 = -1e30f;
#pragma unroll
        for (int nt = 0; nt < 8; nt++) {
            rm0 = fmaxf(rm0, fmaxf(sacc[nt][0], sacc[nt][1]));
            rm1 = fmaxf(rm1, fmaxf(sacc[nt][2], sacc[nt][3]));
        }
        rm0 *= scale; rm1 *= scale;
#pragma unroll
        for (int o = 1; o <= 2; o <<= 1) {
            rm0 = fmaxf(rm0, __shfl_xor_sync(0xffffffffu, rm0, o));
            rm1 = fmaxf(rm1, __shfl_xor_sync(0xffffffffu, rm1, o));
        }
        float mn0 = fmaxf(mrow0, rm0);
        float mn1 = fmaxf(mrow1, rm1);
        float al0 = __expf(mrow0 - mn0);
        float al1 = __expf(mrow1 - mn1);
        float sum0 = 0.f, sum1 = 0.f;
#pragma unroll
        for (int nt = 0; nt < 8; nt++) {
            float p0 = __expf(sacc[nt][0] * scale - mn0);
            float p1 = __expf(sacc[nt][1] * scale - mn0);
            float p2 = __expf(sacc[nt][2] * scale - mn1);
            float p3 = __expf(sacc[nt][3] * scale - mn1);
            sum0 += p0 + p1; sum1 += p2 + p3;
            *(u32*)&Ps[(wm + lr) * FP_P + nt * 8 + 2 * lc]     = pack_h2(p0, p1);
            *(u32*)&Ps[(wm + lr + 8) * FP_P + nt * 8 + 2 * lc] = pack_h2(p2, p3);
        }
#pragma unroll
        for (int o = 1; o <= 2; o <<= 1) {
            sum0 += __shfl_xor_sync(0xffffffffu, sum0, o);
            sum1 += __shfl_xor_sync(0xffffffffu, sum1, o);
        }
        lrow0 = lrow0 * al0 + sum0;
        lrow1 = lrow1 * al1 + sum1;
        mrow0 = mn0; mrow1 = mn1;
#pragma unroll
        for (int nt = 0; nt < 12; nt++) {
            oacc[nt][0] *= al0; oacc[nt][1] *= al0;
            oacc[nt][2] *= al1; oacc[nt][3] *= al1;
        }

        if (hn) stage(cur ^ 1);
        __syncwarp();

#pragma unroll
        for (int ksv = 0; ksv < 4; ksv++) {
            const int k0 = ksv * 16;
            u32 a0, a1, a2, a3;
            ldsm_x4(a0, a1, a2, a3, s2u(&Ps[(wm + arow) * FP_P + k0 + acol]));
            u32 bf[12][2];
#pragma unroll
            for (int p = 0; p < 6; p++)
                ldsm_x4t(bf[2 * p][0], bf[2 * p][1], bf[2 * p + 1][0], bf[2 * p + 1][1],
                         s2u(&Vs[(cur * 64 + k0 + tkrow) * FV_P + p * 16 + tncol]));
#pragma unroll
            for (int nt = 0; nt < 12; nt++)
                mma_f16(oacc[nt][0], oacc[nt][1], oacc[nt][2], oacc[nt][3],
                        a0, a1, a2, a3, bf[nt][0], bf[nt][1]);
        }
        __syncthreads();
    }

    float inv0 = 1.f / lrow0;
    float inv1 = 1.f / lrow1;
    int r0 = mt0 + wm + lr;
    int r1 = r0 + 8;
#pragma unroll
    for (int nt = 0; nt < 12; nt++) {
        int col = head * DK + nt * 8 + 2 * lc;
        *(u32*)(O + (long)r0 * DIM + col) = pack_h2(oacc[nt][0] * inv0, oacc[nt][1] * inv0);
        *(u32*)(O + (long)r1 * DIM + col) = pack_h2(oacc[nt][2] * inv1, oacc[nt][3] * inv1);
    }
}

// ---------------- span max pooling ----------------
__global__ void pool_kernel(const float* __restrict__ emb, const int* __restrict__ spans,
                            float* __restrict__ htb)
{
    int node = blockIdx.x;
    int bag  = node / NPD;
    int s0 = spans[node * 2 + 0];
    int s1 = spans[node * 2 + 1];
    const float* base = emb + (long)bag * SEQ * DIM;
    for (int d = threadIdx.x; d < DIM; d += blockDim.x) {
        float m = -3.4e38f;
        for (int p = s0; p <= s1; p++)
            m = fmaxf(m, base[(long)p * DIM + d]);
        htb[(long)node * DIM + d] = m;
    }
}

// ---------------- x = LN(x + o) * g + b  -> fp32 x and fp16 xh ----------------
__global__ void add_ln_kernel(float* __restrict__ x, __half* __restrict__ xh,
                              const float* __restrict__ o,
                              const float* __restrict__ g, const float* __restrict__ b)
{
    long base = (long)blockIdx.x * DIM;
    float* xr = x + base;
    __half* xhr = xh + base;
    const float* orr = o + base;
    __shared__ float sh[32];
    float v[3];
    float s = 0.f, s2 = 0.f;
#pragma unroll
    for (int i = 0; i < 3; i++) {
        int d = threadIdx.x + i * 256;
        float t = xr[d] + orr[d];
        v[i] = t; s += t; s2 += t * t;
    }
    s  = blk_reduce(s,  sh, false);
    s2 = blk_reduce(s2, sh, false);
    float mean = s * (1.f / DIM);
    float var  = s2 * (1.f / DIM) - mean * mean;
    float inv  = rsqrtf(var + 1e-5f);
#pragma unroll
    for (int i = 0; i < 3; i++) {
        int d = threadIdx.x + i * 256;
        float r = (v[i] - mean) * inv * g[d] + b[d];
        xr[d] = r;
        xhr[d] = __float2half_rn(r);
    }
}

// ---------------- final: gather (h,t) cells, LN, predictor ----------------
__global__ void final_kernel(const float* __restrict__ x, const float* __restrict__ ng,
                             const float* __restrict__ nb, const float* __restrict__ Wp,
                             const float* __restrict__ bp, float* __restrict__ ht)
{
    int bag = blockIdx.x;
    long r = (long)(bag * NPD) * NN_ + (bag * NPD + 1);
    const float* row = x + r * DIM;
    __shared__ float sh[DIM];
    __shared__ float red[32];
    float s = 0.f, s2 = 0.f;
    for (int d = threadIdx.x; d < DIM; d += blockDim.x) {
        float t = row[d];
        sh[d] = t; s += t; s2 += t * t;
    }
    s  = blk_reduce(s,  red, false);
    s2 = blk_reduce(s2, red, false);
    float mean = s * (1.f / DIM);
    float inv  = rsqrtf(s2 * (1.f / DIM) - mean * mean + 1e-5f);
    __syncthreads();
    for (int d = threadIdx.x; d < DIM; d += blockDim.x)
        sh[d] = (sh[d] - mean) * inv * ng[d] + nb[d];
    __syncthreads();
    for (int n = threadIdx.x; n < NREL; n += blockDim.x) {
        float acc = bp[n];
        for (int k = 0; k < DIM; k++)
            acc = fmaf(sh[k], Wp[(long)k * NREL + n], acc);
        ht[bag * NREL + n] = acc;
    }
}

// ---------------- output assembly: bag max + layout ----------------
__global__ void writeout_kernel(const float* __restrict__ ht, float* __restrict__ out,
                                int out_size)
{
    int n = threadIdx.x;
    if (n >= NREL) return;
    float m = -3.4e38f;
    for (int b = 0; b < BAG; b++) m = fmaxf(m, ht[b * NREL + n]);
    if (out_size >= NREL * (BAG + 1)) {
        out[n] = m;
        for (int b = 0; b < BAG; b++) out[NREL + b * NREL + n] = ht[b * NREL + n];
    } else if (out_size == NREL) {
        out[n] = m;
    } else {
        for (int b = 0; b < BAG; b++) out[b * NREL + n] = ht[b * NREL + n];
    }
}

// ---------------- host ----------------
template <typename T>
static inline void* symv(T& s) {
    void* p = nullptr;
    cudaGetSymbolAddress(&p, s);
    return p;
}

extern "C" void kernel_launch(void* const* d_in, const int* in_sizes, int n_in,
                              void* d_out, int out_size)
{
    const float* emb   = (const float*)d_in[0];
    const int*   spans = (const int*)  d_in[1];
    const float* Wu = (const float*)d_in[2];  const float* bu = (const float*)d_in[3];
    const float* Wv = (const float*)d_in[4];  const float* bv = (const float*)d_in[5];
    const float* Wl = (const float*)d_in[6];  const float* bl = (const float*)d_in[7];
    const float* Wq = (const float*)d_in[8];  const float* bq = (const float*)d_in[9];
    const float* Wk = (const float*)d_in[10]; const float* bk = (const float*)d_in[11];
    const float* Wvm= (const float*)d_in[12]; const float* bvm= (const float*)d_in[13];
    const float* Wo = (const float*)d_in[14]; const float* bo = (const float*)d_in[15];
    const float* F1 = (const float*)d_in[16]; const float* f1 = (const float*)d_in[17];
    const float* F2 = (const float*)d_in[18]; const float* f2 = (const float*)d_in[19];
    const float* g1 = (const float*)d_in[20]; const float* be1= (const float*)d_in[21];
    const float* g2 = (const float*)d_in[22]; const float* be2= (const float*)d_in[23];
    const float* ng = (const float*)d_in[24]; const float* nb = (const float*)d_in[25];
    const float* Wp = (const float*)d_in[26]; const float* bp = (const float*)d_in[27];

    float*  htb = (float*) symv(g_htb);
    float*  u   = (float*) symv(g_u);
    float*  v   = (float*) symv(g_v);
    float*  x   = (float*) symv(g_x);
    float*  tmp = (float*) symv(g_tmp);
    float*  ht  = (float*) symv(g_ht);
    __half* xh  = (__half*)symv(g_xh);
    __half* qh  = (__half*)symv(g_qh);
    __half* kh  = (__half*)symv(g_kh);
    __half* vh  = (__half*)symv(g_vh);
    __half* ah  = (__half*)symv(g_ah);
    __half* fh  = (__half*)symv(g_fh);
    float*  out = (float*)d_out;

    const float scale = 0.102062072615966f;   // 1/sqrt(96)

    cudaFuncSetAttribute(flash_kernel, cudaFuncAttributeMaxDynamicSharedMemorySize,
                         FLASH_SMEM);

    const dim3 g768(8, 18);    // N=768 via BN=96, M=2304
    const dim3 gFFN1(8, 18);   // N=1024 via BN=128

    // 1) span max pooling -> htb [48,768]
    pool_kernel<<<NN_, 256>>>(emb, spans, htb);

    // 2) u/v projections (merged, M=48)
    gemm_uv<<<dim3(8, 1, 2), 256>>>(htb, Wu, bu, u, Wv, bv, v);

    // 3) x = relu(relu(u_i + v_j) @ Wl + bl)   (pair fused into A-stage)
    gemm_h<3, true, true, true, true><<<g768, 256>>>(
        nullptr, u, v, Wl, bl, x, xh, DIM, DIM, DIM, DIM);

    // 4) MatTransformer layers
    for (int l = 0; l < NLAYER; l++) {
        const float* Wq_l = Wq + (size_t)l * DIM * DIM;  const float* bq_l = bq + (size_t)l * DIM;
        const float* Wk_l = Wk + (size_t)l * DIM * DIM;  const float* bk_l = bk + (size_t)l * DIM;
        const float* Wv_l = Wvm+ (size_t)l * DIM * DIM;  const float* bv_l = bvm+ (size_t)l * DIM;
        const float* Wo_l = Wo + (size_t)l * DIM * DIM;  const float* bo_l = bo + (size_t)l * DIM;
        const float* F1_l = F1 + (size_t)l * DIM * DFF;  const float* f1_l = f1 + (size_t)l * DFF;
        const float* F2_l = F2 + (size_t)l * DFF * DIM;  const float* f2_l = f2 + (size_t)l * DIM;
        const float* g1_l = g1 + (size_t)l * DIM;        const float* be1_l= be1+ (size_t)l * DIM;
        const float* g2_l = g2 + (size_t)l * DIM;        const float* be2_l= be2+ (size_t)l * DIM;

        // QKV projections (half in, half out)
        gemm_h<3, false, false, false, true><<<g768, 256>>>(
            xh, nullptr, nullptr, Wq_l, bq_l, nullptr, qh, DIM, DIM, DIM, DIM);
        gemm_h<3, false, false, false, true><<<g768, 256>>>(
            xh, nullptr, nullptr, Wk_l, bk_l, nullptr, kh, DIM, DIM, DIM, DIM);
        gemm_h<3, false, false, false, true><<<g768, 256>>>(
            xh, nullptr, nullptr, Wv_l, bv_l, nullptr, vh, DIM, DIM, DIM, DIM);

        // fused attention (half in, half out)
        flash_kernel<<<dim3(TT / 128, NHEAD), 256, FLASH_SMEM>>>(qh, kh, vh, ah, scale);

        // output projection + residual LN
        gemm_h<3, false, false, true, false><<<g768, 256>>>(
            ah, nullptr, nullptr, Wo_l, bo_l, tmp, nullptr, DIM, DIM, DIM, DIM);
        add_ln_kernel<<<TT, 256>>>(x, xh, tmp, g1_l, be1_l);

        // FFN + residual LN
        gemm_h<4, false, true, false, true><<<gFFN1, 256>>>(
            xh, nullptr, nullptr, F1_l, f1_l, nullptr, fh, DIM, DIM, DFF, DFF);
        gemm_h<3, false, false, true, false><<<g768, 256>>>(
            fh, nullptr, nullptr, F2_l, f2_l, tmp, nullptr, DFF, DFF, DIM, DIM);
        add_ln_kernel<<<TT, 256>>>(x, xh, tmp, g2_l, be2_l);
    }

    // 5) final gather + LN + predictor + bag max
    final_kernel<<<BAG, 256>>>(x, ng, nb, Wp, bp, ht);
    writeout_kernel<<<1, 128>>>(ht, out, out_size);
}

// round 14
// speedup vs baseline: 2.2417x; 1.0736x over previous
#include <cuda_runtime.h>
#include <cuda_fp16.h>
#include <cstdint>

// ---------------- problem constants ----------------
#define BAG  8
#define SEQ  512
#define DIM  768
#define NPD  6
#define NN_  48          // N nodes
#define TT   2304        // T = N*N
#define NHEAD 8
#define DK   96
#define DFF  1024
#define NLAYER 4
#define NREL 97

typedef uint32_t u32;

// ---------------- device scratch (no allocations allowed) ----------------
__device__ float  g_htb [NN_ * DIM];
__device__ float  g_u   [NN_ * DIM];
__device__ float  g_v   [NN_ * DIM];
__device__ float  g_x   [TT * DIM];
__device__ float  g_tmp [TT * DIM];
__device__ float  g_ht  [BAG * NREL];
__device__ __half g_xh  [TT * DIM];
__device__ __half g_qh  [TT * DIM];
__device__ __half g_kh  [TT * DIM];
__device__ __half g_vh  [TT * DIM];
__device__ __half g_ah  [TT * DIM];
__device__ __half g_fh  [TT * DFF];

// ---------------- fp16 / ldmatrix helpers ----------------
__device__ __forceinline__ u32 pack_h2(float a, float b) {
    __half2 h = __floats2half2_rn(a, b);
    return *(u32*)&h;
}
__device__ __forceinline__ void mma_f16(float& c0, float& c1, float& c2, float& c3,
                                        u32 a0, u32 a1, u32 a2, u32 a3,
                                        u32 b0, u32 b1) {
    asm("mma.sync.aligned.m16n8k16.row.col.f32.f16.f16.f32 "
        "{%0,%1,%2,%3}, {%4,%5,%6,%7}, {%8,%9}, {%0,%1,%2,%3};"
        : "+f"(c0), "+f"(c1), "+f"(c2), "+f"(c3)
        : "r"(a0), "r"(a1), "r"(a2), "r"(a3), "r"(b0), "r"(b1));
}
__device__ __forceinline__ u32 s2u(const void* p) {
    return (u32)__cvta_generic_to_shared(p);
}
__device__ __forceinline__ void ldsm_x4(u32& r0, u32& r1, u32& r2, u32& r3, u32 addr) {
    asm volatile("ldmatrix.sync.aligned.m8n8.x4.shared.b16 {%0,%1,%2,%3}, [%4];"
                 : "=r"(r0), "=r"(r1), "=r"(r2), "=r"(r3) : "r"(addr));
}
__device__ __forceinline__ void ldsm_x4t(u32& r0, u32& r1, u32& r2, u32& r3, u32 addr) {
    asm volatile("ldmatrix.sync.aligned.m8n8.x4.trans.shared.b16 {%0,%1,%2,%3}, [%4];"
                 : "=r"(r0), "=r"(r1), "=r"(r2), "=r"(r3) : "r"(addr));
}
__device__ __forceinline__ void ldsm_x2t(u32& r0, u32& r1, u32 addr) {
    asm volatile("ldmatrix.sync.aligned.m8n8.x2.trans.shared.b16 {%0,%1}, [%2];"
                 : "=r"(r0), "=r"(r1) : "r"(addr));
}

// ---------------- block reduction helper ----------------
__device__ __forceinline__ float blk_reduce(float val, float* sh, bool do_max) {
    const unsigned mask = 0xffffffffu;
#pragma unroll
    for (int o = 16; o > 0; o >>= 1) {
        float other = __shfl_xor_sync(mask, val, o);
        val = do_max ? fmaxf(val, other) : (val + other);
    }
    int lane = threadIdx.x & 31, w = threadIdx.x >> 5;
    __syncthreads();
    if (lane == 0) sh[w] = val;
    __syncthreads();
    int nw = (blockDim.x + 31) >> 5;
    if (w == 0) {
        val = (lane < nw) ? sh[lane] : (do_max ? -3.4e38f : 0.f);
#pragma unroll
        for (int o = 16; o > 0; o >>= 1) {
            float other = __shfl_xor_sync(mask, val, o);
            val = do_max ? fmaxf(val, other) : (val + other);
        }
        if (lane == 0) sh[0] = val;
    }
    __syncthreads();
    return sh[0];
}

// ============ 64xBN fp16 GEMM, BK=32, 2 CTAs/SM, half A, fp32 B ============
// z-batched over up to 3 (B, bias, Ch) triples (QKV in one launch).
// C = A @ B (+bias)(ReLU).  A: half [M][lda] (or PAIR: relu(u_i+v_j) on the fly)
// M % 64 == 0 (no row guards), N % BN == 0, K % 32 == 0.
template<int NT, bool PAIR, bool RELU, bool OUTF, bool OUTH>
__global__ __launch_bounds__(256, 2)
void gemm_h(const __half* __restrict__ A, const float* __restrict__ U,
            const float* __restrict__ Vv,
            const float* B0, const float* b0, float* __restrict__ Cf, __half* Ch0,
            const float* B1, const float* b1, __half* Ch1,
            const float* B2, const float* b2, __half* Ch2,
            int K, int lda, int ldb, int ldc)
{
    constexpr int BM = 64;
    constexpr int BN = 32 * NT;
    constexpr int BK = 32;
    constexpr int AP = 40;          // 80B row (5x16B, odd) -> conflict-free ldsm
    constexpr int BP = BN + 8;      // 104/136 halfs -> 13/17 x16B, odd
    constexpr int NBT = (BK * BN) / 1024;   // float4 B tasks per thread (3 or 4)

    const float* B    = B0;
    const float* bias = b0;
    __half*      Ch   = Ch0;
    if (blockIdx.z == 1) { B = B1; bias = b1; Ch = Ch1; }
    else if (blockIdx.z == 2) { B = B2; bias = b2; Ch = Ch2; }

    __shared__ __half As[2][BM][AP];
    __shared__ __half Bs[2][BK][BP];

    const int tid  = threadIdx.x;
    const int lane = tid & 31;
    const int warp = tid >> 5;
    const int wR   = (warp & 1) * 32;            // 2 warps in M (32 rows each)
    const int wC   = (warp >> 1) * (8 * NT);     // 4 warps in N
    const int row0 = blockIdx.y * BM;
    const int col0 = blockIdx.x * BN;
    const int lr   = lane >> 2;
    const int lc   = lane & 3;
    const int ph   = lane >> 3;
    const int rr   = lane & 7;

    const int arow = rr + (ph & 1) * 8;
    const int acol = (ph >> 1) * 8;
    const int tkrow = rr + (ph & 1) * 8;
    const int tncol = (ph >> 1) * 8;

    // A stage map: 256 uint4 tasks (1/thread)
    const int sr0 = tid >> 2;                 // 0..63
    const int sc8 = (tid & 3) * 8;

    uint4 ra;
    float4 fu[2], fv[2];
    float4 fb[NBT];

    float acc[2][NT][4];
#pragma unroll
    for (int i = 0; i < 2; i++)
#pragma unroll
        for (int j = 0; j < NT; j++)
#pragma unroll
            for (int c = 0; c < 4; c++) acc[i][j][c] = 0.f;

    const int KT = K / BK;

    auto fetch = [&](int kb) {
        if (PAIR) {
            int m = row0 + sr0;
            int ii = m / NN_, jj = m % NN_;
            const float* up = U + (long)ii * DIM + kb + sc8;
            const float* vp = Vv + (long)jj * DIM + kb + sc8;
            fu[0] = *(const float4*)up;  fu[1] = *(const float4*)(up + 4);
            fv[0] = *(const float4*)vp;  fv[1] = *(const float4*)(vp + 4);
        } else {
            ra = *(const uint4*)(A + (long)(row0 + sr0) * lda + kb + sc8);
        }
#pragma unroll
        for (int i = 0; i < NBT; i++) {
            int id = tid + i * 256;
            int krow, nc4;
            if (NT == 4) { krow = id >> 5; nc4 = (id & 31) * 4; }
            else         { krow = id / 24; nc4 = (id % 24) * 4; }
            fb[i] = *(const float4*)(B + (long)(kb + krow) * ldb + col0 + nc4);
        }
    };
    auto stage = [&](int buf) {
        if (PAIR) {
            uint4 q;
            q.x = pack_h2(fmaxf(fu[0].x + fv[0].x, 0.f), fmaxf(fu[0].y + fv[0].y, 0.f));
            q.y = pack_h2(fmaxf(fu[0].z + fv[0].z, 0.f), fmaxf(fu[0].w + fv[0].w, 0.f));
            q.z = pack_h2(fmaxf(fu[1].x + fv[1].x, 0.f), fmaxf(fu[1].y + fv[1].y, 0.f));
            q.w = pack_h2(fmaxf(fu[1].z + fv[1].z, 0.f), fmaxf(fu[1].w + fv[1].w, 0.f));
            *(uint4*)&As[buf][sr0][sc8] = q;
        } else {
            *(uint4*)&As[buf][sr0][sc8] = ra;
        }
#pragma unroll
        for (int i = 0; i < NBT; i++) {
            int id = tid + i * 256;
            int krow, nc4;
            if (NT == 4) { krow = id >> 5; nc4 = (id & 31) * 4; }
            else         { krow = id / 24; nc4 = (id % 24) * 4; }
            uint2 q;
            q.x = pack_h2(fb[i].x, fb[i].y); q.y = pack_h2(fb[i].z, fb[i].w);
            *(uint2*)&Bs[buf][krow][nc4] = q;
        }
    };

    fetch(0);
    stage(0);
    __syncthreads();

    for (int kt = 0; kt < KT; kt++) {
        const int cur = kt & 1;
        const bool hn = (kt + 1 < KT);
        if (hn) fetch((kt + 1) * BK);

#pragma unroll
        for (int ks = 0; ks < 2; ks++) {
            const int k0 = ks * 16;
            u32 af[2][4], bf[NT][2];
#pragma unroll
            for (int mt = 0; mt < 2; mt++)
                ldsm_x4(af[mt][0], af[mt][1], af[mt][2], af[mt][3],
                        s2u(&As[cur][wR + mt * 16 + arow][k0 + acol]));
#pragma unroll
            for (int p = 0; p < NT / 2; p++)
                ldsm_x4t(bf[2 * p][0], bf[2 * p][1], bf[2 * p + 1][0], bf[2 * p + 1][1],
                         s2u(&Bs[cur][k0 + tkrow][wC + p * 16 + tncol]));
            if (NT & 1)
                ldsm_x2t(bf[NT - 1][0], bf[NT - 1][1],
                         s2u(&Bs[cur][k0 + tkrow][wC + (NT - 1) * 8]));
#pragma unroll
            for (int mt = 0; mt < 2; mt++)
#pragma unroll
                for (int nt = 0; nt < NT; nt++)
                    mma_f16(acc[mt][nt][0], acc[mt][nt][1], acc[mt][nt][2], acc[mt][nt][3],
                            af[mt][0], af[mt][1], af[mt][2], af[mt][3],
                            bf[nt][0], bf[nt][1]);
        }

        if (hn) stage(cur ^ 1);
        __syncthreads();
    }

    // ---- epilogue ----
#pragma unroll
    for (int nt = 0; nt < NT; nt++) {
        int gn = col0 + wC + nt * 8 + 2 * lc;
        float b0v = bias[gn], b1v = bias[gn + 1];
#pragma unroll
        for (int mt = 0; mt < 2; mt++) {
            int gm0 = row0 + wR + mt * 16 + lr;
#pragma unroll
            for (int h = 0; h < 2; h++) {
                int gm = gm0 + h * 8;
                float v0 = acc[mt][nt][2 * h]     + b0v;
                float v1 = acc[mt][nt][2 * h + 1] + b1v;
                if (RELU) { v0 = fmaxf(v0, 0.f); v1 = fmaxf(v1, 0.f); }
                if (OUTF) *(float2*)(Cf + (long)gm * ldc + gn) = make_float2(v0, v1);
                if (OUTH) *(u32*)(Ch + (long)gm * ldc + gn) = pack_h2(v0, v1);
            }
        }
    }
}

// ---------------- small-M GEMM (u/v projections, merged over z) ----------------
__global__ __launch_bounds__(256)
void gemm_uv(const float* __restrict__ Aht, const float* __restrict__ B1,
             const float* __restrict__ bias1, float* __restrict__ C1,
             const float* __restrict__ B2, const float* __restrict__ bias2,
             float* __restrict__ C2)
{
    constexpr int NT = 3, BN = 96, BK = 16, AP = 24, BP = BN + 8;
    const float* B   = blockIdx.z ? B2 : B1;
    const float* bia = blockIdx.z ? bias2 : bias1;
    float*       C   = blockIdx.z ? C2 : C1;
    const int M = NN_, Kt = DIM;

    __shared__ __half As[2][128][AP];
    __shared__ __half Bs[2][BK][BP];

    const int tid  = threadIdx.x;
    const int lane = tid & 31;
    const int warp = tid >> 5;
    const int wR   = (warp & 1) * 64;
    const int wC   = (warp >> 1) * 24;
    const int col0 = blockIdx.x * BN;
    const int lr   = lane >> 2;
    const int lc   = lane & 3;
    const int ph   = lane >> 3;
    const int rr   = lane & 7;

    const int arow = rr + (ph & 1) * 8;
    const int acol = (ph >> 1) * 8;
    const int tkrow = rr + (ph & 1) * 8;
    const int tncol = (ph >> 1) * 8;

    const int ar = tid >> 1;
    const int ac = (tid & 1) * 8;
    int kb0 = tid / 24, nb0 = (tid % 24) * 4;
    bool b1v = (tid < 128);
    int id1 = tid + 256;
    int kb1 = id1 / 24, nb1 = (id1 % 24) * 4;

    const float4 f4z = make_float4(0.f, 0.f, 0.f, 0.f);
    float4 fa0, fa1, fb0, fb1;

    float acc[4][NT][4];
#pragma unroll
    for (int i = 0; i < 4; i++)
#pragma unroll
        for (int j = 0; j < NT; j++)
#pragma unroll
            for (int c = 0; c < 4; c++) acc[i][j][c] = 0.f;

    auto fetch = [&](int k0g) {
        const float* ap = Aht + (long)ar * DIM + k0g + ac;
        fa0 = (ar < M) ? *(const float4*)ap : f4z;
        fa1 = (ar < M) ? *(const float4*)(ap + 4) : f4z;
        fb0 = *(const float4*)(B + (long)(k0g + kb0) * DIM + col0 + nb0);
        if (b1v) fb1 = *(const float4*)(B + (long)(k0g + kb1) * DIM + col0 + nb1);
    };
    auto stage = [&](int buf) {
        uint4 qa;
        qa.x = pack_h2(fa0.x, fa0.y); qa.y = pack_h2(fa0.z, fa0.w);
        qa.z = pack_h2(fa1.x, fa1.y); qa.w = pack_h2(fa1.z, fa1.w);
        *(uint4*)&As[buf][ar][ac] = qa;
        uint2 qb0;
        qb0.x = pack_h2(fb0.x, fb0.y); qb0.y = pack_h2(fb0.z, fb0.w);
        *(uint2*)&Bs[buf][kb0][nb0] = qb0;
        if (b1v) {
            uint2 qb1;
            qb1.x = pack_h2(fb1.x, fb1.y); qb1.y = pack_h2(fb1.z, fb1.w);
            *(uint2*)&Bs[buf][kb1][nb1] = qb1;
        }
    };

    fetch(0);
    stage(0);
    __syncthreads();

    const int KT = Kt / BK;
    for (int kt = 0; kt < KT; kt++) {
        const int cur = kt & 1;
        const bool hn = (kt + 1 < KT);
        if (hn) fetch((kt + 1) * BK);

        u32 af[4][4], bf[NT][2];
#pragma unroll
        for (int mt = 0; mt < 4; mt++)
            ldsm_x4(af[mt][0], af[mt][1], af[mt][2], af[mt][3],
                    s2u(&As[cur][wR + mt * 16 + arow][acol]));
        ldsm_x4t(bf[0][0], bf[0][1], bf[1][0], bf[1][1],
                 s2u(&Bs[cur][tkrow][wC + tncol]));
        ldsm_x2t(bf[2][0], bf[2][1], s2u(&Bs[cur][tkrow][wC + 16]));
#pragma unroll
        for (int mt = 0; mt < 4; mt++)
#pragma unroll
            for (int nt = 0; nt < NT; nt++)
                mma_f16(acc[mt][nt][0], acc[mt][nt][1], acc[mt][nt][2], acc[mt][nt][3],
                        af[mt][0], af[mt][1], af[mt][2], af[mt][3],
                        bf[nt][0], bf[nt][1]);

        if (hn) stage(cur ^ 1);
        __syncthreads();
    }

#pragma unroll
    for (int nt = 0; nt < NT; nt++) {
        int gn = col0 + wC + nt * 8 + 2 * lc;
        float b0 = bia[gn], b1 = bia[gn + 1];
#pragma unroll
        for (int mt = 0; mt < 4; mt++) {
            int gm0 = wR + mt * 16 + lr;
#pragma unroll
            for (int h = 0; h < 2; h++) {
                int gm = gm0 + h * 8;
                if (gm >= M) continue;
                *(float2*)(C + (long)gm * DIM + gn) =
                    make_float2(acc[mt][nt][2 * h] + b0, acc[mt][nt][2 * h + 1] + b1);
            }
        }
    }
}

// ---------------- flash attention (fp16 in/out, online softmax) ----------------
#define FQ_P 104
#define FK_P 104
#define FV_P 104
#define FP_P 72
#define FQ_OFF 0
#define FK_OFF 13312
#define FV_OFF 26624
#define FP_OFF 39936
#define FLASH_SMEM ((39936 + 128 * 72) * 2)

__global__ __launch_bounds__(256)
void flash_kernel(const __half* __restrict__ Q, const __half* __restrict__ K,
                  const __half* __restrict__ V, __half* __restrict__ O, float scale)
{
    extern __shared__ __half smh[];
    __half* Qs = smh + FQ_OFF;
    __half* Ks = smh + FK_OFF;
    __half* Vs = smh + FV_OFF;
    __half* Ps = smh + FP_OFF;

    const int tid  = threadIdx.x;
    const int lane = tid & 31;
    const int warp = tid >> 5;
    const int lr   = lane >> 2;
    const int lc   = lane & 3;
    const int ph   = lane >> 3;
    const int rr   = lane & 7;
    const int wm   = warp * 16;
    const int mt0  = blockIdx.x * 128;
    const int head = blockIdx.y;

    const int arow = rr + (ph & 1) * 8;
    const int acol = (ph >> 1) * 8;
    const int brow = rr + (ph >> 1) * 8;
    const int bcol = (ph & 1) * 8;
    const int tkrow = rr + (ph & 1) * 8;
    const int tncol = (ph >> 1) * 8;

    const __half* Qb = Q + (long)mt0 * DIM + head * DK;
    const __half* Kb = K + head * DK;
    const __half* Vb = V + head * DK;

#pragma unroll
    for (int it = 0; it < 6; it++) {
        int id  = tid + it * 256;
        int row = id / 12;
        int c8  = (id % 12) * 8;
        *(uint4*)&Qs[row * FQ_P + c8] = *(const uint4*)(Qb + (long)row * DIM + c8);
    }

    uint4 rk[3], rv[3];
    auto fetch = [&](int t) {
        int kv0 = t * 64;
#pragma unroll
        for (int it = 0; it < 3; it++) {
            int id  = tid + it * 256;
            int row = id / 12;
            int c8  = (id % 12) * 8;
            rk[it] = *(const uint4*)(Kb + (long)(kv0 + row) * DIM + c8);
            rv[it] = *(const uint4*)(Vb + (long)(kv0 + row) * DIM + c8);
        }
    };
    auto stage = [&](int buf) {
#pragma unroll
        for (int it = 0; it < 3; it++) {
            int id  = tid + it * 256;
            int row = id / 12;
            int c8  = (id % 12) * 8;
            *(uint4*)&Ks[(buf * 64 + row) * FK_P + c8] = rk[it];
            *(uint4*)&Vs[(buf * 64 + row) * FV_P + c8] = rv[it];
        }
    };

    float oacc[12][4];
#pragma unroll
    for (int i = 0; i < 12; i++)
#pragma unroll
        for (int c = 0; c < 4; c++) oacc[i][c] = 0.f;
    float mrow0 = -1e30f, mrow1 = -1e30f, lrow0 = 0.f, lrow1 = 0.f;

    fetch(0);
    stage(0);
    __syncthreads();

    const int NIT = TT / 64;
    for (int t = 0; t < NIT; t++) {
        const int cur = t & 1;
        const bool hn = (t + 1 < NIT);
        if (hn) fetch(t + 1);

        float sacc[8][4];
#pragma unroll
        for (int nt = 0; nt < 8; nt++)
#pragma unroll
            for (int c = 0; c < 4; c++) sacc[nt][c] = 0.f;

#pragma unroll
        for (int ks = 0; ks < 6; ks++) {
            const int k0 = ks * 16;
            u32 a0, a1, a2, a3;
            ldsm_x4(a0, a1, a2, a3, s2u(&Qs[(wm + arow) * FQ_P + k0 + acol]));
            u32 bf[8][2];
#pragma unroll
            for (int p = 0; p < 4; p++)
                ldsm_x4(bf[2 * p][0], bf[2 * p][1], bf[2 * p + 1][0], bf[2 * p + 1][1],
                        s2u(&Ks[(cur * 64 + p * 16 + brow) * FK_P + k0 + bcol]));
#pragma unroll
            for (int nt = 0; nt < 8; nt++)
                mma_f16(sacc[nt][0], sacc[nt][1], sacc[nt][2], sacc[nt][3],
                        a0, a1, a2, a3, bf[nt][0], bf[nt][1]);
        }

        float rm0 = -1e30f, rm1 = -1e30f;
#pragma unroll
        for (int nt = 0; nt < 8; nt++) {
            rm0 = fmaxf(rm0, fmaxf(sacc[nt][0], sacc[nt][1]));
            rm1 = fmaxf(rm1, fmaxf(sacc[nt][2], sacc[nt][3]));
        }
        rm0 *= scale; rm1 *= scale;
#pragma unroll
        for (int o = 1; o <= 2; o <<= 1) {
            rm0 = fmaxf(rm0, __shfl_xor_sync(0xffffffffu, rm0, o));
            rm1 = fmaxf(rm1, __shfl_xor_sync(0xffffffffu, rm1, o));
        }
        float mn0 = fmaxf(mrow0, rm0);
        float mn1 = fmaxf(mrow1, rm1);
        float al0 = __expf(mrow0 - mn0);
        float al1 = __expf(mrow1 - mn1);
        float sum0 = 0.f, sum1 = 0.f;
#pragma unroll
        for (int nt = 0; nt < 8; nt++) {
            float p0 = __expf(sacc[nt][0] * scale - mn0);
            float p1 = __expf(sacc[nt][1] * scale - mn0);
            float p2 = __expf(sacc[nt][2] * scale - mn1);
            float p3 = __expf(sacc[nt][3] * scale - mn1);
            sum0 += p0 + p1; sum1 += p2 + p3;
            *(u32*)&Ps[(wm + lr) * FP_P + nt * 8 + 2 * lc]     = pack_h2(p0, p1);
            *(u32*)&Ps[(wm + lr + 8) * FP_P + nt * 8 + 2 * lc] = pack_h2(p2, p3);
        }
#pragma unroll
        for (int o = 1; o <= 2; o <<= 1) {
            sum0 += __shfl_xor_sync(0xffffffffu, sum0, o);
            sum1 += __shfl_xor_sync(0xffffffffu, sum1, o);
        }
        lrow0 = lrow0 * al0 + sum0;
        lrow1 = lrow1 * al1 + sum1;
        mrow0 = mn0; mrow1 = mn1;
#pragma unroll
        for (int nt = 0; nt < 12; nt++) {
            oacc[nt][0] *= al0; oacc[nt][1] *= al0;
            oacc[nt][2] *= al1; oacc[nt][3] *= al1;
        }

        if (hn) stage(cur ^ 1);
        __syncwarp();

#pragma unroll
        for (int ksv = 0; ksv < 4; ksv++) {
            const int k0 = ksv * 16;
            u32 a0, a1, a2, a3;
            ldsm_x4(a0, a1, a2, a3, s2u(&Ps[(wm + arow) * FP_P + k0 + acol]));
            u32 bf[12][2];
#pragma unroll
            for (int p = 0; p < 6; p++)
                ldsm_x4t(bf[2 * p][0], bf[2 * p][1], bf[2 * p + 1][0], bf[2 * p + 1][1],
                         s2u(&Vs[(cur * 64 + k0 + tkrow) * FV_P + p * 16 + tncol]));
#pragma unroll
            for (int nt = 0; nt < 12; nt++)
                mma_f16(oacc[nt][0], oacc[nt][1], oacc[nt][2], oacc[nt][3],
                        a0, a1, a2, a3, bf[nt][0], bf[nt][1]);
        }
        __syncthreads();
    }

    float inv0 = 1.f / lrow0;
    float inv1 = 1.f / lrow1;
    int r0 = mt0 + wm + lr;
    int r1 = r0 + 8;
#pragma unroll
    for (int nt = 0; nt < 12; nt++) {
        int col = head * DK + nt * 8 + 2 * lc;
        *(u32*)(O + (long)r0 * DIM + col) = pack_h2(oacc[nt][0] * inv0, oacc[nt][1] * inv0);
        *(u32*)(O + (long)r1 * DIM + col) = pack_h2(oacc[nt][2] * inv1, oacc[nt][3] * inv1);
    }
}

// ---------------- span max pooling ----------------
__global__ void pool_kernel(const float* __restrict__ emb, const int* __restrict__ spans,
                            float* __restrict__ htb)
{
    int node = blockIdx.x;
    int bag  = node / NPD;
    int s0 = spans[node * 2 + 0];
    int s1 = spans[node * 2 + 1];
    const float* base = emb + (long)bag * SEQ * DIM;
    for (int d = threadIdx.x; d < DIM; d += blockDim.x) {
        float m = -3.4e38f;
        for (int p = s0; p <= s1; p++)
            m = fmaxf(m, base[(long)p * DIM + d]);
        htb[(long)node * DIM + d] = m;
    }
}

// ---------------- x = LN(x + o) * g + b  -> fp32 x and fp16 xh ----------------
__global__ void add_ln_kernel(float* __restrict__ x, __half* __restrict__ xh,
                              const float* __restrict__ o,
                              const float* __restrict__ g, const float* __restrict__ b)
{
    long base = (long)blockIdx.x * DIM;
    float* xr = x + base;
    __half* xhr = xh + base;
    const float* orr = o + base;
    __shared__ float sh[32];
    float v[3];
    float s = 0.f, s2 = 0.f;
#pragma unroll
    for (int i = 0; i < 3; i++) {
        int d = threadIdx.x + i * 256;
        float t = xr[d] + orr[d];
        v[i] = t; s += t; s2 += t * t;
    }
    s  = blk_reduce(s,  sh, false);
    s2 = blk_reduce(s2, sh, false);
    float mean = s * (1.f / DIM);
    float var  = s2 * (1.f / DIM) - mean * mean;
    float inv  = rsqrtf(var + 1e-5f);
#pragma unroll
    for (int i = 0; i < 3; i++) {
        int d = threadIdx.x + i * 256;
        float r = (v[i] - mean) * inv * g[d] + b[d];
        xr[d] = r;
        xhr[d] = __float2half_rn(r);
    }
}

// ---------------- final: gather (h,t) cells, LN, predictor ----------------
__global__ void final_kernel(const float* __restrict__ x, const float* __restrict__ ng,
                             const float* __restrict__ nb, const float* __restrict__ Wp,
                             const float* __restrict__ bp, float* __restrict__ ht)
{
    int bag = blockIdx.x;
    long r = (long)(bag * NPD) * NN_ + (bag * NPD + 1);
    const float* row = x + r * DIM;
    __shared__ float sh[DIM];
    __shared__ float red[32];
    float s = 0.f, s2 = 0.f;
    for (int d = threadIdx.x; d < DIM; d += blockDim.x) {
        float t = row[d];
        sh[d] = t; s += t; s2 += t * t;
    }
    s  = blk_reduce(s,  red, false);
    s2 = blk_reduce(s2, red, false);
    float mean = s * (1.f / DIM);
    float inv  = rsqrtf(s2 * (1.f / DIM) - mean * mean + 1e-5f);
    __syncthreads();
    for (int d = threadIdx.x; d < DIM; d += blockDim.x)
        sh[d] = (sh[d] - mean) * inv * ng[d] + nb[d];
    __syncthreads();
    for (int n = threadIdx.x; n < NREL; n += blockDim.x) {
        float acc = bp[n];
        for (int k = 0; k < DIM; k++)
            acc = fmaf(sh[k], Wp[(long)k * NREL + n], acc);
        ht[bag * NREL + n] = acc;
    }
}

// ---------------- output assembly: bag max + layout ----------------
__global__ void writeout_kernel(const float* __restrict__ ht, float* __restrict__ out,
                                int out_size)
{
    int n = threadIdx.x;
    if (n >= NREL) return;
    float m = -3.4e38f;
    for (int b = 0; b < BAG; b++) m = fmaxf(m, ht[b * NREL + n]);
    if (out_size >= NREL * (BAG + 1)) {
        out[n] = m;
        for (int b = 0; b < BAG; b++) out[NREL + b * NREL + n] = ht[b * NREL + n];
    } else if (out_size == NREL) {
        out[n] = m;
    } else {
        for (int b = 0; b < BAG; b++) out[b * NREL + n] = ht[b * NREL + n];
    }
}

// ---------------- host ----------------
template <typename T>
static inline void* symv(T& s) {
    void* p = nullptr;
    cudaGetSymbolAddress(&p, s);
    return p;
}

extern "C" void kernel_launch(void* const* d_in, const int* in_sizes, int n_in,
                              void* d_out, int out_size)
{
    const float* emb   = (const float*)d_in[0];
    const int*   spans = (const int*)  d_in[1];
    const float* Wu = (const float*)d_in[2];  const float* bu = (const float*)d_in[3];
    const float* Wv = (const float*)d_in[4];  const float* bv = (const float*)d_in[5];
    const float* Wl = (const float*)d_in[6];  const float* bl = (const float*)d_in[7];
    const float* Wq = (const float*)d_in[8];  const float* bq = (const float*)d_in[9];
    const float* Wk = (const float*)d_in[10]; const float* bk = (const float*)d_in[11];
    const float* Wvm= (const float*)d_in[12]; const float* bvm= (const float*)d_in[13];
    const float* Wo = (const float*)d_in[14]; const float* bo = (const float*)d_in[15];
    const float* F1 = (const float*)d_in[16]; const float* f1 = (const float*)d_in[17];
    const float* F2 = (const float*)d_in[18]; const float* f2 = (const float*)d_in[19];
    const float* g1 = (const float*)d_in[20]; const float* be1= (const float*)d_in[21];
    const float* g2 = (const float*)d_in[22]; const float* be2= (const float*)d_in[23];
    const float* ng = (const float*)d_in[24]; const float* nb = (const float*)d_in[25];
    const float* Wp = (const float*)d_in[26]; const float* bp = (const float*)d_in[27];

    float*  htb = (float*) symv(g_htb);
    float*  u   = (float*) symv(g_u);
    float*  v   = (float*) symv(g_v);
    float*  x   = (float*) symv(g_x);
    float*  tmp = (float*) symv(g_tmp);
    float*  ht  = (float*) symv(g_ht);
    __half* xh  = (__half*)symv(g_xh);
    __half* qh  = (__half*)symv(g_qh);
    __half* kh  = (__half*)symv(g_kh);
    __half* vh  = (__half*)symv(g_vh);
    __half* ah  = (__half*)symv(g_ah);
    __half* fh  = (__half*)symv(g_fh);
    float*  out = (float*)d_out;

    const float scale = 0.102062072615966f;   // 1/sqrt(96)

    cudaFuncSetAttribute(flash_kernel, cudaFuncAttributeMaxDynamicSharedMemorySize,
                         FLASH_SMEM);

    const dim3 g1z(8, 36, 1);    // N=768 via BN=96, M=2304, BM=64 -> 288 CTAs
    const dim3 g3z(8, 36, 3);    // QKV merged -> 864 CTAs
    const dim3 gF1(8, 36, 1);    // N=1024 via BN=128 -> 288 CTAs

    // 1) span max pooling -> htb [48,768]
    pool_kernel<<<NN_, 256>>>(emb, spans, htb);

    // 2) u/v projections (merged, M=48)
    gemm_uv<<<dim3(8, 1, 2), 256>>>(htb, Wu, bu, u, Wv, bv, v);

    // 3) x = relu(relu(u_i + v_j) @ Wl + bl)   (pair fused into A-stage)
    gemm_h<3, true, true, true, true><<<g1z, 256>>>(
        nullptr, u, v, Wl, bl, x, xh, Wl, bl, xh, Wl, bl, xh, DIM, DIM, DIM, DIM);

    // 4) MatTransformer layers
    for (int l = 0; l < NLAYER; l++) {
        const float* Wq_l = Wq + (size_t)l * DIM * DIM;  const float* bq_l = bq + (size_t)l * DIM;
        const float* Wk_l = Wk + (size_t)l * DIM * DIM;  const float* bk_l = bk + (size_t)l * DIM;
        const float* Wv_l = Wvm+ (size_t)l * DIM * DIM;  const float* bv_l = bvm+ (size_t)l * DIM;
        const float* Wo_l = Wo + (size_t)l * DIM * DIM;  const float* bo_l = bo + (size_t)l * DIM;
        const float* F1_l = F1 + (size_t)l * DIM * DFF;  const float* f1_l = f1 + (size_t)l * DFF;
        const float* F2_l = F2 + (size_t)l * DFF * DIM;  const float* f2_l = f2 + (size_t)l * DIM;
        const float* g1_l = g1 + (size_t)l * DIM;        const float* be1_l= be1+ (size_t)l * DIM;
        const float* g2_l = g2 + (size_t)l * DIM;        const float* be2_l= be2+ (size_t)l * DIM;

        // QKV projections: ONE launch, z selects W/b/out
        gemm_h<3, false, false, false, true><<<g3z, 256>>>(
            xh, nullptr, nullptr,
            Wq_l, bq_l, nullptr, qh,
            Wk_l, bk_l, kh,
            Wv_l, bv_l, vh, DIM, DIM, DIM, DIM);

        // fused attention (half in, half out)
        flash_kernel<<<dim3(TT / 128, NHEAD), 256, FLASH_SMEM>>>(qh, kh, vh, ah, scale);

        // output projection + residual LN
        gemm_h<3, false, false, true, false><<<g1z, 256>>>(
            ah, nullptr, nullptr, Wo_l, bo_l, tmp, nullptr,
            Wo_l, bo_l, nullptr, Wo_l, bo_l, nullptr, DIM, DIM, DIM, DIM);
        add_ln_kernel<<<TT, 256>>>(x, xh, tmp, g1_l, be1_l);

        // FFN + residual LN
        gemm_h<4, false, true, false, true><<<gF1, 256>>>(
            xh, nullptr, nullptr, F1_l, f1_l, nullptr, fh,
            F1_l, f1_l, fh, F1_l, f1_l, fh, DIM, DIM, DFF, DFF);
        gemm_h<3, false, false, true, false><<<g1z, 256>>>(
            fh, nullptr, nullptr, F2_l, f2_l, tmp, nullptr,
            F2_l, f2_l, nullptr, F2_l, f2_l, nullptr, DFF, DFF, DIM, DIM);
        add_ln_kernel<<<TT, 256>>>(x, xh, tmp, g2_l, be2_l);
    }

    // 5) final gather + LN + predictor + bag max
    final_kernel<<<BAG, 256>>>(x, ng, nb, Wp, bp, ht);
    writeout_kernel<<<1, 128>>>(ht, out, out_size);
}

// round 15
// speedup vs baseline: 2.5200x; 1.1242x over previous
#include <cuda_runtime.h>
#include <cuda_fp16.h>
#include <cstdint>

// ---------------- problem constants ----------------
#define BAG  8
#define SEQ  512
#define DIM  768
#define NPD  6
#define NN_  48          // N nodes
#define TT   2304        // T = N*N
#define NHEAD 8
#define DK   96
#define DFF  1024
#define NLAYER 4
#define NREL 97

typedef uint32_t u32;

// ---------------- device scratch (no allocations allowed) ----------------
__device__ float  g_htb [NN_ * DIM];
__device__ float  g_u   [NN_ * DIM];
__device__ float  g_v   [NN_ * DIM];
__device__ float  g_x   [TT * DIM];
__device__ float  g_tmp [TT * DIM];
__device__ float  g_ht  [BAG * NREL];
__device__ __half g_xh  [TT * DIM];
__device__ __half g_qh  [TT * DIM];
__device__ __half g_kh  [TT * DIM];
__device__ __half g_vh  [TT * DIM];
__device__ __half g_ah  [TT * DIM];
__device__ __half g_fh  [TT * DFF];
// half weights: Wl | Wq | Wk | Wv | Wo | F1 | F2
#define OWL 0
#define OWQ (OWL + DIM*DIM)
#define OWK (OWQ + NLAYER*DIM*DIM)
#define OWV (OWK + NLAYER*DIM*DIM)
#define OWO (OWV + NLAYER*DIM*DIM)
#define OF1 (OWO + NLAYER*DIM*DIM)
#define OF2 (OF1 + NLAYER*DIM*DFF)
#define WH_TOTAL (OF2 + NLAYER*DFF*DIM)
__device__ __half g_wh[WH_TOTAL];

// ---------------- fp16 / ldmatrix / cp.async helpers ----------------
__device__ __forceinline__ u32 pack_h2(float a, float b) {
    __half2 h = __floats2half2_rn(a, b);
    return *(u32*)&h;
}
__device__ __forceinline__ void mma_f16(float& c0, float& c1, float& c2, float& c3,
                                        u32 a0, u32 a1, u32 a2, u32 a3,
                                        u32 b0, u32 b1) {
    asm("mma.sync.aligned.m16n8k16.row.col.f32.f16.f16.f32 "
        "{%0,%1,%2,%3}, {%4,%5,%6,%7}, {%8,%9}, {%0,%1,%2,%3};"
        : "+f"(c0), "+f"(c1), "+f"(c2), "+f"(c3)
        : "r"(a0), "r"(a1), "r"(a2), "r"(a3), "r"(b0), "r"(b1));
}
__device__ __forceinline__ u32 s2u(const void* p) {
    return (u32)__cvta_generic_to_shared(p);
}
__device__ __forceinline__ void ldsm_x4(u32& r0, u32& r1, u32& r2, u32& r3, u32 addr) {
    asm volatile("ldmatrix.sync.aligned.m8n8.x4.shared.b16 {%0,%1,%2,%3}, [%4];"
                 : "=r"(r0), "=r"(r1), "=r"(r2), "=r"(r3) : "r"(addr));
}
__device__ __forceinline__ void ldsm_x4t(u32& r0, u32& r1, u32& r2, u32& r3, u32 addr) {
    asm volatile("ldmatrix.sync.aligned.m8n8.x4.trans.shared.b16 {%0,%1,%2,%3}, [%4];"
                 : "=r"(r0), "=r"(r1), "=r"(r2), "=r"(r3) : "r"(addr));
}
__device__ __forceinline__ void ldsm_x2t(u32& r0, u32& r1, u32 addr) {
    asm volatile("ldmatrix.sync.aligned.m8n8.x2.trans.shared.b16 {%0,%1}, [%2];"
                 : "=r"(r0), "=r"(r1) : "r"(addr));
}
__device__ __forceinline__ void cp16(u32 dst, const void* src) {
    asm volatile("cp.async.cg.shared.global [%0], [%1], 16;" :: "r"(dst), "l"(src));
}
#define CP_COMMIT() asm volatile("cp.async.commit_group;")
#define CP_WAIT(n)  asm volatile("cp.async.wait_group %0;" :: "n"(n))

// ---------------- block reduction helper ----------------
__device__ __forceinline__ float blk_reduce(float val, float* sh, bool do_max) {
    const unsigned mask = 0xffffffffu;
#pragma unroll
    for (int o = 16; o > 0; o >>= 1) {
        float other = __shfl_xor_sync(mask, val, o);
        val = do_max ? fmaxf(val, other) : (val + other);
    }
    int lane = threadIdx.x & 31, w = threadIdx.x >> 5;
    __syncthreads();
    if (lane == 0) sh[w] = val;
    __syncthreads();
    int nw = (blockDim.x + 31) >> 5;
    if (w == 0) {
        val = (lane < nw) ? sh[lane] : (do_max ? -3.4e38f : 0.f);
#pragma unroll
        for (int o = 16; o > 0; o >>= 1) {
            float other = __shfl_xor_sync(mask, val, o);
            val = do_max ? fmaxf(val, other) : (val + other);
        }
        if (lane == 0) sh[0] = val;
    }
    __syncthreads();
    return sh[0];
}

// ---------------- weight fp32 -> fp16 ----------------
__global__ void f2h_kernel(const float* __restrict__ src, __half* __restrict__ dst, int n)
{
    int i = (blockIdx.x * 256 + threadIdx.x) * 8;
    if (i >= n) return;
    float4 a = *(const float4*)(src + i);
    float4 b = *(const float4*)(src + i + 4);
    uint4 q;
    q.x = pack_h2(a.x, a.y); q.y = pack_h2(a.z, a.w);
    q.z = pack_h2(b.x, b.y); q.w = pack_h2(b.z, b.w);
    *(uint4*)(dst + i) = q;
}

// ============ 64xBN fp16 GEMM, BK=32, cp.async pipeline, 2 CTAs/SM ============
// z-batched over up to 3 (B, bias, Ch) triples.
// C = A @ B (+bias)(ReLU).  A: half [M][lda] (or PAIR: relu(u_i+v_j) on the fly)
// M % 64 == 0, N % BN == 0, K % 32 == 0.
template<int NT, bool PAIR, bool RELU, bool OUTF, bool OUTH>
__global__ __launch_bounds__(256, 2)
void gemm_h(const __half* __restrict__ A, const float* __restrict__ U,
            const float* __restrict__ Vv,
            const __half* B0, const float* b0, float* __restrict__ Cf, __half* Ch0,
            const __half* B1, const float* b1, __half* Ch1,
            const __half* B2, const float* b2, __half* Ch2,
            int K, int lda, int ldb, int ldc)
{
    constexpr int BM = 64;
    constexpr int BN = 32 * NT;
    constexpr int BK = 32;
    constexpr int AP = 40;            // 80B row (5x16B, odd) -> conflict-free ldsm
    constexpr int BP = BN + 8;        // 104/136 halfs -> 13/17 x16B, odd
    constexpr int BCH = (BK * BN) / 8;  // B 16B-chunks: 384 (NT=3) / 512 (NT=4)

    const __half* B    = B0;
    const float*  bias = b0;
    __half*       Ch   = Ch0;
    if (blockIdx.z == 1) { B = B1; bias = b1; Ch = Ch1; }
    else if (blockIdx.z == 2) { B = B2; bias = b2; Ch = Ch2; }

    __shared__ __half As[2][BM][AP];
    __shared__ __half Bs[2][BK][BP];

    const int tid  = threadIdx.x;
    const int lane = tid & 31;
    const int warp = tid >> 5;
    const int wR   = (warp & 1) * 32;
    const int wC   = (warp >> 1) * (8 * NT);
    const int row0 = blockIdx.y * BM;
    const int col0 = blockIdx.x * BN;
    const int lr   = lane >> 2;
    const int lc   = lane & 3;
    const int ph   = lane >> 3;
    const int rr   = lane & 7;

    const int arow = rr + (ph & 1) * 8;
    const int acol = (ph >> 1) * 8;
    const int tkrow = rr + (ph & 1) * 8;
    const int tncol = (ph >> 1) * 8;

    // A stage map: 256 16B chunks (1/thread)
    const int sr0 = tid >> 2;                 // 0..63
    const int sc8 = (tid & 3) * 8;

    float4 fu[2], fv[2];                      // PAIR only

    float acc[2][NT][4];
#pragma unroll
    for (int i = 0; i < 2; i++)
#pragma unroll
        for (int j = 0; j < NT; j++)
#pragma unroll
            for (int c = 0; c < 4; c++) acc[i][j][c] = 0.f;

    const int KT = K / BK;

    auto issueB = [&](int kb, int buf) {
#pragma unroll
        for (int i = 0; i < (BCH + 255) / 256; i++) {
            int t = tid + i * 256;
            if ((BCH & 255) && t >= BCH) break;
            int krow = t / (BN / 8), c8 = (t % (BN / 8)) * 8;
            cp16(s2u(&Bs[buf][krow][c8]), B + (long)(kb + krow) * ldb + col0 + c8);
        }
    };
    auto issueA = [&](int kb, int buf) {
        cp16(s2u(&As[buf][sr0][sc8]), A + (long)(row0 + sr0) * lda + kb + sc8);
    };
    auto fetchPA = [&](int kb) {
        int m = row0 + sr0;
        int ii = m / NN_, jj = m % NN_;
        const float* up = U + (long)ii * DIM + kb + sc8;
        const float* vp = Vv + (long)jj * DIM + kb + sc8;
        fu[0] = *(const float4*)up;  fu[1] = *(const float4*)(up + 4);
        fv[0] = *(const float4*)vp;  fv[1] = *(const float4*)(vp + 4);
    };
    auto stagePA = [&](int buf) {
        uint4 q;
        q.x = pack_h2(fmaxf(fu[0].x + fv[0].x, 0.f), fmaxf(fu[0].y + fv[0].y, 0.f));
        q.y = pack_h2(fmaxf(fu[0].z + fv[0].z, 0.f), fmaxf(fu[0].w + fv[0].w, 0.f));
        q.z = pack_h2(fmaxf(fu[1].x + fv[1].x, 0.f), fmaxf(fu[1].y + fv[1].y, 0.f));
        q.w = pack_h2(fmaxf(fu[1].z + fv[1].z, 0.f), fmaxf(fu[1].w + fv[1].w, 0.f));
        *(uint4*)&As[buf][sr0][sc8] = q;
    };

    // prologue
    if (PAIR) { fetchPA(0); stagePA(0); }
    else      issueA(0, 0);
    issueB(0, 0);
    CP_COMMIT();

    for (int kt = 0; kt < KT; kt++) {
        const int cur = kt & 1;
        const bool hn = (kt + 1 < KT);
        if (hn) {
            if (PAIR) fetchPA((kt + 1) * BK);
            else      issueA((kt + 1) * BK, cur ^ 1);
            issueB((kt + 1) * BK, cur ^ 1);
            CP_COMMIT();
            CP_WAIT(1);
        } else {
            CP_WAIT(0);
        }
        __syncthreads();

#pragma unroll
        for (int ks = 0; ks < 2; ks++) {
            const int k0 = ks * 16;
            u32 af[2][4], bf[NT][2];
#pragma unroll
            for (int mt = 0; mt < 2; mt++)
                ldsm_x4(af[mt][0], af[mt][1], af[mt][2], af[mt][3],
                        s2u(&As[cur][wR + mt * 16 + arow][k0 + acol]));
#pragma unroll
            for (int p = 0; p < NT / 2; p++)
                ldsm_x4t(bf[2 * p][0], bf[2 * p][1], bf[2 * p + 1][0], bf[2 * p + 1][1],
                         s2u(&Bs[cur][k0 + tkrow][wC + p * 16 + tncol]));
            if (NT & 1)
                ldsm_x2t(bf[NT - 1][0], bf[NT - 1][1],
                         s2u(&Bs[cur][k0 + tkrow][wC + (NT - 1) * 8]));
#pragma unroll
            for (int mt = 0; mt < 2; mt++)
#pragma unroll
                for (int nt = 0; nt < NT; nt++)
                    mma_f16(acc[mt][nt][0], acc[mt][nt][1], acc[mt][nt][2], acc[mt][nt][3],
                            af[mt][0], af[mt][1], af[mt][2], af[mt][3],
                            bf[nt][0], bf[nt][1]);
        }

        if (hn && PAIR) stagePA(cur ^ 1);
        __syncthreads();
    }

    // ---- epilogue ----
#pragma unroll
    for (int nt = 0; nt < NT; nt++) {
        int gn = col0 + wC + nt * 8 + 2 * lc;
        float b0v = bias[gn], b1v = bias[gn + 1];
#pragma unroll
        for (int mt = 0; mt < 2; mt++) {
            int gm0 = row0 + wR + mt * 16 + lr;
#pragma unroll
            for (int h = 0; h < 2; h++) {
                int gm = gm0 + h * 8;
                float v0 = acc[mt][nt][2 * h]     + b0v;
                float v1 = acc[mt][nt][2 * h + 1] + b1v;
                if (RELU) { v0 = fmaxf(v0, 0.f); v1 = fmaxf(v1, 0.f); }
                if (OUTF) *(float2*)(Cf + (long)gm * ldc + gn) = make_float2(v0, v1);
                if (OUTH) *(u32*)(Ch + (long)gm * ldc + gn) = pack_h2(v0, v1);
            }
        }
    }
}

// ---------------- small-M GEMM (u/v projections, merged over z) ----------------
__global__ __launch_bounds__(256)
void gemm_uv(const float* __restrict__ Aht, const float* __restrict__ B1,
             const float* __restrict__ bias1, float* __restrict__ C1,
             const float* __restrict__ B2, const float* __restrict__ bias2,
             float* __restrict__ C2)
{
    constexpr int NT = 3, BN = 96, BK = 16, AP = 24, BP = BN + 8;
    const float* B   = blockIdx.z ? B2 : B1;
    const float* bia = blockIdx.z ? bias2 : bias1;
    float*       C   = blockIdx.z ? C2 : C1;
    const int M = NN_, Kt = DIM;

    __shared__ __half As[2][128][AP];
    __shared__ __half Bs[2][BK][BP];

    const int tid  = threadIdx.x;
    const int lane = tid & 31;
    const int warp = tid >> 5;
    const int wR   = (warp & 1) * 64;
    const int wC   = (warp >> 1) * 24;
    const int col0 = blockIdx.x * BN;
    const int lr   = lane >> 2;
    const int lc   = lane & 3;
    const int ph   = lane >> 3;
    const int rr   = lane & 7;

    const int arow = rr + (ph & 1) * 8;
    const int acol = (ph >> 1) * 8;
    const int tkrow = rr + (ph & 1) * 8;
    const int tncol = (ph >> 1) * 8;

    const int ar = tid >> 1;
    const int ac = (tid & 1) * 8;
    int kb0 = tid / 24, nb0 = (tid % 24) * 4;
    bool b1v = (tid < 128);
    int id1 = tid + 256;
    int kb1 = id1 / 24, nb1 = (id1 % 24) * 4;

    const float4 f4z = make_float4(0.f, 0.f, 0.f, 0.f);
    float4 fa0, fa1, fb0, fb1;

    float acc[4][NT][4];
#pragma unroll
    for (int i = 0; i < 4; i++)
#pragma unroll
        for (int j = 0; j < NT; j++)
#pragma unroll
            for (int c = 0; c < 4; c++) acc[i][j][c] = 0.f;

    auto fetch = [&](int k0g) {
        const float* ap = Aht + (long)ar * DIM + k0g + ac;
        fa0 = (ar < M) ? *(const float4*)ap : f4z;
        fa1 = (ar < M) ? *(const float4*)(ap + 4) : f4z;
        fb0 = *(const float4*)(B + (long)(k0g + kb0) * DIM + col0 + nb0);
        if (b1v) fb1 = *(const float4*)(B + (long)(k0g + kb1) * DIM + col0 + nb1);
    };
    auto stage = [&](int buf) {
        uint4 qa;
        qa.x = pack_h2(fa0.x, fa0.y); qa.y = pack_h2(fa0.z, fa0.w);
        qa.z = pack_h2(fa1.x, fa1.y); qa.w = pack_h2(fa1.z, fa1.w);
        *(uint4*)&As[buf][ar][ac] = qa;
        uint2 qb0;
        qb0.x = pack_h2(fb0.x, fb0.y); qb0.y = pack_h2(fb0.z, fb0.w);
        *(uint2*)&Bs[buf][kb0][nb0] = qb0;
        if (b1v) {
            uint2 qb1;
            qb1.x = pack_h2(fb1.x, fb1.y); qb1.y = pack_h2(fb1.z, fb1.w);
            *(uint2*)&Bs[buf][kb1][nb1] = qb1;
        }
    };

    fetch(0);
    stage(0);
    __syncthreads();

    const int KT = Kt / BK;
    for (int kt = 0; kt < KT; kt++) {
        const int cur = kt & 1;
        const bool hn = (kt + 1 < KT);
        if (hn) fetch((kt + 1) * BK);

        u32 af[4][4], bf[NT][2];
#pragma unroll
        for (int mt = 0; mt < 4; mt++)
            ldsm_x4(af[mt][0], af[mt][1], af[mt][2], af[mt][3],
                    s2u(&As[cur][wR + mt * 16 + arow][acol]));
        ldsm_x4t(bf[0][0], bf[0][1], bf[1][0], bf[1][1],
                 s2u(&Bs[cur][tkrow][wC + tncol]));
        ldsm_x2t(bf[2][0], bf[2][1], s2u(&Bs[cur][tkrow][wC + 16]));
#pragma unroll
        for (int mt = 0; mt < 4; mt++)
#pragma unroll
            for (int nt = 0; nt < NT; nt++)
                mma_f16(acc[mt][nt][0], acc[mt][nt][1], acc[mt][nt][2], acc[mt][nt][3],
                        af[mt][0], af[mt][1], af[mt][2], af[mt][3],
                        bf[nt][0], bf[nt][1]);

        if (hn) stage(cur ^ 1);
        __syncthreads();
    }

#pragma unroll
    for (int nt = 0; nt < NT; nt++) {
        int gn = col0 + wC + nt * 8 + 2 * lc;
        float b0 = bia[gn], b1 = bia[gn + 1];
#pragma unroll
        for (int mt = 0; mt < 4; mt++) {
            int gm0 = wR + mt * 16 + lr;
#pragma unroll
            for (int h = 0; h < 2; h++) {
                int gm = gm0 + h * 8;
                if (gm >= M) continue;
                *(float2*)(C + (long)gm * DIM + gn) =
                    make_float2(acc[mt][nt][2 * h] + b0, acc[mt][nt][2 * h + 1] + b1);
            }
        }
    }
}

// ---------------- flash attention (fp16, cp.async K/V, online softmax) ----------------
#define FQ_P 104
#define FK_P 104
#define FV_P 104
#define FP_P 72
#define FQ_OFF 0
#define FK_OFF 13312
#define FV_OFF 26624
#define FP_OFF 39936
#define FLASH_SMEM ((39936 + 128 * 72) * 2)

__global__ __launch_bounds__(256)
void flash_kernel(const __half* __restrict__ Q, const __half* __restrict__ K,
                  const __half* __restrict__ V, __half* __restrict__ O, float scale)
{
    extern __shared__ __half smh[];
    __half* Qs = smh + FQ_OFF;
    __half* Ks = smh + FK_OFF;
    __half* Vs = smh + FV_OFF;
    __half* Ps = smh + FP_OFF;

    const int tid  = threadIdx.x;
    const int lane = tid & 31;
    const int warp = tid >> 5;
    const int lr   = lane >> 2;
    const int lc   = lane & 3;
    const int ph   = lane >> 3;
    const int rr   = lane & 7;
    const int wm   = warp * 16;
    const int mt0  = blockIdx.x * 128;
    const int head = blockIdx.y;

    const int arow = rr + (ph & 1) * 8;
    const int acol = (ph >> 1) * 8;
    const int brow = rr + (ph >> 1) * 8;
    const int bcol = (ph & 1) * 8;
    const int tkrow = rr + (ph & 1) * 8;
    const int tncol = (ph >> 1) * 8;

    const __half* Qb = Q + (long)mt0 * DIM + head * DK;
    const __half* Kb = K + head * DK;
    const __half* Vb = V + head * DK;

#pragma unroll
    for (int it = 0; it < 6; it++) {
        int id  = tid + it * 256;
        int row = id / 12;
        int c8  = (id % 12) * 8;
        *(uint4*)&Qs[row * FQ_P + c8] = *(const uint4*)(Qb + (long)row * DIM + c8);
    }

    auto issueKV = [&](int t, int buf) {
#pragma unroll
        for (int it = 0; it < 3; it++) {
            int id  = tid + it * 256;
            int row = id / 12;
            int c8  = (id % 12) * 8;
            cp16(s2u(&Ks[(buf * 64 + row) * FK_P + c8]),
                 Kb + (long)(t * 64 + row) * DIM + c8);
            cp16(s2u(&Vs[(buf * 64 + row) * FV_P + c8]),
                 Vb + (long)(t * 64 + row) * DIM + c8);
        }
    };

    float oacc[12][4];
#pragma unroll
    for (int i = 0; i < 12; i++)
#pragma unroll
        for (int c = 0; c < 4; c++) oacc[i][c] = 0.f;
    float mrow0 = -1e30f, mrow1 = -1e30f, lrow0 = 0.f, lrow1 = 0.f;

    issueKV(0, 0);
    CP_COMMIT();

    const int NIT = TT / 64;
    for (int t = 0; t < NIT; t++) {
        const int cur = t & 1;
        const bool hn = (t + 1 < NIT);
        if (hn) {
            issueKV(t + 1, cur ^ 1);
            CP_COMMIT();
            CP_WAIT(1);
        } else {
            CP_WAIT(0);
        }
        __syncthreads();

        float sacc[8][4];
#pragma unroll
        for (int nt = 0; nt < 8; nt++)
#pragma unroll
            for (int c = 0; c < 4; c++) sacc[nt][c] = 0.f;

#pragma unroll
        for (int ks = 0; ks < 6; ks++) {
            const int k0 = ks * 16;
            u32 a0, a1, a2, a3;
            ldsm_x4(a0, a1, a2, a3, s2u(&Qs[(wm + arow) * FQ_P + k0 + acol]));
            u32 bf[8][2];
#pragma unroll
            for (int p = 0; p < 4; p++)
                ldsm_x4(bf[2 * p][0], bf[2 * p][1], bf[2 * p + 1][0], bf[2 * p + 1][1],
                        s2u(&Ks[(cur * 64 + p * 16 + brow) * FK_P + k0 + bcol]));
#pragma unroll
            for (int nt = 0; nt < 8; nt++)
                mma_f16(sacc[nt][0], sacc[nt][1], sacc[nt][2], sacc[nt][3],
                        a0, a1, a2, a3, bf[nt][0], bf[nt][1]);
        }

        float rm0 = -1e30f, rm1 = -1e30f;
#pragma unroll
        for (int nt = 0; nt < 8; nt++) {
            rm0 = fmaxf(rm0, fmaxf(sacc[nt][0], sacc[nt][1]));
            rm1 = fmaxf(rm1, fmaxf(sacc[nt][2], sacc[nt][3]));
        }
        rm0 *= scale; rm1 *= scale;
#pragma unroll
        for (int o = 1; o <= 2; o <<= 1) {
            rm0 = fmaxf(rm0, __shfl_xor_sync(0xffffffffu, rm0, o));
            rm1 = fmaxf(rm1, __shfl_xor_sync(0xffffffffu, rm1, o));
        }
        float mn0 = fmaxf(mrow0, rm0);
        float mn1 = fmaxf(mrow1, rm1);
        float al0 = __expf(mrow0 - mn0);
        float al1 = __expf(mrow1 - mn1);
        float sum0 = 0.f, sum1 = 0.f;
#pragma unroll
        for (int nt = 0; nt < 8; nt++) {
            float p0 = __expf(sacc[nt][0] * scale - mn0);
            float p1 = __expf(sacc[nt][1] * scale - mn0);
            float p2 = __expf(sacc[nt][2] * scale - mn1);
            float p3 = __expf(sacc[nt][3] * scale - mn1);
            sum0 += p0 + p1; sum1 += p2 + p3;
            *(u32*)&Ps[(wm + lr) * FP_P + nt * 8 + 2 * lc]     = pack_h2(p0, p1);
            *(u32*)&Ps[(wm + lr + 8) * FP_P + nt * 8 + 2 * lc] = pack_h2(p2, p3);
        }
#pragma unroll
        for (int o = 1; o <= 2; o <<= 1) {
            sum0 += __shfl_xor_sync(0xffffffffu, sum0, o);
            sum1 += __shfl_xor_sync(0xffffffffu, sum1, o);
        }
        lrow0 = lrow0 * al0 + sum0;
        lrow1 = lrow1 * al1 + sum1;
        mrow0 = mn0; mrow1 = mn1;
#pragma unroll
        for (int nt = 0; nt < 12; nt++) {
            oacc[nt][0] *= al0; oacc[nt][1] *= al0;
            oacc[nt][2] *= al1; oacc[nt][3] *= al1;
        }
        __syncwarp();

#pragma unroll
        for (int ksv = 0; ksv < 4; ksv++) {
            const int k0 = ksv * 16;
            u32 a0, a1, a2, a3;
            ldsm_x4(a0, a1, a2, a3, s2u(&Ps[(wm + arow) * FP_P + k0 + acol]));
            u32 bf[12][2];
#pragma unroll
            for (int p = 0; p < 6; p++)
                ldsm_x4t(bf[2 * p][0], bf[2 * p][1], bf[2 * p + 1][0], bf[2 * p + 1][1],
                         s2u(&Vs[(cur * 64 + k0 + tkrow) * FV_P + p * 16 + tncol]));
#pragma unroll
            for (int nt = 0; nt < 12; nt++)
                mma_f16(oacc[nt][0], oacc[nt][1], oacc[nt][2], oacc[nt][3],
                        a0, a1, a2, a3, bf[nt][0], bf[nt][1]);
        }
        __syncthreads();
    }

    float inv0 = 1.f / lrow0;
    float inv1 = 1.f / lrow1;
    int r0 = mt0 + wm + lr;
    int r1 = r0 + 8;
#pragma unroll
    for (int nt = 0; nt < 12; nt++) {
        int col = head * DK + nt * 8 + 2 * lc;
        *(u32*)(O + (long)r0 * DIM + col) = pack_h2(oacc[nt][0] * inv0, oacc[nt][1] * inv0);
        *(u32*)(O + (long)r1 * DIM + col) = pack_h2(oacc[nt][2] * inv1, oacc[nt][3] * inv1);
    }
}

// ---------------- span max pooling ----------------
__global__ void pool_kernel(const float* __restrict__ emb, const int* __restrict__ spans,
                            float* __restrict__ htb)
{
    int node = blockIdx.x;
    int bag  = node / NPD;
    int s0 = spans[node * 2 + 0];
    int s1 = spans[node * 2 + 1];
    const float* base = emb + (long)bag * SEQ * DIM;
    for (int d = threadIdx.x; d < DIM; d += blockDim.x) {
        float m = -3.4e38f;
        for (int p = s0; p <= s1; p++)
            m = fmaxf(m, base[(long)p * DIM + d]);
        htb[(long)node * DIM + d] = m;
    }
}

// ---------------- x = LN(x + o) * g + b  -> fp32 x and fp16 xh ----------------
__global__ void add_ln_kernel(float* __restrict__ x, __half* __restrict__ xh,
                              const float* __restrict__ o,
                              const float* __restrict__ g, const float* __restrict__ b)
{
    long base = (long)blockIdx.x * DIM;
    float* xr = x + base;
    __half* xhr = xh + base;
    const float* orr = o + base;
    __shared__ float sh[32];
    float v[3];
    float s = 0.f, s2 = 0.f;
#pragma unroll
    for (int i = 0; i < 3; i++) {
        int d = threadIdx.x + i * 256;
        float t = xr[d] + orr[d];
        v[i] = t; s += t; s2 += t * t;
    }
    s  = blk_reduce(s,  sh, false);
    s2 = blk_reduce(s2, sh, false);
    float mean = s * (1.f / DIM);
    float var  = s2 * (1.f / DIM) - mean * mean;
    float inv  = rsqrtf(var + 1e-5f);
#pragma unroll
    for (int i = 0; i < 3; i++) {
        int d = threadIdx.x + i * 256;
        float r = (v[i] - mean) * inv * g[d] + b[d];
        xr[d] = r;
        xhr[d] = __float2half_rn(r);
    }
}

// ---------------- final: gather (h,t) cells, LN, predictor ----------------
__global__ void final_kernel(const float* __restrict__ x, const float* __restrict__ ng,
                             const float* __restrict__ nb, const float* __restrict__ Wp,
                             const float* __restrict__ bp, float* __restrict__ ht)
{
    int bag = blockIdx.x;
    long r = (long)(bag * NPD) * NN_ + (bag * NPD + 1);
    const float* row = x + r * DIM;
    __shared__ float sh[DIM];
    __shared__ float red[32];
    float s = 0.f, s2 = 0.f;
    for (int d = threadIdx.x; d < DIM; d += blockDim.x) {
        float t = row[d];
        sh[d] = t; s += t; s2 += t * t;
    }
    s  = blk_reduce(s,  red, false);
    s2 = blk_reduce(s2, red, false);
    float mean = s * (1.f / DIM);
    float inv  = rsqrtf(s2 * (1.f / DIM) - mean * mean + 1e-5f);
    __syncthreads();
    for (int d = threadIdx.x; d < DIM; d += blockDim.x)
        sh[d] = (sh[d] - mean) * inv * ng[d] + nb[d];
    __syncthreads();
    for (int n = threadIdx.x; n < NREL; n += blockDim.x) {
        float acc = bp[n];
        for (int k = 0; k < DIM; k++)
            acc = fmaf(sh[k], Wp[(long)k * NREL + n], acc);
        ht[bag * NREL + n] = acc;
    }
}

// ---------------- output assembly: bag max + layout ----------------
__global__ void writeout_kernel(const float* __restrict__ ht, float* __restrict__ out,
                                int out_size)
{
    int n = threadIdx.x;
    if (n >= NREL) return;
    float m = -3.4e38f;
    for (int b = 0; b < BAG; b++) m = fmaxf(m, ht[b * NREL + n]);
    if (out_size >= NREL * (BAG + 1)) {
        out[n] = m;
        for (int b = 0; b < BAG; b++) out[NREL + b * NREL + n] = ht[b * NREL + n];
    } else if (out_size == NREL) {
        out[n] = m;
    } else {
        for (int b = 0; b < BAG; b++) out[b * NREL + n] = ht[b * NREL + n];
    }
}

// ---------------- host ----------------
template <typename T>
static inline void* symv(T& s) {
    void* p = nullptr;
    cudaGetSymbolAddress(&p, s);
    return p;
}

extern "C" void kernel_launch(void* const* d_in, const int* in_sizes, int n_in,
                              void* d_out, int out_size)
{
    const float* emb   = (const float*)d_in[0];
    const int*   spans = (const int*)  d_in[1];
    const float* Wu = (const float*)d_in[2];  const float* bu = (const float*)d_in[3];
    const float* Wv = (const float*)d_in[4];  const float* bv = (const float*)d_in[5];
    const float* Wl = (const float*)d_in[6];  const float* bl = (const float*)d_in[7];
    const float* Wq = (const float*)d_in[8];  const float* bq = (const float*)d_in[9];
    const float* Wk = (const float*)d_in[10]; const float* bk = (const float*)d_in[11];
    const float* Wvm= (const float*)d_in[12]; const float* bvm= (const float*)d_in[13];
    const float* Wo = (const float*)d_in[14]; const float* bo = (const float*)d_in[15];
    const float* F1 = (const float*)d_in[16]; const float* f1 = (const float*)d_in[17];
    const float* F2 = (const float*)d_in[18]; const float* f2 = (const float*)d_in[19];
    const float* g1 = (const float*)d_in[20]; const float* be1= (const float*)d_in[21];
    const float* g2 = (const float*)d_in[22]; const float* be2= (const float*)d_in[23];
    const float* ng = (const float*)d_in[24]; const float* nb = (const float*)d_in[25];
    const float* Wp = (const float*)d_in[26]; const float* bp = (const float*)d_in[27];

    float*  htb = (float*) symv(g_htb);
    float*  u   = (float*) symv(g_u);
    float*  v   = (float*) symv(g_v);
    float*  x   = (float*) symv(g_x);
    float*  tmp = (float*) symv(g_tmp);
    float*  ht  = (float*) symv(g_ht);
    __half* xh  = (__half*)symv(g_xh);
    __half* qh  = (__half*)symv(g_qh);
    __half* kh  = (__half*)symv(g_kh);
    __half* vh  = (__half*)symv(g_vh);
    __half* ah  = (__half*)symv(g_ah);
    __half* fh  = (__half*)symv(g_fh);
    __half* wh  = (__half*)symv(g_wh);
    float*  out = (float*)d_out;

    const float scale = 0.102062072615966f;   // 1/sqrt(96)

    cudaFuncSetAttribute(flash_kernel, cudaFuncAttributeMaxDynamicSharedMemorySize,
                         FLASH_SMEM);

    // 0) weights -> fp16 (once per call)
    f2h_kernel<<<DIM * DIM / 2048, 256>>>(Wl, wh + OWL, DIM * DIM);
    f2h_kernel<<<NLAYER * DIM * DIM / 2048, 256>>>(Wq, wh + OWQ, NLAYER * DIM * DIM);
    f2h_kernel<<<NLAYER * DIM * DIM / 2048, 256>>>(Wk, wh + OWK, NLAYER * DIM * DIM);
    f2h_kernel<<<NLAYER * DIM * DIM / 2048, 256>>>(Wvm, wh + OWV, NLAYER * DIM * DIM);
    f2h_kernel<<<NLAYER * DIM * DIM / 2048, 256>>>(Wo, wh + OWO, NLAYER * DIM * DIM);
    f2h_kernel<<<NLAYER * DIM * DFF / 2048, 256>>>(F1, wh + OF1, NLAYER * DIM * DFF);
    f2h_kernel<<<NLAYER * DFF * DIM / 2048, 256>>>(F2, wh + OF2, NLAYER * DFF * DIM);

    const dim3 g1z(8, 36, 1);    // N=768 via BN=96, M=2304, BM=64 -> 288 CTAs
    const dim3 g3z(8, 36, 3);    // QKV merged -> 864 CTAs
    const dim3 gF1(8, 36, 1);    // N=1024 via BN=128 -> 288 CTAs

    // 1) span max pooling -> htb [48,768]
    pool_kernel<<<NN_, 256>>>(emb, spans, htb);

    // 2) u/v projections (merged, M=48)
    gemm_uv<<<dim3(8, 1, 2), 256>>>(htb, Wu, bu, u, Wv, bv, v);

    // 3) x = relu(relu(u_i + v_j) @ Wl + bl)   (pair fused into A-stage)
    gemm_h<3, true, true, true, true><<<g1z, 256>>>(
        nullptr, u, v, wh + OWL, bl, x, xh,
        wh + OWL, bl, xh, wh + OWL, bl, xh, DIM, DIM, DIM, DIM);

    // 4) MatTransformer layers
    for (int l = 0; l < NLAYER; l++) {
        const __half* Wqh = wh + OWQ + (size_t)l * DIM * DIM;
        const __half* Wkh = wh + OWK + (size_t)l * DIM * DIM;
        const __half* Wvh = wh + OWV + (size_t)l * DIM * DIM;
        const __half* Woh = wh + OWO + (size_t)l * DIM * DIM;
        const __half* F1h = wh + OF1 + (size_t)l * DIM * DFF;
        const __half* F2h = wh + OF2 + (size_t)l * DFF * DIM;
        const float* bq_l = bq + (size_t)l * DIM;
        const float* bk_l = bk + (size_t)l * DIM;
        const float* bv_l = bvm+ (size_t)l * DIM;
        const float* bo_l = bo + (size_t)l * DIM;
        const float* f1_l = f1 + (size_t)l * DFF;
        const float* f2_l = f2 + (size_t)l * DIM;
        const float* g1_l = g1 + (size_t)l * DIM;  const float* be1_l = be1 + (size_t)l * DIM;
        const float* g2_l = g2 + (size_t)l * DIM;  const float* be2_l = be2 + (size_t)l * DIM;

        // QKV projections: ONE launch, z selects W/b/out
        gemm_h<3, false, false, false, true><<<g3z, 256>>>(
            xh, nullptr, nullptr,
            Wqh, bq_l, nullptr, qh,
            Wkh, bk_l, kh,
            Wvh, bv_l, vh, DIM, DIM, DIM, DIM);

        // fused attention (half in, half out)
        flash_kernel<<<dim3(TT / 128, NHEAD), 256, FLASH_SMEM>>>(qh, kh, vh, ah, scale);

        // output projection + residual LN
        gemm_h<3, false, false, true, false><<<g1z, 256>>>(
            ah, nullptr, nullptr, Woh, bo_l, tmp, nullptr,
            Woh, bo_l, nullptr, Woh, bo_l, nullptr, DIM, DIM, DIM, DIM);
        add_ln_kernel<<<TT, 256>>>(x, xh, tmp, g1_l, be1_l);

        // FFN + residual LN
        gemm_h<4, false, true, false, true><<<gF1, 256>>>(
            xh, nullptr, nullptr, F1h, f1_l, nullptr, fh,
            F1h, f1_l, fh, F1h, f1_l, fh, DIM, DIM, DFF, DFF);
        gemm_h<3, false, false, true, false><<<g1z, 256>>>(
            fh, nullptr, nullptr, F2h, f2_l, tmp, nullptr,
            F2h, f2_l, nullptr, F2h, f2_l, nullptr, DFF, DFF, DIM, DIM);
        add_ln_kernel<<<TT, 256>>>(x, xh, tmp, g2_l, be2_l);
    }

    // 5) final gather + LN + predictor + bag max
    final_kernel<<<BAG, 256>>>(x, ng, nb, Wp, bp, ht);
    writeout_kernel<<<1, 128>>>(ht, out, out_size);
}

// round 16
// speedup vs baseline: 2.6126x; 1.0367x over previous
#include <cuda_runtime.h>
#include <cuda_fp16.h>
#include <cstdint>

// ---------------- problem constants ----------------
#define BAG  8
#define SEQ  512
#define DIM  768
#define NPD  6
#define NN_  48          // N nodes
#define TT   2304        // T = N*N
#define NHEAD 8
#define DK   96
#define DFF  1024
#define NLAYER 4
#define NREL 97

typedef uint32_t u32;

// ---------------- device scratch (no allocations allowed) ----------------
__device__ float  g_htb [NN_ * DIM];
__device__ float  g_u   [NN_ * DIM];
__device__ float  g_v   [NN_ * DIM];
__device__ float  g_x   [TT * DIM];
__device__ float  g_tmp [TT * DIM];
__device__ float  g_ht  [BAG * NREL];
__device__ __half g_xh  [TT * DIM];
__device__ __half g_qh  [TT * DIM];
__device__ __half g_kh  [TT * DIM];
__device__ __half g_vh  [TT * DIM];
__device__ __half g_ah  [TT * DIM];
__device__ __half g_fh  [TT * DFF];
// half weights: Wl | Wq | Wk | Wv | Wo | F1 | F2
#define OWL 0
#define OWQ (OWL + DIM*DIM)
#define OWK (OWQ + NLAYER*DIM*DIM)
#define OWV (OWK + NLAYER*DIM*DIM)
#define OWO (OWV + NLAYER*DIM*DIM)
#define OF1 (OWO + NLAYER*DIM*DIM)
#define OF2 (OF1 + NLAYER*DIM*DFF)
#define WH_TOTAL (OF2 + NLAYER*DFF*DIM)
__device__ __half g_wh[WH_TOTAL];

// ---------------- fp16 / ldmatrix / cp.async helpers ----------------
__device__ __forceinline__ u32 pack_h2(float a, float b) {
    __half2 h = __floats2half2_rn(a, b);
    return *(u32*)&h;
}
__device__ __forceinline__ void mma_f16(float& c0, float& c1, float& c2, float& c3,
                                        u32 a0, u32 a1, u32 a2, u32 a3,
                                        u32 b0, u32 b1) {
    asm("mma.sync.aligned.m16n8k16.row.col.f32.f16.f16.f32 "
        "{%0,%1,%2,%3}, {%4,%5,%6,%7}, {%8,%9}, {%0,%1,%2,%3};"
        : "+f"(c0), "+f"(c1), "+f"(c2), "+f"(c3)
        : "r"(a0), "r"(a1), "r"(a2), "r"(a3), "r"(b0), "r"(b1));
}
__device__ __forceinline__ u32 s2u(const void* p) {
    return (u32)__cvta_generic_to_shared(p);
}
__device__ __forceinline__ void ldsm_x4(u32& r0, u32& r1, u32& r2, u32& r3, u32 addr) {
    asm volatile("ldmatrix.sync.aligned.m8n8.x4.shared.b16 {%0,%1,%2,%3}, [%4];"
                 : "=r"(r0), "=r"(r1), "=r"(r2), "=r"(r3) : "r"(addr));
}
__device__ __forceinline__ void ldsm_x4t(u32& r0, u32& r1, u32& r2, u32& r3, u32 addr) {
    asm volatile("ldmatrix.sync.aligned.m8n8.x4.trans.shared.b16 {%0,%1,%2,%3}, [%4];"
                 : "=r"(r0), "=r"(r1), "=r"(r2), "=r"(r3) : "r"(addr));
}
__device__ __forceinline__ void ldsm_x2t(u32& r0, u32& r1, u32 addr) {
    asm volatile("ldmatrix.sync.aligned.m8n8.x2.trans.shared.b16 {%0,%1}, [%2];"
                 : "=r"(r0), "=r"(r1) : "r"(addr));
}
__device__ __forceinline__ void cp16(u32 dst, const void* src) {
    asm volatile("cp.async.cg.shared.global [%0], [%1], 16;" :: "r"(dst), "l"(src));
}
#define CP_COMMIT() asm volatile("cp.async.commit_group;")
#define CP_WAIT(n)  asm volatile("cp.async.wait_group %0;" :: "n"(n))

// ---------------- block reduction helper ----------------
__device__ __forceinline__ float blk_reduce(float val, float* sh, bool do_max) {
    const unsigned mask = 0xffffffffu;
#pragma unroll
    for (int o = 16; o > 0; o >>= 1) {
        float other = __shfl_xor_sync(mask, val, o);
        val = do_max ? fmaxf(val, other) : (val + other);
    }
    int lane = threadIdx.x & 31, w = threadIdx.x >> 5;
    __syncthreads();
    if (lane == 0) sh[w] = val;
    __syncthreads();
    int nw = (blockDim.x + 31) >> 5;
    if (w == 0) {
        val = (lane < nw) ? sh[lane] : (do_max ? -3.4e38f : 0.f);
#pragma unroll
        for (int o = 16; o > 0; o >>= 1) {
            float other = __shfl_xor_sync(mask, val, o);
            val = do_max ? fmaxf(val, other) : (val + other);
        }
        if (lane == 0) sh[0] = val;
    }
    __syncthreads();
    return sh[0];
}

// ---------------- ALL weights fp32 -> fp16 in ONE launch ----------------
__global__ void f2h_all(const float* s0, __half* d0, int n0,
                        const float* s1, __half* d1, int n1,
                        const float* s2, __half* d2, int n2,
                        const float* s3, __half* d3, int n3,
                        const float* s4, __half* d4, int n4,
                        const float* s5, __half* d5, int n5,
                        const float* s6, __half* d6, int n6)
{
    const float* src; __half* dst; int n;
    switch (blockIdx.y) {
        case 0: src = s0; dst = d0; n = n0; break;
        case 1: src = s1; dst = d1; n = n1; break;
        case 2: src = s2; dst = d2; n = n2; break;
        case 3: src = s3; dst = d3; n = n3; break;
        case 4: src = s4; dst = d4; n = n4; break;
        case 5: src = s5; dst = d5; n = n5; break;
        default: src = s6; dst = d6; n = n6; break;
    }
    int i = (blockIdx.x * 256 + threadIdx.x) * 8;
    if (i >= n) return;
    float4 a = *(const float4*)(src + i);
    float4 b = *(const float4*)(src + i + 4);
    uint4 q;
    q.x = pack_h2(a.x, a.y); q.y = pack_h2(a.z, a.w);
    q.z = pack_h2(b.x, b.y); q.w = pack_h2(b.z, b.w);
    *(uint4*)(dst + i) = q;
}

// ======= 64xBN fp16 GEMM, BK=32, 3-stage cp.async pipeline, 2 CTAs/SM =======
// z-batched over up to 3 (B, bias, Ch) triples.
// C = A @ B (+bias)(ReLU).  A: half [M][lda] (or PAIR: relu(u_i+v_j) on the fly)
// M % 64 == 0, N % BN == 0, K % 32 == 0, K/32 >= 2.
template<int NT, bool PAIR, bool RELU, bool OUTF, bool OUTH>
__global__ __launch_bounds__(256, 2)
void gemm_h(const __half* __restrict__ A, const float* __restrict__ U,
            const float* __restrict__ Vv,
            const __half* B0, const float* b0, float* __restrict__ Cf, __half* Ch0,
            const __half* B1, const float* b1, __half* Ch1,
            const __half* B2, const float* b2, __half* Ch2,
            int K, int lda, int ldb, int ldc)
{
    constexpr int BM = 64;
    constexpr int BN = 32 * NT;
    constexpr int BK = 32;
    constexpr int AP = 40;            // 80B row (5x16B, odd) -> conflict-free ldsm
    constexpr int BP = BN + 8;        // 104/136 halfs -> 13/17 x16B, odd
    constexpr int BCH = (BK * BN) / 8;  // B 16B-chunks: 384 (NT=3) / 512 (NT=4)

    const __half* B    = B0;
    const float*  bias = b0;
    __half*       Ch   = Ch0;
    if (blockIdx.z == 1) { B = B1; bias = b1; Ch = Ch1; }
    else if (blockIdx.z == 2) { B = B2; bias = b2; Ch = Ch2; }

    __shared__ __half As[3][BM][AP];
    __shared__ __half Bs[3][BK][BP];

    const int tid  = threadIdx.x;
    const int lane = tid & 31;
    const int warp = tid >> 5;
    const int wR   = (warp & 1) * 32;
    const int wC   = (warp >> 1) * (8 * NT);
    const int row0 = blockIdx.y * BM;
    const int col0 = blockIdx.x * BN;
    const int lr   = lane >> 2;
    const int lc   = lane & 3;
    const int ph   = lane >> 3;
    const int rr   = lane & 7;

    const int arow = rr + (ph & 1) * 8;
    const int acol = (ph >> 1) * 8;
    const int tkrow = rr + (ph & 1) * 8;
    const int tncol = (ph >> 1) * 8;

    // A stage map: 256 16B chunks (1/thread)
    const int sr0 = tid >> 2;                 // 0..63
    const int sc8 = (tid & 3) * 8;

    float acc[2][NT][4];
#pragma unroll
    for (int i = 0; i < 2; i++)
#pragma unroll
        for (int j = 0; j < NT; j++)
#pragma unroll
            for (int c = 0; c < 4; c++) acc[i][j][c] = 0.f;

    const int KT = K / BK;

    auto issueB = [&](int kb, int buf) {
#pragma unroll
        for (int i = 0; i < (BCH + 255) / 256; i++) {
            int t = tid + i * 256;
            if ((BCH & 255) && t >= BCH) break;
            int krow = t / (BN / 8), c8 = (t % (BN / 8)) * 8;
            cp16(s2u(&Bs[buf][krow][c8]), B + (long)(kb + krow) * ldb + col0 + c8);
        }
    };
    auto issueA = [&](int kb, int buf) {
        cp16(s2u(&As[buf][sr0][sc8]), A + (long)(row0 + sr0) * lda + kb + sc8);
    };
    auto stagePA = [&](int kb, int buf) {
        int m = row0 + sr0;
        int ii = m / NN_, jj = m % NN_;
        const float* up = U + (long)ii * DIM + kb + sc8;
        const float* vp = Vv + (long)jj * DIM + kb + sc8;
        float4 u0 = *(const float4*)up, u1 = *(const float4*)(up + 4);
        float4 v0 = *(const float4*)vp, v1 = *(const float4*)(vp + 4);
        uint4 q;
        q.x = pack_h2(fmaxf(u0.x + v0.x, 0.f), fmaxf(u0.y + v0.y, 0.f));
        q.y = pack_h2(fmaxf(u0.z + v0.z, 0.f), fmaxf(u0.w + v0.w, 0.f));
        q.z = pack_h2(fmaxf(u1.x + v1.x, 0.f), fmaxf(u1.y + v1.y, 0.f));
        q.w = pack_h2(fmaxf(u1.z + v1.z, 0.f), fmaxf(u1.w + v1.w, 0.f));
        *(uint4*)&As[buf][sr0][sc8] = q;
    };

    // prologue: stage tiles 0 and 1
    if (PAIR) stagePA(0, 0); else issueA(0, 0);
    issueB(0, 0);
    CP_COMMIT();
    if (PAIR) stagePA(BK, 1); else issueA(BK, 1);
    issueB(BK, 1);
    CP_COMMIT();

    for (int kt = 0; kt < KT; kt++) {
        const int cur = kt % 3;
        if (kt + 1 < KT) { CP_WAIT(1); } else { CP_WAIT(0); }
        __syncthreads();

#pragma unroll
        for (int ks = 0; ks < 2; ks++) {
            const int k0 = ks * 16;
            u32 af[2][4], bf[NT][2];
#pragma unroll
            for (int mt = 0; mt < 2; mt++)
                ldsm_x4(af[mt][0], af[mt][1], af[mt][2], af[mt][3],
                        s2u(&As[cur][wR + mt * 16 + arow][k0 + acol]));
#pragma unroll
            for (int p = 0; p < NT / 2; p++)
                ldsm_x4t(bf[2 * p][0], bf[2 * p][1], bf[2 * p + 1][0], bf[2 * p + 1][1],
                         s2u(&Bs[cur][k0 + tkrow][wC + p * 16 + tncol]));
            if (NT & 1)
                ldsm_x2t(bf[NT - 1][0], bf[NT - 1][1],
                         s2u(&Bs[cur][k0 + tkrow][wC + (NT - 1) * 8]));
#pragma unroll
            for (int mt = 0; mt < 2; mt++)
#pragma unroll
                for (int nt = 0; nt < NT; nt++)
                    mma_f16(acc[mt][nt][0], acc[mt][nt][1], acc[mt][nt][2], acc[mt][nt][3],
                            af[mt][0], af[mt][1], af[mt][2], af[mt][3],
                            bf[nt][0], bf[nt][1]);
        }
        __syncthreads();   // all warps done with buffer (kt-1)%3 == (kt+2)%3

        const int nx = kt + 2;
        if (nx < KT) {
            const int nb = nx % 3;
            if (PAIR) stagePA(nx * BK, nb); else issueA(nx * BK, nb);
            issueB(nx * BK, nb);
            CP_COMMIT();
        }
    }

    // ---- epilogue ----
#pragma unroll
    for (int nt = 0; nt < NT; nt++) {
        int gn = col0 + wC + nt * 8 + 2 * lc;
        float b0v = bias[gn], b1v = bias[gn + 1];
#pragma unroll
        for (int mt = 0; mt < 2; mt++) {
            int gm0 = row0 + wR + mt * 16 + lr;
#pragma unroll
            for (int h = 0; h < 2; h++) {
                int gm = gm0 + h * 8;
                float v0 = acc[mt][nt][2 * h]     + b0v;
                float v1 = acc[mt][nt][2 * h + 1] + b1v;
                if (RELU) { v0 = fmaxf(v0, 0.f); v1 = fmaxf(v1, 0.f); }
                if (OUTF) *(float2*)(Cf + (long)gm * ldc + gn) = make_float2(v0, v1);
                if (OUTH) *(u32*)(Ch + (long)gm * ldc + gn) = pack_h2(v0, v1);
            }
        }
    }
}

// ---------------- small-M GEMM (u/v projections, merged over z) ----------------
__global__ __launch_bounds__(256)
void gemm_uv(const float* __restrict__ Aht, const float* __restrict__ B1,
             const float* __restrict__ bias1, float* __restrict__ C1,
             const float* __restrict__ B2, const float* __restrict__ bias2,
             float* __restrict__ C2)
{
    constexpr int NT = 3, BN = 96, BK = 16, AP = 24, BP = BN + 8;
    const float* B   = blockIdx.z ? B2 : B1;
    const float* bia = blockIdx.z ? bias2 : bias1;
    float*       C   = blockIdx.z ? C2 : C1;
    const int M = NN_, Kt = DIM;

    __shared__ __half As[2][128][AP];
    __shared__ __half Bs[2][BK][BP];

    const int tid  = threadIdx.x;
    const int lane = tid & 31;
    const int warp = tid >> 5;
    const int wR   = (warp & 1) * 64;
    const int wC   = (warp >> 1) * 24;
    const int col0 = blockIdx.x * BN;
    const int lr   = lane >> 2;
    const int lc   = lane & 3;
    const int ph   = lane >> 3;
    const int rr   = lane & 7;

    const int arow = rr + (ph & 1) * 8;
    const int acol = (ph >> 1) * 8;
    const int tkrow = rr + (ph & 1) * 8;
    const int tncol = (ph >> 1) * 8;

    const int ar = tid >> 1;
    const int ac = (tid & 1) * 8;
    int kb0 = tid / 24, nb0 = (tid % 24) * 4;
    bool b1v = (tid < 128);
    int id1 = tid + 256;
    int kb1 = id1 / 24, nb1 = (id1 % 24) * 4;

    const float4 f4z = make_float4(0.f, 0.f, 0.f, 0.f);
    float4 fa0, fa1, fb0, fb1;

    float acc[4][NT][4];
#pragma unroll
    for (int i = 0; i < 4; i++)
#pragma unroll
        for (int j = 0; j < NT; j++)
#pragma unroll
            for (int c = 0; c < 4; c++) acc[i][j][c] = 0.f;

    auto fetch = [&](int k0g) {
        const float* ap = Aht + (long)ar * DIM + k0g + ac;
        fa0 = (ar < M) ? *(const float4*)ap : f4z;
        fa1 = (ar < M) ? *(const float4*)(ap + 4) : f4z;
        fb0 = *(const float4*)(B + (long)(k0g + kb0) * DIM + col0 + nb0);
        if (b1v) fb1 = *(const float4*)(B + (long)(k0g + kb1) * DIM + col0 + nb1);
    };
    auto stage = [&](int buf) {
        uint4 qa;
        qa.x = pack_h2(fa0.x, fa0.y); qa.y = pack_h2(fa0.z, fa0.w);
        qa.z = pack_h2(fa1.x, fa1.y); qa.w = pack_h2(fa1.z, fa1.w);
        *(uint4*)&As[buf][ar][ac] = qa;
        uint2 qb0;
        qb0.x = pack_h2(fb0.x, fb0.y); qb0.y = pack_h2(fb0.z, fb0.w);
        *(uint2*)&Bs[buf][kb0][nb0] = qb0;
        if (b1v) {
            uint2 qb1;
            qb1.x = pack_h2(fb1.x, fb1.y); qb1.y = pack_h2(fb1.z, fb1.w);
            *(uint2*)&Bs[buf][kb1][nb1] = qb1;
        }
    };

    fetch(0);
    stage(0);
    __syncthreads();

    const int KT = Kt / BK;
    for (int kt = 0; kt < KT; kt++) {
        const int cur = kt & 1;
        const bool hn = (kt + 1 < KT);
        if (hn) fetch((kt + 1) * BK);

        u32 af[4][4], bf[NT][2];
#pragma unroll
        for (int mt = 0; mt < 4; mt++)
            ldsm_x4(af[mt][0], af[mt][1], af[mt][2], af[mt][3],
                    s2u(&As[cur][wR + mt * 16 + arow][acol]));
        ldsm_x4t(bf[0][0], bf[0][1], bf[1][0], bf[1][1],
                 s2u(&Bs[cur][tkrow][wC + tncol]));
        ldsm_x2t(bf[2][0], bf[2][1], s2u(&Bs[cur][tkrow][wC + 16]));
#pragma unroll
        for (int mt = 0; mt < 4; mt++)
#pragma unroll
            for (int nt = 0; nt < NT; nt++)
                mma_f16(acc[mt][nt][0], acc[mt][nt][1], acc[mt][nt][2], acc[mt][nt][3],
                        af[mt][0], af[mt][1], af[mt][2], af[mt][3],
                        bf[nt][0], bf[nt][1]);

        if (hn) stage(cur ^ 1);
        __syncthreads();
    }

#pragma unroll
    for (int nt = 0; nt < NT; nt++) {
        int gn = col0 + wC + nt * 8 + 2 * lc;
        float b0 = bia[gn], b1 = bia[gn + 1];
#pragma unroll
        for (int mt = 0; mt < 4; mt++) {
            int gm0 = wR + mt * 16 + lr;
#pragma unroll
            for (int h = 0; h < 2; h++) {
                int gm = gm0 + h * 8;
                if (gm >= M) continue;
                *(float2*)(C + (long)gm * DIM + gn) =
                    make_float2(acc[mt][nt][2 * h] + b0, acc[mt][nt][2 * h + 1] + b1);
            }
        }
    }
}

// ---------------- flash attention (fp16, cp.async K/V, P in registers) ----------------
// Smem: Qs[128][104] | Ks[2][64][104] | Vs[2][64][104]  = 79872 bytes -> 2 CTAs/SM
#define FQ_P 104
#define FK_P 104
#define FV_P 104
#define FQ_OFF 0
#define FK_OFF 13312
#define FV_OFF 26624
#define FLASH_SMEM ((26624 + 2 * 64 * FV_P) * 2)

__global__ __launch_bounds__(256, 2)
void flash_kernel(const __half* __restrict__ Q, const __half* __restrict__ K,
                  const __half* __restrict__ V, __half* __restrict__ O, float scale)
{
    extern __shared__ __half smh[];
    __half* Qs = smh + FQ_OFF;
    __half* Ks = smh + FK_OFF;
    __half* Vs = smh + FV_OFF;

    const int tid  = threadIdx.x;
    const int lane = tid & 31;
    const int warp = tid >> 5;
    const int lr   = lane >> 2;
    const int lc   = lane & 3;
    const int ph   = lane >> 3;
    const int rr   = lane & 7;
    const int wm   = warp * 16;
    const int mt0  = blockIdx.x * 128;
    const int head = blockIdx.y;

    const int arow = rr + (ph & 1) * 8;
    const int acol = (ph >> 1) * 8;
    const int brow = rr + (ph >> 1) * 8;
    const int bcol = (ph & 1) * 8;
    const int tkrow = rr + (ph & 1) * 8;
    const int tncol = (ph >> 1) * 8;

    const __half* Qb = Q + (long)mt0 * DIM + head * DK;
    const __half* Kb = K + head * DK;
    const __half* Vb = V + head * DK;

#pragma unroll
    for (int it = 0; it < 6; it++) {
        int id  = tid + it * 256;
        int row = id / 12;
        int c8  = (id % 12) * 8;
        *(uint4*)&Qs[row * FQ_P + c8] = *(const uint4*)(Qb + (long)row * DIM + c8);
    }

    auto issueKV = [&](int t, int buf) {
#pragma unroll
        for (int it = 0; it < 3; it++) {
            int id  = tid + it * 256;
            int row = id / 12;
            int c8  = (id % 12) * 8;
            cp16(s2u(&Ks[(buf * 64 + row) * FK_P + c8]),
                 Kb + (long)(t * 64 + row) * DIM + c8);
            cp16(s2u(&Vs[(buf * 64 + row) * FV_P + c8]),
                 Vb + (long)(t * 64 + row) * DIM + c8);
        }
    };

    float oacc[12][4];
#pragma unroll
    for (int i = 0; i < 12; i++)
#pragma unroll
        for (int c = 0; c < 4; c++) oacc[i][c] = 0.f;
    float mrow0 = -1e30f, mrow1 = -1e30f, lrow0 = 0.f, lrow1 = 0.f;

    issueKV(0, 0);
    CP_COMMIT();

    const int NIT = TT / 64;
    for (int t = 0; t < NIT; t++) {
        const int cur = t & 1;
        const bool hn = (t + 1 < NIT);
        if (hn) {
            issueKV(t + 1, cur ^ 1);
            CP_COMMIT();
            CP_WAIT(1);
        } else {
            CP_WAIT(0);
        }
        __syncthreads();

        float sacc[8][4];
#pragma unroll
        for (int nt = 0; nt < 8; nt++)
#pragma unroll
            for (int c = 0; c < 4; c++) sacc[nt][c] = 0.f;

#pragma unroll
        for (int ks = 0; ks < 6; ks++) {
            const int k0 = ks * 16;
            u32 a0, a1, a2, a3;
            ldsm_x4(a0, a1, a2, a3, s2u(&Qs[(wm + arow) * FQ_P + k0 + acol]));
            u32 bf[8][2];
#pragma unroll
            for (int p = 0; p < 4; p++)
                ldsm_x4(bf[2 * p][0], bf[2 * p][1], bf[2 * p + 1][0], bf[2 * p + 1][1],
                        s2u(&Ks[(cur * 64 + p * 16 + brow) * FK_P + k0 + bcol]));
#pragma unroll
            for (int nt = 0; nt < 8; nt++)
                mma_f16(sacc[nt][0], sacc[nt][1], sacc[nt][2], sacc[nt][3],
                        a0, a1, a2, a3, bf[nt][0], bf[nt][1]);
        }

        float rm0 = -1e30f, rm1 = -1e30f;
#pragma unroll
        for (int nt = 0; nt < 8; nt++) {
            rm0 = fmaxf(rm0, fmaxf(sacc[nt][0], sacc[nt][1]));
            rm1 = fmaxf(rm1, fmaxf(sacc[nt][2], sacc[nt][3]));
        }
        rm0 *= scale; rm1 *= scale;
#pragma unroll
        for (int o = 1; o <= 2; o <<= 1) {
            rm0 = fmaxf(rm0, __shfl_xor_sync(0xffffffffu, rm0, o));
            rm1 = fmaxf(rm1, __shfl_xor_sync(0xffffffffu, rm1, o));
        }
        float mn0 = fmaxf(mrow0, rm0);
        float mn1 = fmaxf(mrow1, rm1);
        float al0 = __expf(mrow0 - mn0);
        float al1 = __expf(mrow1 - mn1);
        float sum0 = 0.f, sum1 = 0.f;
        u32 pf[8][2];                     // P as A-fragments (C->A layout identity)
#pragma unroll
        for (int nt = 0; nt < 8; nt++) {
            float p0 = __expf(sacc[nt][0] * scale - mn0);
            float p1 = __expf(sacc[nt][1] * scale - mn0);
            float p2 = __expf(sacc[nt][2] * scale - mn1);
            float p3 = __expf(sacc[nt][3] * scale - mn1);
            sum0 += p0 + p1; sum1 += p2 + p3;
            pf[nt][0] = pack_h2(p0, p1);
            pf[nt][1] = pack_h2(p2, p3);
        }
#pragma unroll
        for (int o = 1; o <= 2; o <<= 1) {
            sum0 += __shfl_xor_sync(0xffffffffu, sum0, o);
            sum1 += __shfl_xor_sync(0xffffffffu, sum1, o);
        }
        lrow0 = lrow0 * al0 + sum0;
        lrow1 = lrow1 * al1 + sum1;
        mrow0 = mn0; mrow1 = mn1;
#pragma unroll
        for (int nt = 0; nt < 12; nt++) {
            oacc[nt][0] *= al0; oacc[nt][1] *= al0;
            oacc[nt][2] *= al1; oacc[nt][3] *= al1;
        }

        // ---- O += P V  (P straight from registers) ----
#pragma unroll
        for (int ksv = 0; ksv < 4; ksv++) {
            const int k0 = ksv * 16;
            u32 a0 = pf[2 * ksv][0], a1 = pf[2 * ksv][1];
            u32 a2 = pf[2 * ksv + 1][0], a3 = pf[2 * ksv + 1][1];
            u32 bf[12][2];
#pragma unroll
            for (int p = 0; p < 6; p++)
                ldsm_x4t(bf[2 * p][0], bf[2 * p][1], bf[2 * p + 1][0], bf[2 * p + 1][1],
                         s2u(&Vs[(cur * 64 + k0 + tkrow) * FV_P + p * 16 + tncol]));
#pragma unroll
            for (int nt = 0; nt < 12; nt++)
                mma_f16(oacc[nt][0], oacc[nt][1], oacc[nt][2], oacc[nt][3],
                        a0, a1, a2, a3, bf[nt][0], bf[nt][1]);
        }
        __syncthreads();
    }

    float inv0 = 1.f / lrow0;
    float inv1 = 1.f / lrow1;
    int r0 = mt0 + wm + lr;
    int r1 = r0 + 8;
#pragma unroll
    for (int nt = 0; nt < 12; nt++) {
        int col = head * DK + nt * 8 + 2 * lc;
        *(u32*)(O + (long)r0 * DIM + col) = pack_h2(oacc[nt][0] * inv0, oacc[nt][1] * inv0);
        *(u32*)(O + (long)r1 * DIM + col) = pack_h2(oacc[nt][2] * inv1, oacc[nt][3] * inv1);
    }
}

// ---------------- span max pooling ----------------
__global__ void pool_kernel(const float* __restrict__ emb, const int* __restrict__ spans,
                            float* __restrict__ htb)
{
    int node = blockIdx.x;
    int bag  = node / NPD;
    int s0 = spans[node * 2 + 0];
    int s1 = spans[node * 2 + 1];
    const float* base = emb + (long)bag * SEQ * DIM;
    for (int d = threadIdx.x; d < DIM; d += blockDim.x) {
        float m = -3.4e38f;
        for (int p = s0; p <= s1; p++)
            m = fmaxf(m, base[(long)p * DIM + d]);
        htb[(long)node * DIM + d] = m;
    }
}

// ---------------- x = LN(x + o) * g + b  -> fp32 x and fp16 xh ----------------
__global__ void add_ln_kernel(float* __restrict__ x, __half* __restrict__ xh,
                              const float* __restrict__ o,
                              const float* __restrict__ g, const float* __restrict__ b)
{
    long base = (long)blockIdx.x * DIM;
    float* xr = x + base;
    __half* xhr = xh + base;
    const float* orr = o + base;
    __shared__ float sh[32];
    float v[3];
    float s = 0.f, s2 = 0.f;
#pragma unroll
    for (int i = 0; i < 3; i++) {
        int d = threadIdx.x + i * 256;
        float t = xr[d] + orr[d];
        v[i] = t; s += t; s2 += t * t;
    }
    s  = blk_reduce(s,  sh, false);
    s2 = blk_reduce(s2, sh, false);
    float mean = s * (1.f / DIM);
    float var  = s2 * (1.f / DIM) - mean * mean;
    float inv  = rsqrtf(var + 1e-5f);
#pragma unroll
    for (int i = 0; i < 3; i++) {
        int d = threadIdx.x + i * 256;
        float r = (v[i] - mean) * inv * g[d] + b[d];
        xr[d] = r;
        xhr[d] = __float2half_rn(r);
    }
}

// ---------------- final: gather (h,t) cells, LN, predictor ----------------
__global__ void final_kernel(const float* __restrict__ x, const float* __restrict__ ng,
                             const float* __restrict__ nb, const float* __restrict__ Wp,
                             const float* __restrict__ bp, float* __restrict__ ht)
{
    int bag = blockIdx.x;
    long r = (long)(bag * NPD) * NN_ + (bag * NPD + 1);
    const float* row = x + r * DIM;
    __shared__ float sh[DIM];
    __shared__ float red[32];
    float s = 0.f, s2 = 0.f;
    for (int d = threadIdx.x; d < DIM; d += blockDim.x) {
        float t = row[d];
        sh[d] = t; s += t; s2 += t * t;
    }
    s  = blk_reduce(s,  red, false);
    s2 = blk_reduce(s2, red, false);
    float mean = s * (1.f / DIM);
    float inv  = rsqrtf(s2 * (1.f / DIM) - mean * mean + 1e-5f);
    __syncthreads();
    for (int d = threadIdx.x; d < DIM; d += blockDim.x)
        sh[d] = (sh[d] - mean) * inv * ng[d] + nb[d];
    __syncthreads();
    for (int n = threadIdx.x; n < NREL; n += blockDim.x) {
        float acc = bp[n];
        for (int k = 0; k < DIM; k++)
            acc = fmaf(sh[k], Wp[(long)k * NREL + n], acc);
        ht[bag * NREL + n] = acc;
    }
}

// ---------------- output assembly: bag max + layout ----------------
__global__ void writeout_kernel(const float* __restrict__ ht, float* __restrict__ out,
                                int out_size)
{
    int n = threadIdx.x;
    if (n >= NREL) return;
    float m = -3.4e38f;
    for (int b = 0; b < BAG; b++) m = fmaxf(m, ht[b * NREL + n]);
    if (out_size >= NREL * (BAG + 1)) {
        out[n] = m;
        for (int b = 0; b < BAG; b++) out[NREL + b * NREL + n] = ht[b * NREL + n];
    } else if (out_size == NREL) {
        out[n] = m;
    } else {
        for (int b = 0; b < BAG; b++) out[b * NREL + n] = ht[b * NREL + n];
    }
}

// ---------------- host ----------------
template <typename T>
static inline void* symv(T& s) {
    void* p = nullptr;
    cudaGetSymbolAddress(&p, s);
    return p;
}

extern "C" void kernel_launch(void* const* d_in, const int* in_sizes, int n_in,
                              void* d_out, int out_size)
{
    const float* emb   = (const float*)d_in[0];
    const int*   spans = (const int*)  d_in[1];
    const float* Wu = (const float*)d_in[2];  const float* bu = (const float*)d_in[3];
    const float* Wv = (const float*)d_in[4];  const float* bv = (const float*)d_in[5];
    const float* Wl = (const float*)d_in[6];  const float* bl = (const float*)d_in[7];
    const float* Wq = (const float*)d_in[8];  const float* bq = (const float*)d_in[9];
    const float* Wk = (const float*)d_in[10]; const float* bk = (const float*)d_in[11];
    const float* Wvm= (const float*)d_in[12]; const float* bvm= (const float*)d_in[13];
    const float* Wo = (const float*)d_in[14]; const float* bo = (const float*)d_in[15];
    const float* F1 = (const float*)d_in[16]; const float* f1 = (const float*)d_in[17];
    const float* F2 = (const float*)d_in[18]; const float* f2 = (const float*)d_in[19];
    const float* g1 = (const float*)d_in[20]; const float* be1= (const float*)d_in[21];
    const float* g2 = (const float*)d_in[22]; const float* be2= (const float*)d_in[23];
    const float* ng = (const float*)d_in[24]; const float* nb = (const float*)d_in[25];
    const float* Wp = (const float*)d_in[26]; const float* bp = (const float*)d_in[27];

    float*  htb = (float*) symv(g_htb);
    float*  u   = (float*) symv(g_u);
    float*  v   = (float*) symv(g_v);
    float*  x   = (float*) symv(g_x);
    float*  tmp = (float*) symv(g_tmp);
    float*  ht  = (float*) symv(g_ht);
    __half* xh  = (__half*)symv(g_xh);
    __half* qh  = (__half*)symv(g_qh);
    __half* kh  = (__half*)symv(g_kh);
    __half* vh  = (__half*)symv(g_vh);
    __half* ah  = (__half*)symv(g_ah);
    __half* fh  = (__half*)symv(g_fh);
    __half* wh  = (__half*)symv(g_wh);
    float*  out = (float*)d_out;

    const float scale = 0.102062072615966f;   // 1/sqrt(96)

    cudaFuncSetAttribute(flash_kernel, cudaFuncAttributeMaxDynamicSharedMemorySize,
                         FLASH_SMEM);

    // 0) ALL weights -> fp16 in one launch (blockIdx.y = segment)
    f2h_all<<<dim3(1536, 7), 256>>>(
        Wl,  wh + OWL, DIM * DIM,
        Wq,  wh + OWQ, NLAYER * DIM * DIM,
        Wk,  wh + OWK, NLAYER * DIM * DIM,
        Wvm, wh + OWV, NLAYER * DIM * DIM,
        Wo,  wh + OWO, NLAYER * DIM * DIM,
        F1,  wh + OF1, NLAYER * DIM * DFF,
        F2,  wh + OF2, NLAYER * DFF * DIM);

    const dim3 g1z(8, 36, 1);    // N=768 via BN=96, M=2304, BM=64 -> 288 CTAs
    const dim3 g3z(8, 36, 3);    // QKV merged -> 864 CTAs
    const dim3 gF1(8, 36, 1);    // N=1024 via BN=128 -> 288 CTAs

    // 1) span max pooling -> htb [48,768]
    pool_kernel<<<NN_, 256>>>(emb, spans, htb);

    // 2) u/v projections (merged, M=48)
    gemm_uv<<<dim3(8, 1, 2), 256>>>(htb, Wu, bu, u, Wv, bv, v);

    // 3) x = relu(relu(u_i + v_j) @ Wl + bl)   (pair fused into A-stage)
    gemm_h<3, true, true, true, true><<<g1z, 256>>>(
        nullptr, u, v, wh + OWL, bl, x, xh,
        wh + OWL, bl, xh, wh + OWL, bl, xh, DIM, DIM, DIM, DIM);

    // 4) MatTransformer layers
    for (int l = 0; l < NLAYER; l++) {
        const __half* Wqh = wh + OWQ + (size_t)l * DIM * DIM;
        const __half* Wkh = wh + OWK + (size_t)l * DIM * DIM;
        const __half* Wvh = wh + OWV + (size_t)l * DIM * DIM;
        const __half* Woh = wh + OWO + (size_t)l * DIM * DIM;
        const __half* F1h = wh + OF1 + (size_t)l * DIM * DFF;
        const __half* F2h = wh + OF2 + (size_t)l * DFF * DIM;
        const float* bq_l = bq + (size_t)l * DIM;
        const float* bk_l = bk + (size_t)l * DIM;
        const float* bv_l = bvm+ (size_t)l * DIM;
        const float* bo_l = bo + (size_t)l * DIM;
        const float* f1_l = f1 + (size_t)l * DFF;
        const float* f2_l = f2 + (size_t)l * DIM;
        const float* g1_l = g1 + (size_t)l * DIM;  const float* be1_l = be1 + (size_t)l * DIM;
        const float* g2_l = g2 + (size_t)l * DIM;  const float* be2_l = be2 + (size_t)l * DIM;

        // QKV projections: ONE launch, z selects W/b/out
        gemm_h<3, false, false, false, true><<<g3z, 256>>>(
            xh, nullptr, nullptr,
            Wqh, bq_l, nullptr, qh,
            Wkh, bk_l, kh,
            Wvh, bv_l, vh, DIM, DIM, DIM, DIM);

        // fused attention (half in, half out)
        flash_kernel<<<dim3(TT / 128, NHEAD), 256, FLASH_SMEM>>>(qh, kh, vh, ah, scale);

        // output projection + residual LN
        gemm_h<3, false, false, true, false><<<g1z, 256>>>(
            ah, nullptr, nullptr, Woh, bo_l, tmp, nullptr,
            Woh, bo_l, nullptr, Woh, bo_l, nullptr, DIM, DIM, DIM, DIM);
        add_ln_kernel<<<TT, 256>>>(x, xh, tmp, g1_l, be1_l);

        // FFN + residual LN
        gemm_h<4, false, true, false, true><<<gF1, 256>>>(
            xh, nullptr, nullptr, F1h, f1_l, nullptr, fh,
            F1h, f1_l, fh, F1h, f1_l, fh, DIM, DIM, DFF, DFF);
        gemm_h<3, false, false, true, false><<<g1z, 256>>>(
            fh, nullptr, nullptr, F2h, f2_l, tmp, nullptr,
            F2h, f2_l, nullptr, F2h, f2_l, nullptr, DFF, DFF, DIM, DIM);
        add_ln_kernel<<<TT, 256>>>(x, xh, tmp, g2_l, be2_l);
    }

    // 5) final gather + LN + predictor + bag max
    final_kernel<<<BAG, 256>>>(x, ng, nb, Wp, bp, ht);
    writeout_kernel<<<1, 128>>>(ht, out, out_size);
}

// round 17
// speedup vs baseline: 2.7178x; 1.0402x over previous
#include <cuda_runtime.h>
#include <cuda_fp16.h>
#include <cstdint>

// ---------------- problem constants ----------------
#define BAG  8
#define SEQ  512
#define DIM  768
#define NPD  6
#define NN_  48          // N nodes
#define TT   2304        // T = N*N
#define NHEAD 8
#define DK   96
#define DFF  1024
#define NLAYER 4
#define NREL 97

typedef uint32_t u32;

// ---------------- device scratch (no allocations allowed) ----------------
__device__ float  g_htb [NN_ * DIM];
__device__ float  g_u   [NN_ * DIM];
__device__ float  g_v   [NN_ * DIM];
__device__ float  g_x   [TT * DIM];
__device__ float  g_tmp [TT * DIM];
__device__ float  g_ht  [BAG * NREL];
__device__ __half g_xh  [TT * DIM];
__device__ __half g_qh  [TT * DIM];
__device__ __half g_kh  [TT * DIM];
__device__ __half g_vh  [TT * DIM];
__device__ __half g_ah  [TT * DIM];
__device__ __half g_fh  [TT * DFF];
// half weights: Wl | Wq | Wk | Wv | Wo | F1 | F2
#define OWL 0
#define OWQ (OWL + DIM*DIM)
#define OWK (OWQ + NLAYER*DIM*DIM)
#define OWV (OWK + NLAYER*DIM*DIM)
#define OWO (OWV + NLAYER*DIM*DIM)
#define OF1 (OWO + NLAYER*DIM*DIM)
#define OF2 (OF1 + NLAYER*DIM*DFF)
#define WH_TOTAL (OF2 + NLAYER*DFF*DIM)
__device__ __half g_wh[WH_TOTAL];

// ---------------- fp16 / ldmatrix / cp.async helpers ----------------
__device__ __forceinline__ u32 pack_h2(float a, float b) {
    __half2 h = __floats2half2_rn(a, b);
    return *(u32*)&h;
}
__device__ __forceinline__ void mma_f16(float& c0, float& c1, float& c2, float& c3,
                                        u32 a0, u32 a1, u32 a2, u32 a3,
                                        u32 b0, u32 b1) {
    asm("mma.sync.aligned.m16n8k16.row.col.f32.f16.f16.f32 "
        "{%0,%1,%2,%3}, {%4,%5,%6,%7}, {%8,%9}, {%0,%1,%2,%3};"
        : "+f"(c0), "+f"(c1), "+f"(c2), "+f"(c3)
        : "r"(a0), "r"(a1), "r"(a2), "r"(a3), "r"(b0), "r"(b1));
}
__device__ __forceinline__ u32 s2u(const void* p) {
    return (u32)__cvta_generic_to_shared(p);
}
__device__ __forceinline__ void ldsm_x4(u32& r0, u32& r1, u32& r2, u32& r3, u32 addr) {
    asm volatile("ldmatrix.sync.aligned.m8n8.x4.shared.b16 {%0,%1,%2,%3}, [%4];"
                 : "=r"(r0), "=r"(r1), "=r"(r2), "=r"(r3) : "r"(addr));
}
__device__ __forceinline__ void ldsm_x4t(u32& r0, u32& r1, u32& r2, u32& r3, u32 addr) {
    asm volatile("ldmatrix.sync.aligned.m8n8.x4.trans.shared.b16 {%0,%1,%2,%3}, [%4];"
                 : "=r"(r0), "=r"(r1), "=r"(r2), "=r"(r3) : "r"(addr));
}
__device__ __forceinline__ void ldsm_x2t(u32& r0, u32& r1, u32 addr) {
    asm volatile("ldmatrix.sync.aligned.m8n8.x2.trans.shared.b16 {%0,%1}, [%2];"
                 : "=r"(r0), "=r"(r1) : "r"(addr));
}
__device__ __forceinline__ void cp16(u32 dst, const void* src) {
    asm volatile("cp.async.cg.shared.global [%0], [%1], 16;" :: "r"(dst), "l"(src));
}
#define CP_COMMIT() asm volatile("cp.async.commit_group;")
#define CP_WAIT(n)  asm volatile("cp.async.wait_group %0;" :: "n"(n))

// ---------------- block reduction helper ----------------
__device__ __forceinline__ float blk_reduce(float val, float* sh, bool do_max) {
    const unsigned mask = 0xffffffffu;
#pragma unroll
    for (int o = 16; o > 0; o >>= 1) {
        float other = __shfl_xor_sync(mask, val, o);
        val = do_max ? fmaxf(val, other) : (val + other);
    }
    int lane = threadIdx.x & 31, w = threadIdx.x >> 5;
    __syncthreads();
    if (lane == 0) sh[w] = val;
    __syncthreads();
    int nw = (blockDim.x + 31) >> 5;
    if (w == 0) {
        val = (lane < nw) ? sh[lane] : (do_max ? -3.4e38f : 0.f);
#pragma unroll
        for (int o = 16; o > 0; o >>= 1) {
            float other = __shfl_xor_sync(mask, val, o);
            val = do_max ? fmaxf(val, other) : (val + other);
        }
        if (lane == 0) sh[0] = val;
    }
    __syncthreads();
    return sh[0];
}

// ---------------- ALL weights fp32 -> fp16 in ONE launch ----------------
__global__ void f2h_all(const float* s0, __half* d0, int n0,
                        const float* s1, __half* d1, int n1,
                        const float* s2, __half* d2, int n2,
                        const float* s3, __half* d3, int n3,
                        const float* s4, __half* d4, int n4,
                        const float* s5, __half* d5, int n5,
                        const float* s6, __half* d6, int n6)
{
    const float* src; __half* dst; int n;
    switch (blockIdx.y) {
        case 0: src = s0; dst = d0; n = n0; break;
        case 1: src = s1; dst = d1; n = n1; break;
        case 2: src = s2; dst = d2; n = n2; break;
        case 3: src = s3; dst = d3; n = n3; break;
        case 4: src = s4; dst = d4; n = n4; break;
        case 5: src = s5; dst = d5; n = n5; break;
        default: src = s6; dst = d6; n = n6; break;
    }
    int i = (blockIdx.x * 256 + threadIdx.x) * 8;
    if (i >= n) return;
    float4 a = *(const float4*)(src + i);
    float4 b = *(const float4*)(src + i + 4);
    uint4 q;
    q.x = pack_h2(a.x, a.y); q.y = pack_h2(a.z, a.w);
    q.z = pack_h2(b.x, b.y); q.w = pack_h2(b.z, b.w);
    *(uint4*)(dst + i) = q;
}

// === 64xBN fp16 GEMM, BK=64, 3-stage cp.async, ONE barrier per k-iter ===
// Dynamic smem: As[3][64][72] | Bs[3][64][BN+8].
// z-batched over up to 3 (B, bias, Ch) triples.
// M % 64 == 0, N % BN == 0, K % 64 == 0, K/64 >= 2.
template<int NT, bool PAIR, bool RELU, bool OUTF, bool OUTH>
__global__ __launch_bounds__(256, 2)
void gemm_h(const __half* __restrict__ A, const float* __restrict__ U,
            const float* __restrict__ Vv,
            const __half* B0, const float* b0, float* __restrict__ Cf, __half* Ch0,
            const __half* B1, const float* b1, __half* Ch1,
            const __half* B2, const float* b2, __half* Ch2,
            int K, int lda, int ldb, int ldc)
{
    constexpr int BM = 64;
    constexpr int BN = 32 * NT;
    constexpr int BK = 64;
    constexpr int AP = 72;              // 144B row = 9x16B (odd) -> conflict-free
    constexpr int BP = BN + 8;          // 104/136 halfs -> 13/17 x16B (odd)
    constexpr int ASZ = BM * AP;        // 4608 halfs / buffer
    constexpr int BSZ = BK * BP;        // 6656 / 8704 halfs per buffer
    constexpr int BCH = (BK * BN) / 8;  // B 16B-chunks: 768 / 1024

    extern __shared__ __half sm[];
    __half* As = sm;                    // 3 buffers
    __half* Bs = sm + 3 * ASZ;

    const __half* B    = B0;
    const float*  bias = b0;
    __half*       Ch   = Ch0;
    if (blockIdx.z == 1) { B = B1; bias = b1; Ch = Ch1; }
    else if (blockIdx.z == 2) { B = B2; bias = b2; Ch = Ch2; }

    const int tid  = threadIdx.x;
    const int lane = tid & 31;
    const int warp = tid >> 5;
    const int wR   = (warp & 1) * 32;
    const int wC   = (warp >> 1) * (8 * NT);
    const int row0 = blockIdx.y * BM;
    const int col0 = blockIdx.x * BN;
    const int lr   = lane >> 2;
    const int lc   = lane & 3;
    const int ph   = lane >> 3;
    const int rr   = lane & 7;

    const int arow = rr + (ph & 1) * 8;
    const int acol = (ph >> 1) * 8;
    const int tkrow = rr + (ph & 1) * 8;
    const int tncol = (ph >> 1) * 8;

    // A stage map: 512 16B chunks (2/thread)
    const int sar = tid >> 3;                 // 0..31 (+32 for second)
    const int sac = (tid & 7) * 8;

    float acc[2][NT][4];
#pragma unroll
    for (int i = 0; i < 2; i++)
#pragma unroll
        for (int j = 0; j < NT; j++)
#pragma unroll
            for (int c = 0; c < 4; c++) acc[i][j][c] = 0.f;

    const int KT = K / BK;

    auto issueB = [&](int kb, int buf) {
        __half* bb = Bs + buf * BSZ;
#pragma unroll
        for (int i = 0; i < BCH / 256; i++) {
            int t = tid + i * 256;
            int krow = t / (BN / 8), c8 = (t % (BN / 8)) * 8;
            cp16(s2u(bb + krow * BP + c8), B + (long)(kb + krow) * ldb + col0 + c8);
        }
    };
    auto issueA = [&](int kb, int buf) {
        __half* ab = As + buf * ASZ;
#pragma unroll
        for (int i = 0; i < 2; i++) {
            int r = sar + i * 32;
            cp16(s2u(ab + r * AP + sac), A + (long)(row0 + r) * lda + kb + sac);
        }
    };
    auto stagePA = [&](int kb, int buf) {
        __half* ab = As + buf * ASZ;
#pragma unroll
        for (int i = 0; i < 2; i++) {
            int r = sar + i * 32;
            int m = row0 + r;
            int ii = m / NN_, jj = m % NN_;
            const float* up = U + (long)ii * DIM + kb + sac;
            const float* vp = Vv + (long)jj * DIM + kb + sac;
            float4 u0 = *(const float4*)up, u1 = *(const float4*)(up + 4);
            float4 v0 = *(const float4*)vp, v1 = *(const float4*)(vp + 4);
            uint4 q;
            q.x = pack_h2(fmaxf(u0.x + v0.x, 0.f), fmaxf(u0.y + v0.y, 0.f));
            q.y = pack_h2(fmaxf(u0.z + v0.z, 0.f), fmaxf(u0.w + v0.w, 0.f));
            q.z = pack_h2(fmaxf(u1.x + v1.x, 0.f), fmaxf(u1.y + v1.y, 0.f));
            q.w = pack_h2(fmaxf(u1.z + v1.z, 0.f), fmaxf(u1.w + v1.w, 0.f));
            *(uint4*)(ab + r * AP + sac) = q;
        }
    };

    // prologue: stage tiles 0 and 1
    if (PAIR) stagePA(0, 0); else issueA(0, 0);
    issueB(0, 0);
    CP_COMMIT();
    if (PAIR) stagePA(BK, 1); else issueA(BK, 1);
    issueB(BK, 1);
    CP_COMMIT();

    for (int kt = 0; kt < KT; kt++) {
        const int cur = kt % 3;
        if (kt + 1 < KT) { CP_WAIT(1); } else { CP_WAIT(0); }
        __syncthreads();     // tile kt ready; buffer (kt+2)%3 fully consumed

        const int nx = kt + 2;
        if (nx < KT) {
            const int nb = nx % 3;
            if (PAIR) stagePA(nx * BK, nb); else issueA(nx * BK, nb);
            issueB(nx * BK, nb);
            CP_COMMIT();
        }

        const __half* ab = As + cur * ASZ;
        const __half* bb = Bs + cur * BSZ;
#pragma unroll
        for (int ks = 0; ks < 4; ks++) {
            const int k0 = ks * 16;
            u32 af[2][4], bf[NT][2];
#pragma unroll
            for (int mt = 0; mt < 2; mt++)
                ldsm_x4(af[mt][0], af[mt][1], af[mt][2], af[mt][3],
                        s2u(ab + (wR + mt * 16 + arow) * AP + k0 + acol));
#pragma unroll
            for (int p = 0; p < NT / 2; p++)
                ldsm_x4t(bf[2 * p][0], bf[2 * p][1], bf[2 * p + 1][0], bf[2 * p + 1][1],
                         s2u(bb + (k0 + tkrow) * BP + wC + p * 16 + tncol));
            if (NT & 1)
                ldsm_x2t(bf[NT - 1][0], bf[NT - 1][1],
                         s2u(bb + (k0 + tkrow) * BP + wC + (NT - 1) * 8));
#pragma unroll
            for (int mt = 0; mt < 2; mt++)
#pragma unroll
                for (int nt = 0; nt < NT; nt++)
                    mma_f16(acc[mt][nt][0], acc[mt][nt][1], acc[mt][nt][2], acc[mt][nt][3],
                            af[mt][0], af[mt][1], af[mt][2], af[mt][3],
                            bf[nt][0], bf[nt][1]);
        }
    }

    // ---- epilogue ----
#pragma unroll
    for (int nt = 0; nt < NT; nt++) {
        int gn = col0 + wC + nt * 8 + 2 * lc;
        float b0v = bias[gn], b1v = bias[gn + 1];
#pragma unroll
        for (int mt = 0; mt < 2; mt++) {
            int gm0 = row0 + wR + mt * 16 + lr;
#pragma unroll
            for (int h = 0; h < 2; h++) {
                int gm = gm0 + h * 8;
                float v0 = acc[mt][nt][2 * h]     + b0v;
                float v1 = acc[mt][nt][2 * h + 1] + b1v;
                if (RELU) { v0 = fmaxf(v0, 0.f); v1 = fmaxf(v1, 0.f); }
                if (OUTF) *(float2*)(Cf + (long)gm * ldc + gn) = make_float2(v0, v1);
                if (OUTH) *(u32*)(Ch + (long)gm * ldc + gn) = pack_h2(v0, v1);
            }
        }
    }
}
#define SMEM_G3 ((3 * 64 * 72 + 3 * 64 * 104) * 2)   // 67584
#define SMEM_G4 ((3 * 64 * 72 + 3 * 64 * 136) * 2)   // 79872

// ---------------- small-M GEMM (u/v projections, merged over z) ----------------
__global__ __launch_bounds__(256)
void gemm_uv(const float* __restrict__ Aht, const float* __restrict__ B1,
             const float* __restrict__ bias1, float* __restrict__ C1,
             const float* __restrict__ B2, const float* __restrict__ bias2,
             float* __restrict__ C2)
{
    constexpr int NT = 3, BN = 96, BK = 16, AP = 24, BP = BN + 8;
    const float* B   = blockIdx.z ? B2 : B1;
    const float* bia = blockIdx.z ? bias2 : bias1;
    float*       C   = blockIdx.z ? C2 : C1;
    const int M = NN_, Kt = DIM;

    __shared__ __half As[2][128][AP];
    __shared__ __half Bs[2][BK][BP];

    const int tid  = threadIdx.x;
    const int lane = tid & 31;
    const int warp = tid >> 5;
    const int wR   = (warp & 1) * 64;
    const int wC   = (warp >> 1) * 24;
    const int col0 = blockIdx.x * BN;
    const int lr   = lane >> 2;
    const int lc   = lane & 3;
    const int ph   = lane >> 3;
    const int rr   = lane & 7;

    const int arow = rr + (ph & 1) * 8;
    const int acol = (ph >> 1) * 8;
    const int tkrow = rr + (ph & 1) * 8;
    const int tncol = (ph >> 1) * 8;

    const int ar = tid >> 1;
    const int ac = (tid & 1) * 8;
    int kb0 = tid / 24, nb0 = (tid % 24) * 4;
    bool b1v = (tid < 128);
    int id1 = tid + 256;
    int kb1 = id1 / 24, nb1 = (id1 % 24) * 4;

    const float4 f4z = make_float4(0.f, 0.f, 0.f, 0.f);
    float4 fa0, fa1, fb0, fb1;

    float acc[4][NT][4];
#pragma unroll
    for (int i = 0; i < 4; i++)
#pragma unroll
        for (int j = 0; j < NT; j++)
#pragma unroll
            for (int c = 0; c < 4; c++) acc[i][j][c] = 0.f;

    auto fetch = [&](int k0g) {
        const float* ap = Aht + (long)ar * DIM + k0g + ac;
        fa0 = (ar < M) ? *(const float4*)ap : f4z;
        fa1 = (ar < M) ? *(const float4*)(ap + 4) : f4z;
        fb0 = *(const float4*)(B + (long)(k0g + kb0) * DIM + col0 + nb0);
        if (b1v) fb1 = *(const float4*)(B + (long)(k0g + kb1) * DIM + col0 + nb1);
    };
    auto stage = [&](int buf) {
        uint4 qa;
        qa.x = pack_h2(fa0.x, fa0.y); qa.y = pack_h2(fa0.z, fa0.w);
        qa.z = pack_h2(fa1.x, fa1.y); qa.w = pack_h2(fa1.z, fa1.w);
        *(uint4*)&As[buf][ar][ac] = qa;
        uint2 qb0;
        qb0.x = pack_h2(fb0.x, fb0.y); qb0.y = pack_h2(fb0.z, fb0.w);
        *(uint2*)&Bs[buf][kb0][nb0] = qb0;
        if (b1v) {
            uint2 qb1;
            qb1.x = pack_h2(fb1.x, fb1.y); qb1.y = pack_h2(fb1.z, fb1.w);
            *(uint2*)&Bs[buf][kb1][nb1] = qb1;
        }
    };

    fetch(0);
    stage(0);
    __syncthreads();

    const int KT = Kt / BK;
    for (int kt = 0; kt < KT; kt++) {
        const int cur = kt & 1;
        const bool hn = (kt + 1 < KT);
        if (hn) fetch((kt + 1) * BK);

        u32 af[4][4], bf[NT][2];
#pragma unroll
        for (int mt = 0; mt < 4; mt++)
            ldsm_x4(af[mt][0], af[mt][1], af[mt][2], af[mt][3],
                    s2u(&As[cur][wR + mt * 16 + arow][acol]));
        ldsm_x4t(bf[0][0], bf[0][1], bf[1][0], bf[1][1],
                 s2u(&Bs[cur][tkrow][wC + tncol]));
        ldsm_x2t(bf[2][0], bf[2][1], s2u(&Bs[cur][tkrow][wC + 16]));
#pragma unroll
        for (int mt = 0; mt < 4; mt++)
#pragma unroll
            for (int nt = 0; nt < NT; nt++)
                mma_f16(acc[mt][nt][0], acc[mt][nt][1], acc[mt][nt][2], acc[mt][nt][3],
                        af[mt][0], af[mt][1], af[mt][2], af[mt][3],
                        bf[nt][0], bf[nt][1]);

        if (hn) stage(cur ^ 1);
        __syncthreads();
    }

#pragma unroll
    for (int nt = 0; nt < NT; nt++) {
        int gn = col0 + wC + nt * 8 + 2 * lc;
        float b0 = bia[gn], b1 = bia[gn + 1];
#pragma unroll
        for (int mt = 0; mt < 4; mt++) {
            int gm0 = wR + mt * 16 + lr;
#pragma unroll
            for (int h = 0; h < 2; h++) {
                int gm = gm0 + h * 8;
                if (gm >= M) continue;
                *(float2*)(C + (long)gm * DIM + gn) =
                    make_float2(acc[mt][nt][2 * h] + b0, acc[mt][nt][2 * h + 1] + b1);
            }
        }
    }
}

// ---------------- flash attention (fp16, cp.async K/V, P in registers) ----------------
#define FQ_P 104
#define FK_P 104
#define FV_P 104
#define FQ_OFF 0
#define FK_OFF 13312
#define FV_OFF 26624
#define FLASH_SMEM ((26624 + 2 * 64 * FV_P) * 2)

__global__ __launch_bounds__(256, 2)
void flash_kernel(const __half* __restrict__ Q, const __half* __restrict__ K,
                  const __half* __restrict__ V, __half* __restrict__ O, float scale)
{
    extern __shared__ __half smh[];
    __half* Qs = smh + FQ_OFF;
    __half* Ks = smh + FK_OFF;
    __half* Vs = smh + FV_OFF;

    const int tid  = threadIdx.x;
    const int lane = tid & 31;
    const int warp = tid >> 5;
    const int lr   = lane >> 2;
    const int lc   = lane & 3;
    const int ph   = lane >> 3;
    const int rr   = lane & 7;
    const int wm   = warp * 16;
    const int mt0  = blockIdx.x * 128;
    const int head = blockIdx.y;

    const int arow = rr + (ph & 1) * 8;
    const int acol = (ph >> 1) * 8;
    const int brow = rr + (ph >> 1) * 8;
    const int bcol = (ph & 1) * 8;
    const int tkrow = rr + (ph & 1) * 8;
    const int tncol = (ph >> 1) * 8;

    const __half* Qb = Q + (long)mt0 * DIM + head * DK;
    const __half* Kb = K + head * DK;
    const __half* Vb = V + head * DK;

#pragma unroll
    for (int it = 0; it < 6; it++) {
        int id  = tid + it * 256;
        int row = id / 12;
        int c8  = (id % 12) * 8;
        *(uint4*)&Qs[row * FQ_P + c8] = *(const uint4*)(Qb + (long)row * DIM + c8);
    }

    auto issueKV = [&](int t, int buf) {
#pragma unroll
        for (int it = 0; it < 3; it++) {
            int id  = tid + it * 256;
            int row = id / 12;
            int c8  = (id % 12) * 8;
            cp16(s2u(&Ks[(buf * 64 + row) * FK_P + c8]),
                 Kb + (long)(t * 64 + row) * DIM + c8);
            cp16(s2u(&Vs[(buf * 64 + row) * FV_P + c8]),
                 Vb + (long)(t * 64 + row) * DIM + c8);
        }
    };

    float oacc[12][4];
#pragma unroll
    for (int i = 0; i < 12; i++)
#pragma unroll
        for (int c = 0; c < 4; c++) oacc[i][c] = 0.f;
    float mrow0 = -1e30f, mrow1 = -1e30f, lrow0 = 0.f, lrow1 = 0.f;

    issueKV(0, 0);
    CP_COMMIT();

    const int NIT = TT / 64;
    for (int t = 0; t < NIT; t++) {
        const int cur = t & 1;
        const bool hn = (t + 1 < NIT);
        if (hn) {
            issueKV(t + 1, cur ^ 1);
            CP_COMMIT();
            CP_WAIT(1);
        } else {
            CP_WAIT(0);
        }
        __syncthreads();

        float sacc[8][4];
#pragma unroll
        for (int nt = 0; nt < 8; nt++)
#pragma unroll
            for (int c = 0; c < 4; c++) sacc[nt][c] = 0.f;

#pragma unroll
        for (int ks = 0; ks < 6; ks++) {
            const int k0 = ks * 16;
            u32 a0, a1, a2, a3;
            ldsm_x4(a0, a1, a2, a3, s2u(&Qs[(wm + arow) * FQ_P + k0 + acol]));
            u32 bf[8][2];
#pragma unroll
            for (int p = 0; p < 4; p++)
                ldsm_x4(bf[2 * p][0], bf[2 * p][1], bf[2 * p + 1][0], bf[2 * p + 1][1],
                        s2u(&Ks[(cur * 64 + p * 16 + brow) * FK_P + k0 + bcol]));
#pragma unroll
            for (int nt = 0; nt < 8; nt++)
                mma_f16(sacc[nt][0], sacc[nt][1], sacc[nt][2], sacc[nt][3],
                        a0, a1, a2, a3, bf[nt][0], bf[nt][1]);
        }

        float rm0 = -1e30f, rm1 = -1e30f;
#pragma unroll
        for (int nt = 0; nt < 8; nt++) {
            rm0 = fmaxf(rm0, fmaxf(sacc[nt][0], sacc[nt][1]));
            rm1 = fmaxf(rm1, fmaxf(sacc[nt][2], sacc[nt][3]));
        }
        rm0 *= scale; rm1 *= scale;
#pragma unroll
        for (int o = 1; o <= 2; o <<= 1) {
            rm0 = fmaxf(rm0, __shfl_xor_sync(0xffffffffu, rm0, o));
            rm1 = fmaxf(rm1, __shfl_xor_sync(0xffffffffu, rm1, o));
        }
        float mn0 = fmaxf(mrow0, rm0);
        float mn1 = fmaxf(mrow1, rm1);
        float al0 = __expf(mrow0 - mn0);
        float al1 = __expf(mrow1 - mn1);
        float sum0 = 0.f, sum1 = 0.f;
        u32 pf[8][2];                     // P as A-fragments (C->A layout identity)
#pragma unroll
        for (int nt = 0; nt < 8; nt++) {
            float p0 = __expf(sacc[nt][0] * scale - mn0);
            float p1 = __expf(sacc[nt][1] * scale - mn0);
            float p2 = __expf(sacc[nt][2] * scale - mn1);
            float p3 = __expf(sacc[nt][3] * scale - mn1);
            sum0 += p0 + p1; sum1 += p2 + p3;
            pf[nt][0] = pack_h2(p0, p1);
            pf[nt][1] = pack_h2(p2, p3);
        }
#pragma unroll
        for (int o = 1; o <= 2; o <<= 1) {
            sum0 += __shfl_xor_sync(0xffffffffu, sum0, o);
            sum1 += __shfl_xor_sync(0xffffffffu, sum1, o);
        }
        lrow0 = lrow0 * al0 + sum0;
        lrow1 = lrow1 * al1 + sum1;
        mrow0 = mn0; mrow1 = mn1;
#pragma unroll
        for (int nt = 0; nt < 12; nt++) {
            oacc[nt][0] *= al0; oacc[nt][1] *= al0;
            oacc[nt][2] *= al1; oacc[nt][3] *= al1;
        }

        // ---- O += P V  (P straight from registers) ----
#pragma unroll
        for (int ksv = 0; ksv < 4; ksv++) {
            const int k0 = ksv * 16;
            u32 a0 = pf[2 * ksv][0], a1 = pf[2 * ksv][1];
            u32 a2 = pf[2 * ksv + 1][0], a3 = pf[2 * ksv + 1][1];
            u32 bf[12][2];
#pragma unroll
            for (int p = 0; p < 6; p++)
                ldsm_x4t(bf[2 * p][0], bf[2 * p][1], bf[2 * p + 1][0], bf[2 * p + 1][1],
                         s2u(&Vs[(cur * 64 + k0 + tkrow) * FV_P + p * 16 + tncol]));
#pragma unroll
            for (int nt = 0; nt < 12; nt++)
                mma_f16(oacc[nt][0], oacc[nt][1], oacc[nt][2], oacc[nt][3],
                        a0, a1, a2, a3, bf[nt][0], bf[nt][1]);
        }
        __syncthreads();
    }

    float inv0 = 1.f / lrow0;
    float inv1 = 1.f / lrow1;
    int r0 = mt0 + wm + lr;
    int r1 = r0 + 8;
#pragma unroll
    for (int nt = 0; nt < 12; nt++) {
        int col = head * DK + nt * 8 + 2 * lc;
        *(u32*)(O + (long)r0 * DIM + col) = pack_h2(oacc[nt][0] * inv0, oacc[nt][1] * inv0);
        *(u32*)(O + (long)r1 * DIM + col) = pack_h2(oacc[nt][2] * inv1, oacc[nt][3] * inv1);
    }
}

// ---------------- span max pooling ----------------
__global__ void pool_kernel(const float* __restrict__ emb, const int* __restrict__ spans,
                            float* __restrict__ htb)
{
    int node = blockIdx.x;
    int bag  = node / NPD;
    int s0 = spans[node * 2 + 0];
    int s1 = spans[node * 2 + 1];
    const float* base = emb + (long)bag * SEQ * DIM;
    for (int d = threadIdx.x; d < DIM; d += blockDim.x) {
        float m = -3.4e38f;
        for (int p = s0; p <= s1; p++)
            m = fmaxf(m, base[(long)p * DIM + d]);
        htb[(long)node * DIM + d] = m;
    }
}

// ---------------- x = LN(x + o) * g + b  -> fp32 x and fp16 xh ----------------
__global__ void add_ln_kernel(float* __restrict__ x, __half* __restrict__ xh,
                              const float* __restrict__ o,
                              const float* __restrict__ g, const float* __restrict__ b)
{
    long base = (long)blockIdx.x * DIM;
    float* xr = x + base;
    __half* xhr = xh + base;
    const float* orr = o + base;
    __shared__ float sh[32];
    float v[3];
    float s = 0.f, s2 = 0.f;
#pragma unroll
    for (int i = 0; i < 3; i++) {
        int d = threadIdx.x + i * 256;
        float t = xr[d] + orr[d];
        v[i] = t; s += t; s2 += t * t;
    }
    s  = blk_reduce(s,  sh, false);
    s2 = blk_reduce(s2, sh, false);
    float mean = s * (1.f / DIM);
    float var  = s2 * (1.f / DIM) - mean * mean;
    float inv  = rsqrtf(var + 1e-5f);
#pragma unroll
    for (int i = 0; i < 3; i++) {
        int d = threadIdx.x + i * 256;
        float r = (v[i] - mean) * inv * g[d] + b[d];
        xr[d] = r;
        xhr[d] = __float2half_rn(r);
    }
}

// ---------------- final: gather (h,t) cells, LN, predictor ----------------
__global__ void final_kernel(const float* __restrict__ x, const float* __restrict__ ng,
                             const float* __restrict__ nb, const float* __restrict__ Wp,
                             const float* __restrict__ bp, float* __restrict__ ht)
{
    int bag = blockIdx.x;
    long r = (long)(bag * NPD) * NN_ + (bag * NPD + 1);
    const float* row = x + r * DIM;
    __shared__ float sh[DIM];
    __shared__ float red[32];
    float s = 0.f, s2 = 0.f;
    for (int d = threadIdx.x; d < DIM; d += blockDim.x) {
        float t = row[d];
        sh[d] = t; s += t; s2 += t * t;
    }
    s  = blk_reduce(s,  red, false);
    s2 = blk_reduce(s2, red, false);
    float mean = s * (1.f / DIM);
    float inv  = rsqrtf(s2 * (1.f / DIM) - mean * mean + 1e-5f);
    __syncthreads();
    for (int d = threadIdx.x; d < DIM; d += blockDim.x)
        sh[d] = (sh[d] - mean) * inv * ng[d] + nb[d];
    __syncthreads();
    for (int n = threadIdx.x; n < NREL; n += blockDim.x) {
        float acc = bp[n];
        for (int k = 0; k < DIM; k++)
            acc = fmaf(sh[k], Wp[(long)k * NREL + n], acc);
        ht[bag * NREL + n] = acc;
    }
}

// ---------------- output assembly: bag max + layout ----------------
__global__ void writeout_kernel(const float* __restrict__ ht, float* __restrict__ out,
                                int out_size)
{
    int n = threadIdx.x;
    if (n >= NREL) return;
    float m = -3.4e38f;
    for (int b = 0; b < BAG; b++) m = fmaxf(m, ht[b * NREL + n]);
    if (out_size >= NREL * (BAG + 1)) {
        out[n] = m;
        for (int b = 0; b < BAG; b++) out[NREL + b * NREL + n] = ht[b * NREL + n];
    } else if (out_size == NREL) {
        out[n] = m;
    } else {
        for (int b = 0; b < BAG; b++) out[b * NREL + n] = ht[b * NREL + n];
    }
}

// ---------------- host ----------------
template <typename T>
static inline void* symv(T& s) {
    void* p = nullptr;
    cudaGetSymbolAddress(&p, s);
    return p;
}

extern "C" void kernel_launch(void* const* d_in, const int* in_sizes, int n_in,
                              void* d_out, int out_size)
{
    const float* emb   = (const float*)d_in[0];
    const int*   spans = (const int*)  d_in[1];
    const float* Wu = (const float*)d_in[2];  const float* bu = (const float*)d_in[3];
    const float* Wv = (const float*)d_in[4];  const float* bv = (const float*)d_in[5];
    const float* Wl = (const float*)d_in[6];  const float* bl = (const float*)d_in[7];
    const float* Wq = (const float*)d_in[8];  const float* bq = (const float*)d_in[9];
    const float* Wk = (const float*)d_in[10]; const float* bk = (const float*)d_in[11];
    const float* Wvm= (const float*)d_in[12]; const float* bvm= (const float*)d_in[13];
    const float* Wo = (const float*)d_in[14]; const float* bo = (const float*)d_in[15];
    const float* F1 = (const float*)d_in[16]; const float* f1 = (const float*)d_in[17];
    const float* F2 = (const float*)d_in[18]; const float* f2 = (const float*)d_in[19];
    const float* g1 = (const float*)d_in[20]; const float* be1= (const float*)d_in[21];
    const float* g2 = (const float*)d_in[22]; const float* be2= (const float*)d_in[23];
    const float* ng = (const float*)d_in[24]; const float* nb = (const float*)d_in[25];
    const float* Wp = (const float*)d_in[26]; const float* bp = (const float*)d_in[27];

    float*  htb = (float*) symv(g_htb);
    float*  u   = (float*) symv(g_u);
    float*  v   = (float*) symv(g_v);
    float*  x   = (float*) symv(g_x);
    float*  tmp = (float*) symv(g_tmp);
    float*  ht  = (float*) symv(g_ht);
    __half* xh  = (__half*)symv(g_xh);
    __half* qh  = (__half*)symv(g_qh);
    __half* kh  = (__half*)symv(g_kh);
    __half* vh  = (__half*)symv(g_vh);
    __half* ah  = (__half*)symv(g_ah);
    __half* fh  = (__half*)symv(g_fh);
    __half* wh  = (__half*)symv(g_wh);
    float*  out = (float*)d_out;

    const float scale = 0.102062072615966f;   // 1/sqrt(96)

    cudaFuncSetAttribute(flash_kernel, cudaFuncAttributeMaxDynamicSharedMemorySize,
                         FLASH_SMEM);
    cudaFuncSetAttribute((gemm_h<3, true,  true,  true,  true >),
                         cudaFuncAttributeMaxDynamicSharedMemorySize, SMEM_G3);
    cudaFuncSetAttribute((gemm_h<3, false, false, false, true >),
                         cudaFuncAttributeMaxDynamicSharedMemorySize, SMEM_G3);
    cudaFuncSetAttribute((gemm_h<3, false, false, true,  false>),
                         cudaFuncAttributeMaxDynamicSharedMemorySize, SMEM_G3);
    cudaFuncSetAttribute((gemm_h<4, false, true,  false, true >),
                         cudaFuncAttributeMaxDynamicSharedMemorySize, SMEM_G4);

    // 0) ALL weights -> fp16 in one launch (blockIdx.y = segment)
    f2h_all<<<dim3(1536, 7), 256>>>(
        Wl,  wh + OWL, DIM * DIM,
        Wq,  wh + OWQ, NLAYER * DIM * DIM,
        Wk,  wh + OWK, NLAYER * DIM * DIM,
        Wvm, wh + OWV, NLAYER * DIM * DIM,
        Wo,  wh + OWO, NLAYER * DIM * DIM,
        F1,  wh + OF1, NLAYER * DIM * DFF,
        F2,  wh + OF2, NLAYER * DFF * DIM);

    const dim3 g1z(8, 36, 1);    // N=768 via BN=96, M=2304, BM=64 -> 288 CTAs
    const dim3 g3z(8, 36, 3);    // QKV merged -> 864 CTAs
    const dim3 gF1(8, 36, 1);    // N=1024 via BN=128 -> 288 CTAs

    // 1) span max pooling -> htb [48,768]
    pool_kernel<<<NN_, 256>>>(emb, spans, htb);

    // 2) u/v projections (merged, M=48)
    gemm_uv<<<dim3(8, 1, 2), 256>>>(htb, Wu, bu, u, Wv, bv, v);

    // 3) x = relu(relu(u_i + v_j) @ Wl + bl)   (pair fused into A-stage)
    gemm_h<3, true, true, true, true><<<g1z, 256, SMEM_G3>>>(
        nullptr, u, v, wh + OWL, bl, x, xh,
        wh + OWL, bl, xh, wh + OWL, bl, xh, DIM, DIM, DIM, DIM);

    // 4) MatTransformer layers
    for (int l = 0; l < NLAYER; l++) {
        const __half* Wqh = wh + OWQ + (size_t)l * DIM * DIM;
        const __half* Wkh = wh + OWK + (size_t)l * DIM * DIM;
        const __half* Wvh = wh + OWV + (size_t)l * DIM * DIM;
        const __half* Woh = wh + OWO + (size_t)l * DIM * DIM;
        const __half* F1h = wh + OF1 + (size_t)l * DIM * DFF;
        const __half* F2h = wh + OF2 + (size_t)l * DFF * DIM;
        const float* bq_l = bq + (size_t)l * DIM;
        const float* bk_l = bk + (size_t)l * DIM;
        const float* bv_l = bvm+ (size_t)l * DIM;
        const float* bo_l = bo + (size_t)l * DIM;
        const float* f1_l = f1 + (size_t)l * DFF;
        const float* f2_l = f2 + (size_t)l * DIM;
        const float* g1_l = g1 + (size_t)l * DIM;  const float* be1_l = be1 + (size_t)l * DIM;
        const float* g2_l = g2 + (size_t)l * DIM;  const float* be2_l = be2 + (size_t)l * DIM;

        // QKV projections: ONE launch, z selects W/b/out
        gemm_h<3, false, false, false, true><<<g3z, 256, SMEM_G3>>>(
            xh, nullptr, nullptr,
            Wqh, bq_l, nullptr, qh,
            Wkh, bk_l, kh,
            Wvh, bv_l, vh, DIM, DIM, DIM, DIM);

        // fused attention (half in, half out)
        flash_kernel<<<dim3(TT / 128, NHEAD), 256, FLASH_SMEM>>>(qh, kh, vh, ah, scale);

        // output projection + residual LN
        gemm_h<3, false, false, true, false><<<g1z, 256, SMEM_G3>>>(
            ah, nullptr, nullptr, Woh, bo_l, tmp, nullptr,
            Woh, bo_l, nullptr, Woh, bo_l, nullptr, DIM, DIM, DIM, DIM);
        add_ln_kernel<<<TT, 256>>>(x, xh, tmp, g1_l, be1_l);

        // FFN + residual LN
        gemm_h<4, false, true, false, true><<<gF1, 256, SMEM_G4>>>(
            xh, nullptr, nullptr, F1h, f1_l, nullptr, fh,
            F1h, f1_l, fh, F1h, f1_l, fh, DIM, DIM, DFF, DFF);
        gemm_h<3, false, false, true, false><<<g1z, 256, SMEM_G3>>>(
            fh, nullptr, nullptr, F2h, f2_l, tmp, nullptr,
            F2h, f2_l, nullptr, F2h, f2_l, nullptr, DFF, DFF, DIM, DIM);
        add_ln_kernel<<<TT, 256>>>(x, xh, tmp, g2_l, be2_l);
    }

    // 5) final gather + LN + predictor + bag max
    final_kernel<<<BAG, 256>>>(x, ng, nb, Wp, bp, ht);
    writeout_kernel<<<1, 128>>>(ht, out, out_size);
}